// round 1
// baseline (speedup 1.0000x reference)
#include <cuda_runtime.h>
#include <math.h>

#define B_      2
#define S_      2048
#define DIM_    1024
#define H_      16
#define KVH_    4
#define HD_     64
#define KVDIM_  256
#define R_      4
#define NSTEPS_ 2
#define M_      (B_*S_)

// ---------------- scratch (device globals; no allocs allowed) ----------------
__device__ float g_q[M_*DIM_];      // [b*S+s][h*64+d]
__device__ float g_k[M_*KVDIM_];    // [b*S+s][kvh*64+d]
__device__ float g_v[M_*KVDIM_];
__device__ float g_y[M_*DIM_];      // attention output, [b*S+s][h*64+d]
__device__ float g_xaq[M_*R_];      // x @ A_q^T
__device__ float g_xav[M_*R_];      // x @ A_v^T

// ---------------- LoRA rank-4 projections: xa = x @ A^T ----------------
__global__ void lora_xa_kernel(const float* __restrict__ x,
                               const float* __restrict__ Aq,
                               const float* __restrict__ Av,
                               const int*   __restrict__ stepp) {
    int m    = blockIdx.x;
    int w    = threadIdx.x >> 5;
    int lane = threadIdx.x & 31;
    int step = *stepp;
    bool ok  = (step >= 0 && step < NSTEPS_);
    const float* xr = x + (size_t)m * DIM_;
    float acc = 0.f;
    if (ok) {
        const float* A = (w < 4)
            ? (Aq + ((size_t)step * R_ + w) * DIM_)
            : (Av + ((size_t)step * R_ + (w - 4)) * DIM_);
        #pragma unroll 4
        for (int k = lane; k < DIM_; k += 32) acc += xr[k] * A[k];
    }
    #pragma unroll
    for (int o = 16; o; o >>= 1) acc += __shfl_xor_sync(0xffffffffu, acc, o);
    if (lane == 0) {
        if (w < 4) g_xaq[m * R_ + w]       = acc;
        else       g_xav[m * R_ + (w - 4)] = acc;
    }
}

// ---------------- SGEMM  Y[m,n] = sum_k X[m,k] * W[n,k]  (+ LoRA epilogue) ----------------
// MODE 0: Q  (N=1024, lora=g_xaq)   MODE 1: K (N=256)
// MODE 2: V  (N=256,  lora=g_xav)   MODE 3: proj (N=1024, X=g_y, Y=out)
template<int MODE>
__global__ void gemm_kernel(const float* __restrict__ xin,
                            const float* __restrict__ W,
                            const float* __restrict__ loraB,
                            const int*   __restrict__ stepp,
                            float*       __restrict__ out) {
    constexpr int N = (MODE == 0 || MODE == 3) ? 1024 : 256;
    const float* X = (MODE == 3) ? g_y : xin;
    float* Y = (MODE == 0) ? g_q : (MODE == 1) ? g_k : (MODE == 2) ? g_v : out;

    __shared__ float As[16][64];
    __shared__ float Bs[16][64];

    int m0 = blockIdx.y * 64;
    int n0 = blockIdx.x * 64;
    int tid = threadIdx.x;
    int ty = tid >> 4, tx = tid & 15;

    float c[4][4] = {};

    for (int k0 = 0; k0 < DIM_; k0 += 16) {
        #pragma unroll
        for (int i = 0; i < 4; i++) {
            int e  = tid + i * 256;
            int mm = e >> 4, kk = e & 15;
            As[kk][mm] = X[(size_t)(m0 + mm) * DIM_ + k0 + kk];
            Bs[kk][mm] = W[(size_t)(n0 + mm) * DIM_ + k0 + kk];
        }
        __syncthreads();
        #pragma unroll
        for (int kk = 0; kk < 16; kk++) {
            float4 a = *(const float4*)&As[kk][ty * 4];
            float4 b = *(const float4*)&Bs[kk][tx * 4];
            c[0][0] += a.x*b.x; c[0][1] += a.x*b.y; c[0][2] += a.x*b.z; c[0][3] += a.x*b.w;
            c[1][0] += a.y*b.x; c[1][1] += a.y*b.y; c[1][2] += a.y*b.z; c[1][3] += a.y*b.w;
            c[2][0] += a.z*b.x; c[2][1] += a.z*b.y; c[2][2] += a.z*b.z; c[2][3] += a.z*b.w;
            c[3][0] += a.w*b.x; c[3][1] += a.w*b.y; c[3][2] += a.w*b.z; c[3][3] += a.w*b.w;
        }
        __syncthreads();
    }

    // LoRA epilogue: c[m,n] += sum_r xa[m,r] * loraB[n,r]
    if (MODE == 0 || MODE == 2) {
        int step = *stepp;
        if (step >= 0 && step < NSTEPS_) {
            const float* xa = (MODE == 0) ? g_xaq : g_xav;
            const float* Bp = loraB + (size_t)step * N * R_;
            #pragma unroll
            for (int i = 0; i < 4; i++) {
                int m = m0 + ty * 4 + i;
                float4 xm = *(const float4*)&xa[m * R_];
                #pragma unroll
                for (int j = 0; j < 4; j++) {
                    int n = n0 + tx * 4 + j;
                    float4 bb = *(const float4*)&Bp[n * R_];
                    c[i][j] += xm.x*bb.x + xm.y*bb.y + xm.z*bb.z + xm.w*bb.w;
                }
            }
        }
    }

    #pragma unroll
    for (int i = 0; i < 4; i++) {
        int m = m0 + ty * 4 + i;
        #pragma unroll
        for (int j = 0; j < 4; j++) {
            int n = n0 + tx * 4 + j;
            Y[(size_t)m * N + n] = c[i][j];
        }
    }
}

// ---------------- per-head RMSNorm + partial RoPE (+ gain for Q) ----------------
template<bool QSIDE>
__global__ void rms_rope_kernel(const float* __restrict__ gain) {
    const int NH = QSIDE ? H_ : KVH_;
    float* buf = QSIDE ? g_q : g_k;

    int gw   = blockIdx.x * (blockDim.x >> 5) + (threadIdx.x >> 5);
    int lane = threadIdx.x & 31;
    if (gw >= M_ * NH) return;

    int h  = gw % NH;
    int ms = gw / NH;          // b*S + s
    int s  = ms % S_;

    float* p = buf + (size_t)ms * (NH * HD_) + h * HD_;
    float v0 = p[lane];
    float v1 = p[lane + 32];

    float ss = v0 * v0 + v1 * v1;
    #pragma unroll
    for (int o = 16; o; o >>= 1) ss += __shfl_xor_sync(0xffffffffu, ss, o);
    float r = rsqrtf(ss * (1.0f / 64.0f) + 1.1920929e-7f);
    v0 *= r; v1 *= r;

    // partial RoPE on dims [0,32): out[i]    = x1*c + x2*s
    //                              out[i+16] = -x1*s + x2*c
    int   i    = lane & 15;
    float invf = 1.0f / powf(10000.0f, (float)(2 * i) / 32.0f);
    float ang  = (float)s * invf;
    float cc = cosf(ang), sn = sinf(ang);
    float other = __shfl_xor_sync(0xffffffffu, v0, 16);
    float nv0 = (lane < 16) ? (v0 * cc + other * sn)
                            : (-other * sn + v0 * cc);

    float g = 1.0f;
    if (QSIDE) g = gain[h];
    p[lane]      = nv0 * g;
    p[lane + 32] = v1  * g;
}

// ---------------- fp32 causal flash attention, 64q x 64k tiles ----------------
#define FA_SMEM_FLOATS (64*64 + 64*68 + 64*64 + 64*68)
#define FA_SMEM_BYTES  (FA_SMEM_FLOATS * 4)

__global__ void flash_attn_kernel() {
    extern __shared__ float sm[];
    float* Qs = sm;                 // [d][q]  64x64 (transposed, pre-scaled)
    float* Ks = Qs + 64 * 64;       // [d][k]  64x68 (transposed, padded)
    float* Vs = Ks + 64 * 68;       // [k][d]  64x64
    float* Ps = Vs + 64 * 64;       // [k][q]  64x68 (transposed, padded)

    int b   = blockIdx.z;
    int h   = blockIdx.y;
    int q0  = blockIdx.x * 64;
    int kvh = h >> 2;
    int tid = threadIdx.x;
    int ty  = tid >> 4, tx = tid & 15;

    // load Q tile transposed, pre-scaled by 1/sqrt(64)
    for (int e = tid; e < 4096; e += 256) {
        int qq = e >> 6, d = e & 63;
        Qs[d * 64 + qq] =
            g_q[(size_t)(b * S_ + q0 + qq) * DIM_ + h * HD_ + d] * 0.125f;
    }

    float m[4], l[4], o[4][4];
    #pragma unroll
    for (int i = 0; i < 4; i++) {
        m[i] = -INFINITY; l[i] = 0.f;
        #pragma unroll
        for (int j = 0; j < 4; j++) o[i][j] = 0.f;
    }

    for (int j0 = 0; j0 <= q0; j0 += 64) {
        __syncthreads();  // Qs visible (iter 0) / prev gemm2 done
        for (int e = tid; e < 4096; e += 256) {
            int kj = e >> 6, d = e & 63;
            size_t gi = (size_t)(b * S_ + j0 + kj) * KVDIM_ + kvh * HD_ + d;
            Ks[d * 68 + kj] = g_k[gi];
            Vs[kj * 64 + d] = g_v[gi];
        }
        __syncthreads();

        float sf[4][4] = {};
        #pragma unroll 8
        for (int kk = 0; kk < 64; kk++) {
            float4 a = *(const float4*)&Qs[kk * 64 + ty * 4];
            float4 bk = *(const float4*)&Ks[kk * 68 + tx * 4];
            sf[0][0] += a.x*bk.x; sf[0][1] += a.x*bk.y; sf[0][2] += a.x*bk.z; sf[0][3] += a.x*bk.w;
            sf[1][0] += a.y*bk.x; sf[1][1] += a.y*bk.y; sf[1][2] += a.y*bk.z; sf[1][3] += a.y*bk.w;
            sf[2][0] += a.z*bk.x; sf[2][1] += a.z*bk.y; sf[2][2] += a.z*bk.z; sf[2][3] += a.z*bk.w;
            sf[3][0] += a.w*bk.x; sf[3][1] += a.w*bk.y; sf[3][2] += a.w*bk.z; sf[3][3] += a.w*bk.w;
        }

        if (j0 == q0) {  // diagonal tile: mask key > query
            #pragma unroll
            for (int i = 0; i < 4; i++)
                #pragma unroll
                for (int j = 0; j < 4; j++)
                    if (tx * 4 + j > ty * 4 + i) sf[i][j] = -INFINITY;
        }

        // online softmax per row (replicated across the 16 tx threads)
        #pragma unroll
        for (int i = 0; i < 4; i++) {
            float rm = fmaxf(fmaxf(sf[i][0], sf[i][1]), fmaxf(sf[i][2], sf[i][3]));
            #pragma unroll
            for (int oo = 8; oo; oo >>= 1)
                rm = fmaxf(rm, __shfl_xor_sync(0xffffffffu, rm, oo));
            float mn    = fmaxf(m[i], rm);
            float alpha = __expf(m[i] - mn);
            float rs = 0.f;
            float pr[4];
            #pragma unroll
            for (int j = 0; j < 4; j++) { pr[j] = __expf(sf[i][j] - mn); rs += pr[j]; }
            #pragma unroll
            for (int oo = 8; oo; oo >>= 1)
                rs += __shfl_xor_sync(0xffffffffu, rs, oo);
            l[i] = l[i] * alpha + rs;
            m[i] = mn;
            #pragma unroll
            for (int j = 0; j < 4; j++) o[i][j] *= alpha;
            #pragma unroll
            for (int j = 0; j < 4; j++)
                Ps[(tx * 4 + j) * 68 + ty * 4 + i] = pr[j];
        }
        __syncthreads();  // Ps visible

        #pragma unroll 8
        for (int kk = 0; kk < 64; kk++) {
            float4 a = *(const float4*)&Ps[kk * 68 + ty * 4];
            float4 bv = *(const float4*)&Vs[kk * 64 + tx * 4];
            o[0][0] += a.x*bv.x; o[0][1] += a.x*bv.y; o[0][2] += a.x*bv.z; o[0][3] += a.x*bv.w;
            o[1][0] += a.y*bv.x; o[1][1] += a.y*bv.y; o[1][2] += a.y*bv.z; o[1][3] += a.y*bv.w;
            o[2][0] += a.z*bv.x; o[2][1] += a.z*bv.y; o[2][2] += a.z*bv.z; o[2][3] += a.z*bv.w;
            o[3][0] += a.w*bv.x; o[3][1] += a.w*bv.y; o[3][2] += a.w*bv.z; o[3][3] += a.w*bv.w;
        }
    }

    #pragma unroll
    for (int i = 0; i < 4; i++) {
        int qi = q0 + ty * 4 + i;
        float inv = 1.0f / l[i];
        #pragma unroll
        for (int j = 0; j < 4; j++)
            g_y[(size_t)(b * S_ + qi) * DIM_ + h * HD_ + tx * 4 + j] = o[i][j] * inv;
    }
}

// ---------------- launch ----------------
extern "C" void kernel_launch(void* const* d_in, const int* in_sizes, int n_in,
                              void* d_out, int out_size) {
    const float* x    = (const float*)d_in[0];
    const float* Wq   = (const float*)d_in[1];
    const float* Wk   = (const float*)d_in[2];
    const float* Wv   = (const float*)d_in[3];
    const float* Wp   = (const float*)d_in[4];
    const float* gain = (const float*)d_in[5];
    const float* Aq   = (const float*)d_in[6];
    const float* Bq   = (const float*)d_in[7];
    const float* Av   = (const float*)d_in[8];
    const float* Bv   = (const float*)d_in[9];
    const int*   step = (const int*)d_in[10];
    float* out = (float*)d_out;

    lora_xa_kernel<<<M_, 256>>>(x, Aq, Av, step);

    gemm_kernel<0><<<dim3(DIM_/64,   M_/64), 256>>>(x, Wq, Bq,      step, nullptr);
    gemm_kernel<1><<<dim3(KVDIM_/64, M_/64), 256>>>(x, Wk, nullptr, step, nullptr);
    gemm_kernel<2><<<dim3(KVDIM_/64, M_/64), 256>>>(x, Wv, Bv,      step, nullptr);

    rms_rope_kernel<true ><<<(M_*H_)  / 8, 256>>>(gain);
    rms_rope_kernel<false><<<(M_*KVH_)/ 8, 256>>>(nullptr);

    cudaFuncSetAttribute(flash_attn_kernel,
                         cudaFuncAttributeMaxDynamicSharedMemorySize, FA_SMEM_BYTES);
    flash_attn_kernel<<<dim3(S_/64, H_, B_), 256, FA_SMEM_BYTES>>>();

    gemm_kernel<3><<<dim3(DIM_/64, M_/64), 256>>>(nullptr, Wp, nullptr, step, out);
}

// round 2
// speedup vs baseline: 1.4299x; 1.4299x over previous
#include <cuda_runtime.h>
#include <math.h>

#define B_      2
#define S_      2048
#define DIM_    1024
#define H_      16
#define KVH_    4
#define HD_     64
#define KVDIM_  256
#define R_      4
#define NSTEPS_ 2
#define M_      (B_*S_)

typedef unsigned long long ull;

// ---------------- f32x2 packed math (FFMA2 — ptxas won't emit from C++) ----------------
__device__ __forceinline__ ull pk2(float x, float y) {
    ull r; asm("mov.b64 %0, {%1, %2};" : "=l"(r) : "f"(x), "f"(y)); return r;
}
__device__ __forceinline__ void up2(float& x, float& y, ull v) {
    asm("mov.b64 {%0, %1}, %2;" : "=f"(x), "=f"(y) : "l"(v));
}
__device__ __forceinline__ void fma2(ull& d, ull a, ull b) {
    asm("fma.rn.f32x2 %0, %1, %2, %0;" : "+l"(d) : "l"(a), "l"(b));
}
__device__ __forceinline__ void mul2(ull& d, ull a) {
    asm("mul.rn.f32x2 %0, %0, %1;" : "+l"(d) : "l"(a));
}

// ---------------- scratch ----------------
__device__ float g_q[M_*DIM_];
__device__ float g_k[M_*KVDIM_];
__device__ float g_v[M_*KVDIM_];
__device__ float g_y[M_*DIM_];
__device__ float g_xaq[M_*R_];
__device__ float g_xav[M_*R_];

// ---------------- LoRA rank-4: xa = x @ A^T ----------------
__global__ void lora_xa_kernel(const float* __restrict__ x,
                               const float* __restrict__ Aq,
                               const float* __restrict__ Av,
                               const int*   __restrict__ stepp) {
    int m = blockIdx.x, w = threadIdx.x >> 5, lane = threadIdx.x & 31;
    int step = *stepp;
    bool ok = (step >= 0 && step < NSTEPS_);
    const float* xr = x + (size_t)m * DIM_;
    float acc = 0.f;
    if (ok) {
        const float* A = (w < 4) ? (Aq + ((size_t)step * R_ + w) * DIM_)
                                 : (Av + ((size_t)step * R_ + (w - 4)) * DIM_);
        #pragma unroll 4
        for (int k = lane; k < DIM_; k += 32) acc += xr[k] * A[k];
    }
    #pragma unroll
    for (int o = 16; o; o >>= 1) acc += __shfl_xor_sync(0xffffffffu, acc, o);
    if (lane == 0) { if (w < 4) g_xaq[m*R_+w] = acc; else g_xav[m*R_+(w-4)] = acc; }
}

// ---------------- SGEMM  Y[m,n] = sum_k X[m,k] W[n,k]  (FFMA2, BMx128 tiles, 8x8/thr)
// MODE 0: Q (N=1024, BM=128) | MODE 1: fused K+V (N=512, BM=64) | MODE 2: proj (BM=128)
template<int BM, int MODE>
__global__ void __launch_bounds__(BM*2)
gemm_kernel(const float* __restrict__ xin,
            const float* __restrict__ W0,   // Q: Wq | KV: Wk | proj: Wproj
            const float* __restrict__ W1,   // KV: Wv
            const float* __restrict__ loraB,
            const int*   __restrict__ stepp,
            float*       __restrict__ out) {
    constexpr int THREADS = BM * 2;
    constexpr int N = (MODE == 1) ? 512 : 1024;
    const float* X = (MODE == 2) ? g_y : xin;

    __shared__ float As[16 * BM];
    __shared__ float Bs[16 * 128];

    int m0 = blockIdx.y * BM;
    int n0 = blockIdx.x * 128;
    int tid = threadIdx.x;
    int ty = tid >> 4, tx = tid & 15;

    ull c2[8][4];
    #pragma unroll
    for (int i = 0; i < 8; i++)
        #pragma unroll
        for (int p = 0; p < 4; p++) c2[i][p] = 0ULL;

    for (int k0 = 0; k0 < DIM_; k0 += 16) {
        // load A tile (transposed to k-major)
        #pragma unroll
        for (int t = 0; t < (BM*4)/THREADS; t++) {
            int idx = tid + t * THREADS;
            int mm = idx >> 2, kv = idx & 3;
            float4 v = *(const float4*)&X[(size_t)(m0+mm)*DIM_ + k0 + kv*4];
            As[(kv*4+0)*BM+mm]=v.x; As[(kv*4+1)*BM+mm]=v.y;
            As[(kv*4+2)*BM+mm]=v.z; As[(kv*4+3)*BM+mm]=v.w;
        }
        // load B tile
        #pragma unroll
        for (int t = 0; t < 512/THREADS; t++) {
            int idx = tid + t * THREADS;
            int nn = idx >> 2, kv = idx & 3;
            int row = n0 + nn;
            const float* Wr = (MODE == 1)
                ? ((row < 256) ? W0 + (size_t)row*DIM_ : W1 + (size_t)(row-256)*DIM_)
                : W0 + (size_t)row*DIM_;
            float4 v = *(const float4*)&Wr[k0 + kv*4];
            Bs[(kv*4+0)*128+nn]=v.x; Bs[(kv*4+1)*128+nn]=v.y;
            Bs[(kv*4+2)*128+nn]=v.z; Bs[(kv*4+3)*128+nn]=v.w;
        }
        __syncthreads();
        #pragma unroll
        for (int kk = 0; kk < 16; kk++) {
            float4 a0 = *(const float4*)&As[kk*BM + ty*8];
            float4 a1 = *(const float4*)&As[kk*BM + ty*8 + 4];
            ulonglong2 bl0 = *(const ulonglong2*)&Bs[kk*128 + tx*8];
            ulonglong2 bl1 = *(const ulonglong2*)&Bs[kk*128 + tx*8 + 4];
            ull b[4] = {bl0.x, bl0.y, bl1.x, bl1.y};
            float av[8] = {a0.x,a0.y,a0.z,a0.w,a1.x,a1.y,a1.z,a1.w};
            #pragma unroll
            for (int i = 0; i < 8; i++) {
                ull ad = pk2(av[i], av[i]);
                #pragma unroll
                for (int p = 0; p < 4; p++) fma2(c2[i][p], ad, b[p]);
            }
        }
        __syncthreads();
    }

    // unpack
    float c[8][8];
    #pragma unroll
    for (int i = 0; i < 8; i++)
        #pragma unroll
        for (int p = 0; p < 4; p++) up2(c[i][2*p], c[i][2*p+1], c2[i][p]);

    // LoRA epilogue
    bool do_lora = (MODE == 0) || (MODE == 1 && n0 >= 256);
    if (do_lora) {
        int step = *stepp;
        if (step >= 0 && step < NSTEPS_) {
            const float* xa = (MODE == 0) ? g_xaq : g_xav;
            int nbase = (MODE == 1) ? (n0 - 256) : n0;
            const float* Bp = loraB + (size_t)step * ((MODE==0)?1024:256) * R_;
            #pragma unroll
            for (int i = 0; i < 8; i++) {
                float4 xm = *(const float4*)&xa[(m0 + ty*8 + i) * R_];
                #pragma unroll
                for (int j = 0; j < 8; j++) {
                    float4 bb = *(const float4*)&Bp[(nbase + tx*8 + j) * R_];
                    c[i][j] += xm.x*bb.x + xm.y*bb.y + xm.z*bb.z + xm.w*bb.w;
                }
            }
        }
    }

    // store
    #pragma unroll
    for (int i = 0; i < 8; i++) {
        int m = m0 + ty*8 + i;
        int n = n0 + tx*8;
        float4 r0 = {c[i][0],c[i][1],c[i][2],c[i][3]};
        float4 r1 = {c[i][4],c[i][5],c[i][6],c[i][7]};
        if (MODE == 0) {
            *(float4*)&g_q[(size_t)m*1024 + n] = r0;
            *(float4*)&g_q[(size_t)m*1024 + n + 4] = r1;
        } else if (MODE == 2) {
            *(float4*)&out[(size_t)m*1024 + n] = r0;
            *(float4*)&out[(size_t)m*1024 + n + 4] = r1;
        } else {
            if (n0 < 256) {
                *(float4*)&g_k[(size_t)m*256 + n] = r0;
                *(float4*)&g_k[(size_t)m*256 + n + 4] = r1;
            } else {
                *(float4*)&g_v[(size_t)m*256 + (n-256)] = r0;
                *(float4*)&g_v[(size_t)m*256 + (n-256) + 4] = r1;
            }
        }
    }
}

// ---------------- per-head RMSNorm + partial RoPE (+ gain) ----------------
template<bool QSIDE>
__global__ void rms_rope_kernel(const float* __restrict__ gain) {
    const int NH = QSIDE ? H_ : KVH_;
    float* buf = QSIDE ? g_q : g_k;
    int gw = blockIdx.x * (blockDim.x >> 5) + (threadIdx.x >> 5);
    int lane = threadIdx.x & 31;
    if (gw >= M_ * NH) return;
    int h = gw % NH, ms = gw / NH, s = ms % S_;
    float* p = buf + (size_t)ms * (NH*HD_) + h * HD_;
    float v0 = p[lane], v1 = p[lane + 32];
    float ss = v0*v0 + v1*v1;
    #pragma unroll
    for (int o = 16; o; o >>= 1) ss += __shfl_xor_sync(0xffffffffu, ss, o);
    float r = rsqrtf(ss * (1.0f/64.0f) + 1.1920929e-7f);
    v0 *= r; v1 *= r;
    int i = lane & 15;
    float invf = 1.0f / powf(10000.0f, (float)(2*i) / 32.0f);
    float ang = (float)s * invf;
    float cc = cosf(ang), sn = sinf(ang);
    float other = __shfl_xor_sync(0xffffffffu, v0, 16);
    float nv0 = (lane < 16) ? (v0*cc + other*sn) : (-other*sn + v0*cc);
    float g = 1.0f;
    if (QSIDE) g = gain[h];
    p[lane] = nv0 * g;
    p[lane + 32] = v1 * g;
}

// ---------------- causal flash attention: 128q x 128k tiles, FFMA2 ----------------
#define FA_SMEM_FLOATS (64*128 + 64*128 + 128*64 + 128*128)
#define FA_SMEM_BYTES  (FA_SMEM_FLOATS * 4)

__global__ void __launch_bounds__(256)
flash_attn_kernel() {
    extern __shared__ float sm[];
    float* Qs = sm;                  // [d][q]  64x128 (pre-scaled)
    float* Ks = Qs + 64*128;         // [d][k]  64x128
    float* Vs = Ks + 64*128;         // [k][d]  128x64
    float* Ps = Vs + 128*64;         // [q][k]  128x128

    int b = blockIdx.z, h = blockIdx.y;
    int q0 = (gridDim.x - 1 - blockIdx.x) * 128;   // big tiles first
    int kvh = h >> 2;
    int tid = threadIdx.x;
    int ty = tid >> 4, tx = tid & 15;

    for (int e = tid; e < 128*64; e += 256) {
        int q = e >> 6, d = e & 63;
        Qs[d*128 + q] = g_q[(size_t)(b*S_ + q0 + q)*DIM_ + h*HD_ + d] * 0.125f;
    }

    float m[8], l[8];
    ull o2[8][2];
    #pragma unroll
    for (int i = 0; i < 8; i++) { m[i] = -INFINITY; l[i] = 0.f; o2[i][0]=0ULL; o2[i][1]=0ULL; }

    for (int j0 = 0; j0 <= q0; j0 += 128) {
        __syncthreads();
        for (int e = tid; e < 128*64; e += 256) {
            int kj = e >> 6, d = e & 63;
            size_t gi = (size_t)(b*S_ + j0 + kj)*KVDIM_ + kvh*HD_ + d;
            Ks[d*128 + kj] = g_k[gi];
            Vs[kj*64 + d]  = g_v[gi];
        }
        __syncthreads();

        // scores: sf2[8 q][4 k-pairs]
        ull sf2[8][4];
        #pragma unroll
        for (int i = 0; i < 8; i++)
            #pragma unroll
            for (int p = 0; p < 4; p++) sf2[i][p] = 0ULL;

        #pragma unroll 4
        for (int kk = 0; kk < 64; kk++) {
            float4 a0 = *(const float4*)&Qs[kk*128 + ty*8];
            float4 a1 = *(const float4*)&Qs[kk*128 + ty*8 + 4];
            ulonglong2 bl0 = *(const ulonglong2*)&Ks[kk*128 + tx*8];
            ulonglong2 bl1 = *(const ulonglong2*)&Ks[kk*128 + tx*8 + 4];
            ull bb[4] = {bl0.x, bl0.y, bl1.x, bl1.y};
            float av[8] = {a0.x,a0.y,a0.z,a0.w,a1.x,a1.y,a1.z,a1.w};
            #pragma unroll
            for (int i = 0; i < 8; i++) {
                ull ad = pk2(av[i], av[i]);
                #pragma unroll
                for (int p = 0; p < 4; p++) fma2(sf2[i][p], ad, bb[p]);
            }
        }

        float sf[8][8];
        #pragma unroll
        for (int i = 0; i < 8; i++)
            #pragma unroll
            for (int p = 0; p < 4; p++) up2(sf[i][2*p], sf[i][2*p+1], sf2[i][p]);

        if (j0 == q0) {
            #pragma unroll
            for (int i = 0; i < 8; i++)
                #pragma unroll
                for (int j = 0; j < 8; j++)
                    if (tx*8 + j > ty*8 + i) sf[i][j] = -INFINITY;
        }

        // online softmax (row reduce over 16 tx lanes)
        #pragma unroll
        for (int i = 0; i < 8; i++) {
            float rm = sf[i][0];
            #pragma unroll
            for (int j = 1; j < 8; j++) rm = fmaxf(rm, sf[i][j]);
            #pragma unroll
            for (int oo = 8; oo; oo >>= 1)
                rm = fmaxf(rm, __shfl_xor_sync(0xffffffffu, rm, oo));
            float mn = fmaxf(m[i], rm);
            float alpha = __expf(m[i] - mn);
            m[i] = mn;
            float rs = 0.f;
            #pragma unroll
            for (int j = 0; j < 8; j++) { sf[i][j] = __expf(sf[i][j] - mn); rs += sf[i][j]; }
            #pragma unroll
            for (int oo = 8; oo; oo >>= 1)
                rs += __shfl_xor_sync(0xffffffffu, rs, oo);
            l[i] = l[i]*alpha + rs;
            ull a2 = pk2(alpha, alpha);
            mul2(o2[i][0], a2);
            mul2(o2[i][1], a2);
            float4 w0 = {sf[i][0],sf[i][1],sf[i][2],sf[i][3]};
            float4 w1 = {sf[i][4],sf[i][5],sf[i][6],sf[i][7]};
            *(float4*)&Ps[(ty*8+i)*128 + tx*8]     = w0;
            *(float4*)&Ps[(ty*8+i)*128 + tx*8 + 4] = w1;
        }
        __syncthreads();

        // o += P @ V : per-thread 8q x 4d, read P in float4 chunks of 4 k
        #pragma unroll 2
        for (int kk4 = 0; kk4 < 128; kk4 += 4) {
            float4 a4[8];
            #pragma unroll
            for (int i = 0; i < 8; i++)
                a4[i] = *(const float4*)&Ps[(ty*8+i)*128 + kk4];
            #pragma unroll
            for (int kkk = 0; kkk < 4; kkk++) {
                ulonglong2 bv = *(const ulonglong2*)&Vs[(kk4+kkk)*64 + tx*4];
                #pragma unroll
                for (int i = 0; i < 8; i++) {
                    float aval = ((const float*)&a4[i])[kkk];
                    ull ad = pk2(aval, aval);
                    fma2(o2[i][0], ad, bv.x);
                    fma2(o2[i][1], ad, bv.y);
                }
            }
        }
    }

    #pragma unroll
    for (int i = 0; i < 8; i++) {
        float inv = 1.0f / l[i];
        float x0,x1,x2,x3;
        up2(x0, x1, o2[i][0]);
        up2(x2, x3, o2[i][1]);
        float4 r = {x0*inv, x1*inv, x2*inv, x3*inv};
        *(float4*)&g_y[(size_t)(b*S_ + q0 + ty*8 + i)*DIM_ + h*HD_ + tx*4] = r;
    }
}

// ---------------- launch ----------------
extern "C" void kernel_launch(void* const* d_in, const int* in_sizes, int n_in,
                              void* d_out, int out_size) {
    const float* x    = (const float*)d_in[0];
    const float* Wq   = (const float*)d_in[1];
    const float* Wk   = (const float*)d_in[2];
    const float* Wv   = (const float*)d_in[3];
    const float* Wp   = (const float*)d_in[4];
    const float* gain = (const float*)d_in[5];
    const float* Aq   = (const float*)d_in[6];
    const float* Bq   = (const float*)d_in[7];
    const float* Av   = (const float*)d_in[8];
    const float* Bv   = (const float*)d_in[9];
    const int*   step = (const int*)d_in[10];
    float* out = (float*)d_out;

    lora_xa_kernel<<<M_, 256>>>(x, Aq, Av, step);

    gemm_kernel<128,0><<<dim3(1024/128, M_/128), 256>>>(x, Wq, nullptr, Bq, step, nullptr);
    gemm_kernel< 64,1><<<dim3( 512/128, M_/ 64), 128>>>(x, Wk, Wv,      Bv, step, nullptr);

    rms_rope_kernel<true ><<<(M_*H_)  / 8, 256>>>(gain);
    rms_rope_kernel<false><<<(M_*KVH_)/ 8, 256>>>(nullptr);

    cudaFuncSetAttribute(flash_attn_kernel,
                         cudaFuncAttributeMaxDynamicSharedMemorySize, FA_SMEM_BYTES);
    flash_attn_kernel<<<dim3(S_/128, H_, B_), 256, FA_SMEM_BYTES>>>();

    gemm_kernel<128,2><<<dim3(1024/128, M_/128), 256>>>(nullptr, Wp, nullptr, nullptr, step, out);
}

// round 4
// speedup vs baseline: 1.9815x; 1.3857x over previous
#include <cuda_runtime.h>
#include <cuda_bf16.h>
#include <math.h>
#include <stdint.h>

#define B_      2
#define S_      2048
#define DIM_    1024
#define H_      16
#define KVH_    4
#define HD_     64
#define KVDIM_  256
#define R_      4
#define NSTEPS_ 2
#define M_      (B_*S_)
#define WROWS_  2560   // [0,1024): Wq+lora | [1024,1280): Wk | [1280,1536): Wv+lora | [1536,2560): Wp

typedef unsigned long long ull;

// ---------------- f32x2 packed math (attention path) ----------------
__device__ __forceinline__ ull pk2(float x, float y) {
    ull r; asm("mov.b64 %0, {%1, %2};" : "=l"(r) : "f"(x), "f"(y)); return r;
}
__device__ __forceinline__ void up2(float& x, float& y, ull v) {
    asm("mov.b64 {%0, %1}, %2;" : "=f"(x), "=f"(y) : "l"(v));
}
__device__ __forceinline__ void fma2(ull& d, ull a, ull b) {
    asm("fma.rn.f32x2 %0, %1, %2, %0;" : "+l"(d) : "l"(a), "l"(b));
}
__device__ __forceinline__ void mul2(ull& d, ull a) {
    asm("mul.rn.f32x2 %0, %0, %1;" : "+l"(d) : "l"(a));
}

__device__ __forceinline__ uint32_t smem_u32(const void* p) {
    uint32_t a;
    asm("{ .reg .u64 t; cvta.to.shared.u64 t, %1; cvt.u32.u64 %0, t; }" : "=r"(a) : "l"(p));
    return a;
}

#define LDSM4(r, addr) \
    asm volatile("ldmatrix.sync.aligned.m8n8.x4.shared.b16 {%0,%1,%2,%3}, [%4];" \
        : "=r"((r)[0]),"=r"((r)[1]),"=r"((r)[2]),"=r"((r)[3]) : "r"(addr))

#define MMA_BF16(c, a, b0v, b1v) \
    asm volatile("mma.sync.aligned.m16n8k16.row.col.f32.bf16.bf16.f32 " \
        "{%0,%1,%2,%3}, {%4,%5,%6,%7}, {%8,%9}, {%0,%1,%2,%3};" \
        : "+f"((c)[0]),"+f"((c)[1]),"+f"((c)[2]),"+f"((c)[3]) \
        : "r"((a)[0]),"r"((a)[1]),"r"((a)[2]),"r"((a)[3]), "r"(b0v),"r"(b1v))

#define CP_ASYNC16(dst, src) \
    asm volatile("cp.async.cg.shared.global [%0], [%1], 16;" :: "r"(dst), "l"(src) : "memory")
#define CP_COMMIT() asm volatile("cp.async.commit_group;" ::: "memory")
#define CP_WAIT(n)  asm volatile("cp.async.wait_group %0;" :: "n"(n) : "memory")

// ---------------- scratch ----------------
__device__ float g_q[M_*DIM_];
__device__ float g_k[M_*KVDIM_];
__device__ float g_v[M_*KVDIM_];
__device__ float g_y[M_*DIM_];
__device__ __nv_bfloat16 g_xhi[M_*DIM_], g_xlo[M_*DIM_];
__device__ __nv_bfloat16 g_yhi[M_*DIM_], g_ylo[M_*DIM_];
__device__ __nv_bfloat16 g_whi[WROWS_*DIM_], g_wlo[WROWS_*DIM_];

// ---------------- fp32 -> (hi, lo) bf16 ----------------
__device__ __forceinline__ void f2bf2(float x, unsigned short& h, unsigned short& l) {
    __nv_bfloat16 hb = __float2bfloat16_rn(x);
    __nv_bfloat16 lb = __float2bfloat16_rn(x - __bfloat162float(hb));
    h = __bfloat16_as_ushort(hb);
    l = __bfloat16_as_ushort(lb);
}

// generic fp32 matrix -> hi/lo bf16 (used for x and for g_y)
__global__ void prep_split_kernel(const float* __restrict__ src,
                                  __nv_bfloat16* __restrict__ hi,
                                  __nv_bfloat16* __restrict__ lo, int n4) {
    int t = blockIdx.x * blockDim.x + threadIdx.x;
    if (t >= n4) return;
    float4 v = ((const float4*)src)[t];
    unsigned short h0,h1,h2,h3,l0,l1,l2,l3;
    f2bf2(v.x,h0,l0); f2bf2(v.y,h1,l1); f2bf2(v.z,h2,l2); f2bf2(v.w,h3,l3);
    uint2 hp, lp;
    hp.x = (uint32_t)h0 | ((uint32_t)h1 << 16); hp.y = (uint32_t)h2 | ((uint32_t)h3 << 16);
    lp.x = (uint32_t)l0 | ((uint32_t)l1 << 16); lp.y = (uint32_t)l2 | ((uint32_t)l3 << 16);
    ((uint2*)hi)[t] = hp;
    ((uint2*)lo)[t] = lp;
}

// fold LoRA into weights, pack all four weight mats, split to hi/lo bf16
__global__ void prep_w_kernel(const float* __restrict__ Wq, const float* __restrict__ Wk,
                              const float* __restrict__ Wv, const float* __restrict__ Wp,
                              const float* __restrict__ Aq, const float* __restrict__ Bq,
                              const float* __restrict__ Av, const float* __restrict__ Bv,
                              const int*   __restrict__ stepp) {
    int t = blockIdx.x * blockDim.x + threadIdx.x;    // float4 slot
    if (t >= WROWS_ * 256) return;
    int row = t >> 8, k4 = t & 255;
    int step = *stepp;
    bool ok = (step >= 0 && step < NSTEPS_);
    float4 w;
    if (row < 1024) {
        w = ((const float4*)(Wq + (size_t)row * DIM_))[k4];
        if (ok) {
            const float* Ab = Aq + (size_t)step * R_ * DIM_;
            const float* Bb = Bq + ((size_t)step * DIM_ + row) * R_;
            #pragma unroll
            for (int r = 0; r < R_; r++) {
                float b = Bb[r];
                float4 a = ((const float4*)(Ab + (size_t)r * DIM_))[k4];
                w.x += b*a.x; w.y += b*a.y; w.z += b*a.z; w.w += b*a.w;
            }
        }
    } else if (row < 1280) {
        w = ((const float4*)(Wk + (size_t)(row - 1024) * DIM_))[k4];
    } else if (row < 1536) {
        int vr = row - 1280;
        w = ((const float4*)(Wv + (size_t)vr * DIM_))[k4];
        if (ok) {
            const float* Ab = Av + (size_t)step * R_ * DIM_;
            const float* Bb = Bv + ((size_t)step * KVDIM_ + vr) * R_;
            #pragma unroll
            for (int r = 0; r < R_; r++) {
                float b = Bb[r];
                float4 a = ((const float4*)(Ab + (size_t)r * DIM_))[k4];
                w.x += b*a.x; w.y += b*a.y; w.z += b*a.z; w.w += b*a.w;
            }
        }
    } else {
        w = ((const float4*)(Wp + (size_t)(row - 1536) * DIM_))[k4];
    }
    unsigned short h0,h1,h2,h3,l0,l1,l2,l3;
    f2bf2(w.x,h0,l0); f2bf2(w.y,h1,l1); f2bf2(w.z,h2,l2); f2bf2(w.w,h3,l3);
    uint2 hp, lp;
    hp.x = (uint32_t)h0 | ((uint32_t)h1 << 16); hp.y = (uint32_t)h2 | ((uint32_t)h3 << 16);
    lp.x = (uint32_t)l0 | ((uint32_t)l1 << 16); lp.y = (uint32_t)l2 | ((uint32_t)l3 << 16);
    ((uint2*)g_whi)[t] = hp;
    ((uint2*)g_wlo)[t] = lp;
}

// ---------------- mma.sync bf16x2-split GEMM: Y[m,n] = sum_k X[m,k] W[n,k] ----------------
// 128x128 CTA tile, BK=32, 2-stage cp.async pipeline, 8 warps of 32(m)x64(n).
// smem tile: 128 rows x 32 bf16, row stride 80B (conflict-free ldmatrix).
#define GT_      10240            // one tile (128*80)
#define GSTAGE_  (4*GT_)          // Xhi Xlo Whi Wlo
#define G_SMEM   (2*GSTAGE_)      // 81920

// MODE 0: Q (Woff=0, N=1024, out g_q) | MODE 1: KV (Woff=1024, N=512, out g_k/g_v)
// MODE 2: proj (Woff=1536, X=g_yhi/lo, out param)
template<int MODE>
__global__ void __launch_bounds__(256, 2)
gemm_mma_kernel(float* __restrict__ outp) {
    extern __shared__ char smem[];
    uint32_t sb = smem_u32(smem);
    constexpr int WOFF = (MODE == 0) ? 0 : (MODE == 1) ? 1024 : 1536;
    const __nv_bfloat16* Xhi = (MODE == 2) ? g_yhi : g_xhi;
    const __nv_bfloat16* Xlo = (MODE == 2) ? g_ylo : g_xlo;

    int m0 = blockIdx.y * 128, n0 = blockIdx.x * 128;
    int tid = threadIdx.x;
    int wid = tid >> 5, lane = tid & 31;
    int m_base = (wid >> 1) * 32, n_base = (wid & 1) * 64;
    int lrow = (lane & 7) + ((lane >> 3) & 1) * 8;
    int lcol = (lane >> 4) * 8;

    // loader: stage s gets k-chunk it
    auto load_stage = [&](int it, int s) {
        int k0 = it * 32;
        int row_half = tid >> 2;     // 0..63
        int q = tid & 3;
        #pragma unroll
        for (int t = 0; t < 8; t++) {
            int tile = t >> 1;
            int row = (t & 1) * 64 + row_half;
            const __nv_bfloat16* src;
            if (tile == 0)      src = Xhi  + (size_t)(m0 + row) * DIM_ + k0 + q * 8;
            else if (tile == 1) src = Xlo  + (size_t)(m0 + row) * DIM_ + k0 + q * 8;
            else if (tile == 2) src = g_whi + (size_t)(WOFF + n0 + row) * DIM_ + k0 + q * 8;
            else                src = g_wlo + (size_t)(WOFF + n0 + row) * DIM_ + k0 + q * 8;
            uint32_t dst = sb + s * GSTAGE_ + tile * GT_ + row * 80 + q * 16;
            CP_ASYNC16(dst, src);
        }
        CP_COMMIT();
    };

    float c[2][8][4];
    #pragma unroll
    for (int i = 0; i < 2; i++)
        #pragma unroll
        for (int j = 0; j < 8; j++)
            #pragma unroll
            for (int p = 0; p < 4; p++) c[i][j][p] = 0.f;

    load_stage(0, 0);

    for (int it = 0; it < 32; it++) {
        if (it < 31) { load_stage(it + 1, (it + 1) & 1); CP_WAIT(1); }
        else         { CP_WAIT(0); }
        __syncthreads();

        uint32_t base = sb + (it & 1) * GSTAGE_;
        uint32_t sXhi = base, sWhi = base + 2 * GT_;

        #pragma unroll
        for (int ks = 0; ks < 2; ks++) {
            int kb = ks * 16;
            uint32_t ahi[2][4], alo[2][4];
            #pragma unroll
            for (int mc = 0; mc < 2; mc++) {
                uint32_t aaddr = sXhi + (m_base + mc * 16 + lrow) * 80 + (kb + lcol) * 2;
                LDSM4(ahi[mc], aaddr);
                LDSM4(alo[mc], aaddr + GT_);
            }
            #pragma unroll
            for (int nc = 0; nc < 4; nc++) {
                uint32_t baddr = sWhi + (n_base + nc * 16 + lrow) * 80 + (kb + lcol) * 2;
                uint32_t bhi[4], blo[4];
                LDSM4(bhi, baddr);
                LDSM4(blo, baddr + GT_);
                #pragma unroll
                for (int mc = 0; mc < 2; mc++) {
                    MMA_BF16(c[mc][nc*2],   ahi[mc], bhi[0], bhi[2]);
                    MMA_BF16(c[mc][nc*2],   ahi[mc], blo[0], blo[2]);
                    MMA_BF16(c[mc][nc*2],   alo[mc], bhi[0], bhi[2]);
                    MMA_BF16(c[mc][nc*2+1], ahi[mc], bhi[1], bhi[3]);
                    MMA_BF16(c[mc][nc*2+1], ahi[mc], blo[1], blo[3]);
                    MMA_BF16(c[mc][nc*2+1], alo[mc], bhi[1], bhi[3]);
                }
            }
        }
        __syncthreads();
    }

    // epilogue: direct stores (float2 per fragment row)
    #pragma unroll
    for (int mc = 0; mc < 2; mc++) {
        #pragma unroll
        for (int nf = 0; nf < 8; nf++) {
            int gr = m0 + m_base + mc * 16 + (lane >> 2);
            int gc = n0 + n_base + nf * 8 + (lane & 3) * 2;
            float2 v0 = make_float2(c[mc][nf][0], c[mc][nf][1]);
            float2 v1 = make_float2(c[mc][nf][2], c[mc][nf][3]);
            if (MODE == 0) {
                *(float2*)&g_q[(size_t)gr * 1024 + gc] = v0;
                *(float2*)&g_q[(size_t)(gr + 8) * 1024 + gc] = v1;
            } else if (MODE == 2) {
                *(float2*)&outp[(size_t)gr * 1024 + gc] = v0;
                *(float2*)&outp[(size_t)(gr + 8) * 1024 + gc] = v1;
            } else {
                if (gc < 256) {
                    *(float2*)&g_k[(size_t)gr * 256 + gc] = v0;
                    *(float2*)&g_k[(size_t)(gr + 8) * 256 + gc] = v1;
                } else {
                    *(float2*)&g_v[(size_t)gr * 256 + gc - 256] = v0;
                    *(float2*)&g_v[(size_t)(gr + 8) * 256 + gc - 256] = v1;
                }
            }
        }
    }
}

// ---------------- per-head RMSNorm + partial RoPE (+ gain) ----------------
template<bool QSIDE>
__global__ void rms_rope_kernel(const float* __restrict__ gain) {
    const int NH = QSIDE ? H_ : KVH_;
    float* buf = QSIDE ? g_q : g_k;
    int gw = blockIdx.x * (blockDim.x >> 5) + (threadIdx.x >> 5);
    int lane = threadIdx.x & 31;
    if (gw >= M_ * NH) return;
    int h = gw % NH, ms = gw / NH, s = ms % S_;
    float* p = buf + (size_t)ms * (NH*HD_) + h * HD_;
    float v0 = p[lane], v1 = p[lane + 32];
    float ss = v0*v0 + v1*v1;
    #pragma unroll
    for (int o = 16; o; o >>= 1) ss += __shfl_xor_sync(0xffffffffu, ss, o);
    float r = rsqrtf(ss * (1.0f/64.0f) + 1.1920929e-7f);
    v0 *= r; v1 *= r;
    int i = lane & 15;
    float invf = 1.0f / powf(10000.0f, (float)(2*i) / 32.0f);
    float ang = (float)s * invf;
    float cc = cosf(ang), sn = sinf(ang);
    float other = __shfl_xor_sync(0xffffffffu, v0, 16);
    float nv0 = (lane < 16) ? (v0*cc + other*sn) : (-other*sn + v0*cc);
    float g = 1.0f;
    if (QSIDE) g = gain[h];
    p[lane] = nv0 * g;
    p[lane + 32] = v1 * g;
}

// ---------------- causal flash attention: 128q x 128k, FFMA2 ----------------
#define FA_SMEM_FLOATS (64*128 + 64*128 + 128*64 + 128*128)
#define FA_SMEM_BYTES  (FA_SMEM_FLOATS * 4)

__global__ void __launch_bounds__(256)
flash_attn_kernel() {
    extern __shared__ float sm[];
    float* Qs = sm;
    float* Ks = Qs + 64*128;
    float* Vs = Ks + 64*128;
    float* Ps = Vs + 128*64;

    int b = blockIdx.z, h = blockIdx.y;
    int q0 = (gridDim.x - 1 - blockIdx.x) * 128;
    int kvh = h >> 2;
    int tid = threadIdx.x;
    int ty = tid >> 4, tx = tid & 15;

    for (int e = tid; e < 128*64; e += 256) {
        int q = e >> 6, d = e & 63;
        Qs[d*128 + q] = g_q[(size_t)(b*S_ + q0 + q)*DIM_ + h*HD_ + d] * 0.125f;
    }

    float m[8], l[8];
    ull o2[8][2];
    #pragma unroll
    for (int i = 0; i < 8; i++) { m[i] = -INFINITY; l[i] = 0.f; o2[i][0]=0ULL; o2[i][1]=0ULL; }

    for (int j0 = 0; j0 <= q0; j0 += 128) {
        __syncthreads();
        for (int e = tid; e < 128*64; e += 256) {
            int kj = e >> 6, d = e & 63;
            size_t gi = (size_t)(b*S_ + j0 + kj)*KVDIM_ + kvh*HD_ + d;
            Ks[d*128 + kj] = g_k[gi];
            Vs[kj*64 + d]  = g_v[gi];
        }
        __syncthreads();

        ull sf2[8][4];
        #pragma unroll
        for (int i = 0; i < 8; i++)
            #pragma unroll
            for (int p = 0; p < 4; p++) sf2[i][p] = 0ULL;

        #pragma unroll 4
        for (int kk = 0; kk < 64; kk++) {
            float4 a0 = *(const float4*)&Qs[kk*128 + ty*8];
            float4 a1 = *(const float4*)&Qs[kk*128 + ty*8 + 4];
            ulonglong2 bl0 = *(const ulonglong2*)&Ks[kk*128 + tx*8];
            ulonglong2 bl1 = *(const ulonglong2*)&Ks[kk*128 + tx*8 + 4];
            ull bb[4] = {bl0.x, bl0.y, bl1.x, bl1.y};
            float av[8] = {a0.x,a0.y,a0.z,a0.w,a1.x,a1.y,a1.z,a1.w};
            #pragma unroll
            for (int i = 0; i < 8; i++) {
                ull ad = pk2(av[i], av[i]);
                #pragma unroll
                for (int p = 0; p < 4; p++) fma2(sf2[i][p], ad, bb[p]);
            }
        }

        float sf[8][8];
        #pragma unroll
        for (int i = 0; i < 8; i++)
            #pragma unroll
            for (int p = 0; p < 4; p++) up2(sf[i][2*p], sf[i][2*p+1], sf2[i][p]);

        if (j0 == q0) {
            #pragma unroll
            for (int i = 0; i < 8; i++)
                #pragma unroll
                for (int j = 0; j < 8; j++)
                    if (tx*8 + j > ty*8 + i) sf[i][j] = -INFINITY;
        }

        #pragma unroll
        for (int i = 0; i < 8; i++) {
            float rm = sf[i][0];
            #pragma unroll
            for (int j = 1; j < 8; j++) rm = fmaxf(rm, sf[i][j]);
            #pragma unroll
            for (int oo = 8; oo; oo >>= 1)
                rm = fmaxf(rm, __shfl_xor_sync(0xffffffffu, rm, oo));
            float mn = fmaxf(m[i], rm);
            float alpha = __expf(m[i] - mn);
            m[i] = mn;
            float rs = 0.f;
            #pragma unroll
            for (int j = 0; j < 8; j++) { sf[i][j] = __expf(sf[i][j] - mn); rs += sf[i][j]; }
            #pragma unroll
            for (int oo = 8; oo; oo >>= 1)
                rs += __shfl_xor_sync(0xffffffffu, rs, oo);
            l[i] = l[i]*alpha + rs;
            ull a2 = pk2(alpha, alpha);
            mul2(o2[i][0], a2);
            mul2(o2[i][1], a2);
            float4 w0 = {sf[i][0],sf[i][1],sf[i][2],sf[i][3]};
            float4 w1 = {sf[i][4],sf[i][5],sf[i][6],sf[i][7]};
            *(float4*)&Ps[(ty*8+i)*128 + tx*8]     = w0;
            *(float4*)&Ps[(ty*8+i)*128 + tx*8 + 4] = w1;
        }
        __syncthreads();

        #pragma unroll 2
        for (int kk4 = 0; kk4 < 128; kk4 += 4) {
            float4 a4[8];
            #pragma unroll
            for (int i = 0; i < 8; i++)
                a4[i] = *(const float4*)&Ps[(ty*8+i)*128 + kk4];
            #pragma unroll
            for (int kkk = 0; kkk < 4; kkk++) {
                ulonglong2 bv = *(const ulonglong2*)&Vs[(kk4+kkk)*64 + tx*4];
                #pragma unroll
                for (int i = 0; i < 8; i++) {
                    float aval = ((const float*)&a4[i])[kkk];
                    ull ad = pk2(aval, aval);
                    fma2(o2[i][0], ad, bv.x);
                    fma2(o2[i][1], ad, bv.y);
                }
            }
        }
    }

    #pragma unroll
    for (int i = 0; i < 8; i++) {
        float inv = 1.0f / l[i];
        float x0,x1,x2,x3;
        up2(x0, x1, o2[i][0]);
        up2(x2, x3, o2[i][1]);
        float4 r = {x0*inv, x1*inv, x2*inv, x3*inv};
        *(float4*)&g_y[(size_t)(b*S_ + q0 + ty*8 + i)*DIM_ + h*HD_ + tx*4] = r;
    }
}

// ---------------- launch ----------------
extern "C" void kernel_launch(void* const* d_in, const int* in_sizes, int n_in,
                              void* d_out, int out_size) {
    const float* x    = (const float*)d_in[0];
    const float* Wq   = (const float*)d_in[1];
    const float* Wk   = (const float*)d_in[2];
    const float* Wv   = (const float*)d_in[3];
    const float* Wp   = (const float*)d_in[4];
    const float* gain = (const float*)d_in[5];
    const float* Aq   = (const float*)d_in[6];
    const float* Bq   = (const float*)d_in[7];
    const float* Av   = (const float*)d_in[8];
    const float* Bv   = (const float*)d_in[9];
    const int*   step = (const int*)d_in[10];
    float* out = (float*)d_out;

    // resolve device-global pointers for prep_split (x path / y path)
    float* yp;           cudaGetSymbolAddress((void**)&yp,  g_y);
    __nv_bfloat16 *xh, *xl, *yh, *yl;
    cudaGetSymbolAddress((void**)&xh, g_xhi); cudaGetSymbolAddress((void**)&xl, g_xlo);
    cudaGetSymbolAddress((void**)&yh, g_yhi); cudaGetSymbolAddress((void**)&yl, g_ylo);

    prep_w_kernel<<<(WROWS_*256 + 255)/256, 256>>>(Wq, Wk, Wv, Wp, Aq, Bq, Av, Bv, step);
    prep_split_kernel<<<(M_*DIM_/4 + 255)/256, 256>>>(x, xh, xl, M_*DIM_/4);

    cudaFuncSetAttribute(gemm_mma_kernel<0>, cudaFuncAttributeMaxDynamicSharedMemorySize, G_SMEM);
    cudaFuncSetAttribute(gemm_mma_kernel<1>, cudaFuncAttributeMaxDynamicSharedMemorySize, G_SMEM);
    cudaFuncSetAttribute(gemm_mma_kernel<2>, cudaFuncAttributeMaxDynamicSharedMemorySize, G_SMEM);

    gemm_mma_kernel<0><<<dim3(1024/128, M_/128), 256, G_SMEM>>>(nullptr);
    gemm_mma_kernel<1><<<dim3( 512/128, M_/128), 256, G_SMEM>>>(nullptr);

    rms_rope_kernel<true ><<<(M_*H_)  / 8, 256>>>(gain);
    rms_rope_kernel<false><<<(M_*KVH_)/ 8, 256>>>(nullptr);

    cudaFuncSetAttribute(flash_attn_kernel,
                         cudaFuncAttributeMaxDynamicSharedMemorySize, FA_SMEM_BYTES);
    flash_attn_kernel<<<dim3(S_/128, H_, B_), 256, FA_SMEM_BYTES>>>();

    prep_split_kernel<<<(M_*DIM_/4 + 255)/256, 256>>>(yp, yh, yl, M_*DIM_/4);
    gemm_mma_kernel<2><<<dim3(1024/128, M_/128), 256, G_SMEM>>>(out);
}

// round 5
// speedup vs baseline: 3.5375x; 1.7853x over previous
#include <cuda_runtime.h>
#include <cuda_bf16.h>
#include <math.h>
#include <stdint.h>

#define B_      2
#define S_      2048
#define DIM_    1024
#define H_      16
#define KVH_    4
#define HD_     64
#define KVDIM_  256
#define R_      4
#define NSTEPS_ 2
#define M_      (B_*S_)
#define WROWS_  2560   // [0,1024): Wq+lora | [1024,1280): Wk | [1280,1536): Wv+lora | [1536,2560): Wp

// Q scale: 1/sqrt(64) * log2(e)  (softmax computed in base-2 domain)
#define QSCALE_ (0.125f * 1.4426950408889634f)

__device__ __forceinline__ uint32_t smem_u32(const void* p) {
    uint32_t a;
    asm("{ .reg .u64 t; cvta.to.shared.u64 t, %1; cvt.u32.u64 %0, t; }" : "=r"(a) : "l"(p));
    return a;
}

#define LDSM4(r, addr) \
    asm volatile("ldmatrix.sync.aligned.m8n8.x4.shared.b16 {%0,%1,%2,%3}, [%4];" \
        : "=r"((r)[0]),"=r"((r)[1]),"=r"((r)[2]),"=r"((r)[3]) : "r"(addr))
#define LDSM4T(r, addr) \
    asm volatile("ldmatrix.sync.aligned.m8n8.x4.trans.shared.b16 {%0,%1,%2,%3}, [%4];" \
        : "=r"((r)[0]),"=r"((r)[1]),"=r"((r)[2]),"=r"((r)[3]) : "r"(addr))

#define MMA_BF16(c, a, b0v, b1v) \
    asm volatile("mma.sync.aligned.m16n8k16.row.col.f32.bf16.bf16.f32 " \
        "{%0,%1,%2,%3}, {%4,%5,%6,%7}, {%8,%9}, {%0,%1,%2,%3};" \
        : "+f"((c)[0]),"+f"((c)[1]),"+f"((c)[2]),"+f"((c)[3]) \
        : "r"((a)[0]),"r"((a)[1]),"r"((a)[2]),"r"((a)[3]), "r"(b0v),"r"(b1v))

#define CP_ASYNC16(dst, src) \
    asm volatile("cp.async.cg.shared.global [%0], [%1], 16;" :: "r"(dst), "l"(src) : "memory")
#define CP_COMMIT() asm volatile("cp.async.commit_group;" ::: "memory")
#define CP_WAIT(n)  asm volatile("cp.async.wait_group %0;" :: "n"(n) : "memory")

// pack two fp32 -> bf16x2 (lo in low half)
__device__ __forceinline__ uint32_t pkbf(float lo, float hi) {
    uint32_t r; asm("cvt.rn.bf16x2.f32 %0, %1, %2;" : "=r"(r) : "f"(hi), "f"(lo)); return r;
}

// fast exp2 (poly on FMA pipe, clamped; rel err ~1.5e-5)
__device__ __forceinline__ float exp2_fast(float y) {
    y = fmaxf(y, -80.f);
    float fl = floorf(y);
    float t = y - fl;
    float p = 1.5403530e-4f;
    p = fmaf(p, t, 1.3333558e-3f);
    p = fmaf(p, t, 9.6181291e-3f);
    p = fmaf(p, t, 5.5504109e-2f);
    p = fmaf(p, t, 2.4022651e-1f);
    p = fmaf(p, t, 6.9314718e-1f);
    p = fmaf(p, t, 1.0f);
    return __int_as_float(((int)fl + 127) << 23) * p;
}

// ---------------- scratch ----------------
__device__ float g_q[M_*DIM_];     // raw Q gemm out (fp32), pre-norm
__device__ float g_k[M_*KVDIM_];   // raw K gemm out (fp32), pre-norm
__device__ __nv_bfloat16 g_xhi[M_*DIM_], g_xlo[M_*DIM_];
__device__ __nv_bfloat16 g_yhi[M_*DIM_], g_ylo[M_*DIM_];   // attention out (split)
__device__ __nv_bfloat16 g_whi[WROWS_*DIM_], g_wlo[WROWS_*DIM_];
__device__ unsigned short g_qhi[M_*DIM_],  g_qlo[M_*DIM_];   // normed+roped+scaled Q
__device__ unsigned short g_khi[M_*KVDIM_], g_klo[M_*KVDIM_];
__device__ unsigned short g_vhi[M_*KVDIM_], g_vlo[M_*KVDIM_];

__device__ __forceinline__ void f2bf2(float x, unsigned short& h, unsigned short& l) {
    __nv_bfloat16 hb = __float2bfloat16_rn(x);
    __nv_bfloat16 lb = __float2bfloat16_rn(x - __bfloat162float(hb));
    h = __bfloat16_as_ushort(hb);
    l = __bfloat16_as_ushort(lb);
}

// ---------------- prep: x -> hi/lo bf16 ----------------
__global__ void prep_split_kernel(const float* __restrict__ src,
                                  __nv_bfloat16* __restrict__ hi,
                                  __nv_bfloat16* __restrict__ lo, int n4) {
    int t = blockIdx.x * blockDim.x + threadIdx.x;
    if (t >= n4) return;
    float4 v = ((const float4*)src)[t];
    unsigned short h0,h1,h2,h3,l0,l1,l2,l3;
    f2bf2(v.x,h0,l0); f2bf2(v.y,h1,l1); f2bf2(v.z,h2,l2); f2bf2(v.w,h3,l3);
    uint2 hp, lp;
    hp.x = (uint32_t)h0 | ((uint32_t)h1 << 16); hp.y = (uint32_t)h2 | ((uint32_t)h3 << 16);
    lp.x = (uint32_t)l0 | ((uint32_t)l1 << 16); lp.y = (uint32_t)l2 | ((uint32_t)l3 << 16);
    ((uint2*)hi)[t] = hp;
    ((uint2*)lo)[t] = lp;
}

// ---------------- prep: fold LoRA, pack weights, split hi/lo ----------------
__global__ void prep_w_kernel(const float* __restrict__ Wq, const float* __restrict__ Wk,
                              const float* __restrict__ Wv, const float* __restrict__ Wp,
                              const float* __restrict__ Aq, const float* __restrict__ Bq,
                              const float* __restrict__ Av, const float* __restrict__ Bv,
                              const int*   __restrict__ stepp) {
    int t = blockIdx.x * blockDim.x + threadIdx.x;
    if (t >= WROWS_ * 256) return;
    int row = t >> 8, k4 = t & 255;
    int step = *stepp;
    bool ok = (step >= 0 && step < NSTEPS_);
    float4 w;
    if (row < 1024) {
        w = ((const float4*)(Wq + (size_t)row * DIM_))[k4];
        if (ok) {
            const float* Ab = Aq + (size_t)step * R_ * DIM_;
            const float* Bb = Bq + ((size_t)step * DIM_ + row) * R_;
            #pragma unroll
            for (int r = 0; r < R_; r++) {
                float b = Bb[r];
                float4 a = ((const float4*)(Ab + (size_t)r * DIM_))[k4];
                w.x += b*a.x; w.y += b*a.y; w.z += b*a.z; w.w += b*a.w;
            }
        }
    } else if (row < 1280) {
        w = ((const float4*)(Wk + (size_t)(row - 1024) * DIM_))[k4];
    } else if (row < 1536) {
        int vr = row - 1280;
        w = ((const float4*)(Wv + (size_t)vr * DIM_))[k4];
        if (ok) {
            const float* Ab = Av + (size_t)step * R_ * DIM_;
            const float* Bb = Bv + ((size_t)step * KVDIM_ + vr) * R_;
            #pragma unroll
            for (int r = 0; r < R_; r++) {
                float b = Bb[r];
                float4 a = ((const float4*)(Ab + (size_t)r * DIM_))[k4];
                w.x += b*a.x; w.y += b*a.y; w.z += b*a.z; w.w += b*a.w;
            }
        }
    } else {
        w = ((const float4*)(Wp + (size_t)(row - 1536) * DIM_))[k4];
    }
    unsigned short h0,h1,h2,h3,l0,l1,l2,l3;
    f2bf2(w.x,h0,l0); f2bf2(w.y,h1,l1); f2bf2(w.z,h2,l2); f2bf2(w.w,h3,l3);
    uint2 hp, lp;
    hp.x = (uint32_t)h0 | ((uint32_t)h1 << 16); hp.y = (uint32_t)h2 | ((uint32_t)h3 << 16);
    lp.x = (uint32_t)l0 | ((uint32_t)l1 << 16); lp.y = (uint32_t)l2 | ((uint32_t)l3 << 16);
    ((uint2*)g_whi)[t] = hp;
    ((uint2*)g_wlo)[t] = lp;
}

// ---------------- mma.sync split GEMM (as R3) ----------------
#define GT_      10240
#define GSTAGE_  (4*GT_)
#define G_SMEM   (2*GSTAGE_)

// MODE 0: Q | MODE 1: KV (k fp32, v split bf16) | MODE 2: proj
template<int MODE>
__global__ void __launch_bounds__(256, 2)
gemm_mma_kernel(float* __restrict__ outp) {
    extern __shared__ char smem[];
    uint32_t sb = smem_u32(smem);
    constexpr int WOFF = (MODE == 0) ? 0 : (MODE == 1) ? 1024 : 1536;
    const __nv_bfloat16* Xhi = (MODE == 2) ? g_yhi : g_xhi;
    const __nv_bfloat16* Xlo = (MODE == 2) ? g_ylo : g_xlo;

    int m0 = blockIdx.y * 128, n0 = blockIdx.x * 128;
    int tid = threadIdx.x;
    int wid = tid >> 5, lane = tid & 31;
    int m_base = (wid >> 1) * 32, n_base = (wid & 1) * 64;
    int lrow = (lane & 7) + ((lane >> 3) & 1) * 8;
    int lcol = (lane >> 4) * 8;

    auto load_stage = [&](int it, int s) {
        int k0 = it * 32;
        int row_half = tid >> 2;
        int q = tid & 3;
        #pragma unroll
        for (int t = 0; t < 8; t++) {
            int tile = t >> 1;
            int row = (t & 1) * 64 + row_half;
            const __nv_bfloat16* src;
            if (tile == 0)      src = Xhi  + (size_t)(m0 + row) * DIM_ + k0 + q * 8;
            else if (tile == 1) src = Xlo  + (size_t)(m0 + row) * DIM_ + k0 + q * 8;
            else if (tile == 2) src = g_whi + (size_t)(WOFF + n0 + row) * DIM_ + k0 + q * 8;
            else                src = g_wlo + (size_t)(WOFF + n0 + row) * DIM_ + k0 + q * 8;
            uint32_t dst = sb + s * GSTAGE_ + tile * GT_ + row * 80 + q * 16;
            CP_ASYNC16(dst, src);
        }
        CP_COMMIT();
    };

    float c[2][8][4];
    #pragma unroll
    for (int i = 0; i < 2; i++)
        #pragma unroll
        for (int j = 0; j < 8; j++)
            #pragma unroll
            for (int p = 0; p < 4; p++) c[i][j][p] = 0.f;

    load_stage(0, 0);

    for (int it = 0; it < 32; it++) {
        if (it < 31) { load_stage(it + 1, (it + 1) & 1); CP_WAIT(1); }
        else         { CP_WAIT(0); }
        __syncthreads();

        uint32_t base = sb + (it & 1) * GSTAGE_;
        uint32_t sXhi = base, sWhi = base + 2 * GT_;

        #pragma unroll
        for (int ks = 0; ks < 2; ks++) {
            int kb = ks * 16;
            uint32_t ahi[2][4], alo[2][4];
            #pragma unroll
            for (int mc = 0; mc < 2; mc++) {
                uint32_t aaddr = sXhi + (m_base + mc * 16 + lrow) * 80 + (kb + lcol) * 2;
                LDSM4(ahi[mc], aaddr);
                LDSM4(alo[mc], aaddr + GT_);
            }
            #pragma unroll
            for (int nc = 0; nc < 4; nc++) {
                uint32_t baddr = sWhi + (n_base + nc * 16 + lrow) * 80 + (kb + lcol) * 2;
                uint32_t bhi[4], blo[4];
                LDSM4(bhi, baddr);
                LDSM4(blo, baddr + GT_);
                #pragma unroll
                for (int mc = 0; mc < 2; mc++) {
                    MMA_BF16(c[mc][nc*2],   ahi[mc], bhi[0], bhi[2]);
                    MMA_BF16(c[mc][nc*2],   ahi[mc], blo[0], blo[2]);
                    MMA_BF16(c[mc][nc*2],   alo[mc], bhi[0], bhi[2]);
                    MMA_BF16(c[mc][nc*2+1], ahi[mc], bhi[1], bhi[3]);
                    MMA_BF16(c[mc][nc*2+1], ahi[mc], blo[1], blo[3]);
                    MMA_BF16(c[mc][nc*2+1], alo[mc], bhi[1], bhi[3]);
                }
            }
        }
        __syncthreads();
    }

    #pragma unroll
    for (int mc = 0; mc < 2; mc++) {
        #pragma unroll
        for (int nf = 0; nf < 8; nf++) {
            int gr = m0 + m_base + mc * 16 + (lane >> 2);
            int gc = n0 + n_base + nf * 8 + (lane & 3) * 2;
            float2 v0 = make_float2(c[mc][nf][0], c[mc][nf][1]);
            float2 v1 = make_float2(c[mc][nf][2], c[mc][nf][3]);
            if (MODE == 0) {
                *(float2*)&g_q[(size_t)gr * 1024 + gc] = v0;
                *(float2*)&g_q[(size_t)(gr + 8) * 1024 + gc] = v1;
            } else if (MODE == 2) {
                *(float2*)&outp[(size_t)gr * 1024 + gc] = v0;
                *(float2*)&outp[(size_t)(gr + 8) * 1024 + gc] = v1;
            } else {
                if (gc < 256) {
                    *(float2*)&g_k[(size_t)gr * 256 + gc] = v0;
                    *(float2*)&g_k[(size_t)(gr + 8) * 256 + gc] = v1;
                } else {
                    int vc = gc - 256;
                    unsigned short h0,h1,l0,l1;
                    f2bf2(v0.x,h0,l0); f2bf2(v0.y,h1,l1);
                    *(uint32_t*)&g_vhi[(size_t)gr*256 + vc] = (uint32_t)h0 | ((uint32_t)h1<<16);
                    *(uint32_t*)&g_vlo[(size_t)gr*256 + vc] = (uint32_t)l0 | ((uint32_t)l1<<16);
                    f2bf2(v1.x,h0,l0); f2bf2(v1.y,h1,l1);
                    *(uint32_t*)&g_vhi[(size_t)(gr+8)*256 + vc] = (uint32_t)h0 | ((uint32_t)h1<<16);
                    *(uint32_t*)&g_vlo[(size_t)(gr+8)*256 + vc] = (uint32_t)l0 | ((uint32_t)l1<<16);
                }
            }
        }
    }
}

// ---------------- RMSNorm + partial RoPE + gain -> split bf16 ----------------
template<bool QSIDE>
__global__ void rms_rope_kernel(const float* __restrict__ gain) {
    const int NH = QSIDE ? H_ : KVH_;
    const float* buf = QSIDE ? g_q : g_k;
    int gw = blockIdx.x * (blockDim.x >> 5) + (threadIdx.x >> 5);
    int lane = threadIdx.x & 31;
    if (gw >= M_ * NH) return;
    int h = gw % NH, ms = gw / NH, s = ms % S_;
    const float* p = buf + (size_t)ms * (NH*HD_) + h * HD_;
    float v0 = p[lane], v1 = p[lane + 32];
    float ss = v0*v0 + v1*v1;
    #pragma unroll
    for (int o = 16; o; o >>= 1) ss += __shfl_xor_sync(0xffffffffu, ss, o);
    float r = rsqrtf(ss * (1.0f/64.0f) + 1.1920929e-7f);
    v0 *= r; v1 *= r;
    int i = lane & 15;
    float invf = 1.0f / powf(10000.0f, (float)(2*i) / 32.0f);
    float ang = (float)s * invf;
    float cc = cosf(ang), sn = sinf(ang);
    float other = __shfl_xor_sync(0xffffffffu, v0, 16);
    float nv0 = (lane < 16) ? (v0*cc + other*sn) : (-other*sn + v0*cc);
    float g = QSIDE ? (gain[h] * QSCALE_) : 1.0f;
    nv0 *= g; v1 *= g;
    unsigned short h0,l0,h1,l1;
    f2bf2(nv0,h0,l0); f2bf2(v1,h1,l1);
    size_t base = (size_t)ms * (NH*HD_) + h * HD_;
    if (QSIDE) {
        g_qhi[base + lane] = h0;   g_qlo[base + lane] = l0;
        g_qhi[base + lane + 32] = h1; g_qlo[base + lane + 32] = l1;
    } else {
        g_khi[base + lane] = h0;   g_klo[base + lane] = l0;
        g_khi[base + lane + 32] = h1; g_klo[base + lane + 32] = l1;
    }
}

// ---------------- tensor-core causal flash attention ----------------
// 128q x 128k tiles, 8 warps x 16q each, k in 64-wide halves.
// smem: KH, KL, VH, VL each [128][72] bf16 (144B rows).
#define FA_KH   0
#define FA_KL   18432
#define FA_VH   36864
#define FA_VL   55296
#define FA_SMEM 73728

__global__ void __launch_bounds__(256, 2)
flash_mma_kernel() {
    extern __shared__ char smem[];
    uint32_t sb = smem_u32(smem);

    int b = blockIdx.z, h = blockIdx.y;
    int q0 = (gridDim.x - 1 - blockIdx.x) * 128;
    int kvh = h >> 2;
    int tid = threadIdx.x;
    int wid = tid >> 5, lane = tid & 31;
    int r = lane >> 2, c2 = (lane & 3) * 2;
    int lrow = (lane & 7) + ((lane >> 3) & 1) * 8;
    int lcol = (lane >> 4) * 8;

    int qg0 = q0 + wid * 16 + r;      // global q row (this thread, low)
    int qg1 = qg0 + 8;
    size_t tok0 = (size_t)(b * S_) + qg0;
    size_t tok1 = tok0 + 8;
    int qmaxw = q0 + wid * 16 + 15;

    // Q fragments (registers, hi/lo)
    uint32_t qh[4][4], ql[4][4];
    #pragma unroll
    for (int t = 0; t < 4; t++) {
        size_t c0 = (size_t)h * 64 + t * 16 + c2;
        qh[t][0] = *(const uint32_t*)&g_qhi[tok0 * 1024 + c0];
        qh[t][1] = *(const uint32_t*)&g_qhi[tok1 * 1024 + c0];
        qh[t][2] = *(const uint32_t*)&g_qhi[tok0 * 1024 + c0 + 8];
        qh[t][3] = *(const uint32_t*)&g_qhi[tok1 * 1024 + c0 + 8];
        ql[t][0] = *(const uint32_t*)&g_qlo[tok0 * 1024 + c0];
        ql[t][1] = *(const uint32_t*)&g_qlo[tok1 * 1024 + c0];
        ql[t][2] = *(const uint32_t*)&g_qlo[tok0 * 1024 + c0 + 8];
        ql[t][3] = *(const uint32_t*)&g_qlo[tok1 * 1024 + c0 + 8];
    }

    float oc[8][4];
    #pragma unroll
    for (int j = 0; j < 8; j++)
        #pragma unroll
        for (int p = 0; p < 4; p++) oc[j][p] = 0.f;
    float mrow[2] = {-INFINITY, -INFINITY};
    float lrw[2]  = {0.f, 0.f};

    int q8 = tid & 7, rr = tid >> 3;   // loader indices

    for (int j0 = 0; j0 <= q0; j0 += 128) {
        __syncthreads();
        // load K/V hi/lo tiles (cp.async)
        const unsigned short* srcs[4] = {g_khi, g_klo, g_vhi, g_vlo};
        #pragma unroll
        for (int arr = 0; arr < 4; arr++) {
            #pragma unroll
            for (int p = 0; p < 4; p++) {
                int row = p * 32 + rr;
                const unsigned short* src = srcs[arr] +
                    (size_t)(b * S_ + j0 + row) * 256 + kvh * 64 + q8 * 8;
                CP_ASYNC16(sb + arr * 18432 + row * 144 + q8 * 16, src);
            }
        }
        CP_COMMIT(); CP_WAIT(0);
        __syncthreads();

        #pragma unroll
        for (int half = 0; half < 2; half++) {
            int kg0 = j0 + half * 64;
            if (kg0 > qmaxw) continue;   // fully masked for this warp
            int ks = half * 64;          // smem key offset

            // scores = Q @ K^T (3-term split)
            float sc[8][4];
            #pragma unroll
            for (int j = 0; j < 8; j++)
                #pragma unroll
                for (int p = 0; p < 4; p++) sc[j][p] = 0.f;

            #pragma unroll
            for (int nc = 0; nc < 4; nc++) {
                uint32_t ka = sb + FA_KH + (ks + nc * 16 + lrow) * 144 + lcol * 2;
                #pragma unroll
                for (int t = 0; t < 4; t++) {
                    uint32_t bh[4], bl[4];
                    LDSM4(bh, ka + t * 32);
                    LDSM4(bl, ka + t * 32 + (FA_KL - FA_KH));
                    MMA_BF16(sc[nc*2],   qh[t], bh[0], bh[2]);
                    MMA_BF16(sc[nc*2],   ql[t], bh[0], bh[2]);
                    MMA_BF16(sc[nc*2],   qh[t], bl[0], bl[2]);
                    MMA_BF16(sc[nc*2+1], qh[t], bh[1], bh[3]);
                    MMA_BF16(sc[nc*2+1], ql[t], bh[1], bh[3]);
                    MMA_BF16(sc[nc*2+1], qh[t], bl[1], bl[3]);
                }
            }

            // causal mask
            if (kg0 + 63 > q0 + wid * 16) {
                #pragma unroll
                for (int j = 0; j < 8; j++) {
                    int key = kg0 + 8 * j + c2;
                    if (key     > qg0) sc[j][0] = -1e30f;
                    if (key + 1 > qg0) sc[j][1] = -1e30f;
                    if (key     > qg1) sc[j][2] = -1e30f;
                    if (key + 1 > qg1) sc[j][3] = -1e30f;
                }
            }

            // online softmax (base-2 domain; scale folded into Q)
            #pragma unroll
            for (int rh = 0; rh < 2; rh++) {
                float rm = sc[0][rh*2];
                #pragma unroll
                for (int j = 0; j < 8; j++) {
                    rm = fmaxf(rm, sc[j][rh*2]);
                    rm = fmaxf(rm, sc[j][rh*2+1]);
                }
                rm = fmaxf(rm, __shfl_xor_sync(0xffffffffu, rm, 1));
                rm = fmaxf(rm, __shfl_xor_sync(0xffffffffu, rm, 2));
                float mn = fmaxf(mrow[rh], rm);
                float alpha = exp2_fast(mrow[rh] - mn);
                mrow[rh] = mn;
                float rs = 0.f;
                #pragma unroll
                for (int j = 0; j < 8; j++) {
                    sc[j][rh*2]   = exp2_fast(sc[j][rh*2]   - mn);
                    sc[j][rh*2+1] = exp2_fast(sc[j][rh*2+1] - mn);
                    rs += sc[j][rh*2] + sc[j][rh*2+1];
                }
                rs += __shfl_xor_sync(0xffffffffu, rs, 1);
                rs += __shfl_xor_sync(0xffffffffu, rs, 2);
                lrw[rh] = lrw[rh] * alpha + rs;
                #pragma unroll
                for (int j = 0; j < 8; j++) {
                    oc[j][rh*2]   *= alpha;
                    oc[j][rh*2+1] *= alpha;
                }
            }

            // O += P @ V  (P split hi/lo, V split hi/lo: 3 terms)
            #pragma unroll
            for (int u = 0; u < 4; u++) {
                uint32_t ah[4], al[4];
                #pragma unroll
                for (int fr = 0; fr < 4; fr++) {
                    int cj = 2*u + (fr >> 1);
                    int po = (fr & 1) * 2;
                    float p0 = sc[cj][po], p1 = sc[cj][po+1];
                    uint32_t hp = pkbf(p0, p1);
                    float h0 = __uint_as_float(hp << 16);
                    float h1 = __uint_as_float(hp & 0xffff0000u);
                    ah[fr] = hp;
                    al[fr] = pkbf(p0 - h0, p1 - h1);
                }
                // reorder to A-frag convention: a0=(r,k0..1) a1=(r+8,k0..1) a2=(r,k8..9) a3=(r+8,...)
                uint32_t A_hi[4] = {ah[0], ah[1], ah[2], ah[3]};
                uint32_t A_lo[4] = {al[0], al[1], al[2], al[3]};
                #pragma unroll
                for (int dv = 0; dv < 4; dv++) {
                    uint32_t va = sb + FA_VH + (ks + u * 16 + (lane & 15)) * 144
                                 + (dv * 16 + (lane >> 4) * 8) * 2;
                    uint32_t vh[4], vl[4];
                    LDSM4T(vh, va);
                    LDSM4T(vl, va + (FA_VL - FA_VH));
                    MMA_BF16(oc[dv*2],   A_hi, vh[0], vh[1]);
                    MMA_BF16(oc[dv*2],   A_lo, vh[0], vh[1]);
                    MMA_BF16(oc[dv*2],   A_hi, vl[0], vl[1]);
                    MMA_BF16(oc[dv*2+1], A_hi, vh[2], vh[3]);
                    MMA_BF16(oc[dv*2+1], A_lo, vh[2], vh[3]);
                    MMA_BF16(oc[dv*2+1], A_hi, vl[2], vl[3]);
                }
            }
        }
    }

    // epilogue: y = O / l -> split bf16 into g_yhi/g_ylo
    float inv0 = 1.0f / lrw[0], inv1 = 1.0f / lrw[1];
    #pragma unroll
    for (int j = 0; j < 8; j++) {
        size_t col = (size_t)h * 64 + 8 * j + c2;
        float y0 = oc[j][0] * inv0, y1 = oc[j][1] * inv0;
        float y2 = oc[j][2] * inv1, y3 = oc[j][3] * inv1;
        uint32_t hp0 = pkbf(y0, y1);
        uint32_t lp0 = pkbf(y0 - __uint_as_float(hp0 << 16),
                            y1 - __uint_as_float(hp0 & 0xffff0000u));
        uint32_t hp1 = pkbf(y2, y3);
        uint32_t lp1 = pkbf(y2 - __uint_as_float(hp1 << 16),
                            y3 - __uint_as_float(hp1 & 0xffff0000u));
        *(uint32_t*)&g_yhi[tok0 * 1024 + col] = hp0;
        *(uint32_t*)&g_ylo[tok0 * 1024 + col] = lp0;
        *(uint32_t*)&g_yhi[tok1 * 1024 + col] = hp1;
        *(uint32_t*)&g_ylo[tok1 * 1024 + col] = lp1;
    }
}

// ---------------- launch ----------------
extern "C" void kernel_launch(void* const* d_in, const int* in_sizes, int n_in,
                              void* d_out, int out_size) {
    const float* x    = (const float*)d_in[0];
    const float* Wq   = (const float*)d_in[1];
    const float* Wk   = (const float*)d_in[2];
    const float* Wv   = (const float*)d_in[3];
    const float* Wp   = (const float*)d_in[4];
    const float* gain = (const float*)d_in[5];
    const float* Aq   = (const float*)d_in[6];
    const float* Bq   = (const float*)d_in[7];
    const float* Av   = (const float*)d_in[8];
    const float* Bv   = (const float*)d_in[9];
    const int*   step = (const int*)d_in[10];
    float* out = (float*)d_out;

    __nv_bfloat16 *xh, *xl;
    cudaGetSymbolAddress((void**)&xh, g_xhi);
    cudaGetSymbolAddress((void**)&xl, g_xlo);

    prep_w_kernel<<<(WROWS_*256 + 255)/256, 256>>>(Wq, Wk, Wv, Wp, Aq, Bq, Av, Bv, step);
    prep_split_kernel<<<(M_*DIM_/4 + 255)/256, 256>>>(x, xh, xl, M_*DIM_/4);

    cudaFuncSetAttribute(gemm_mma_kernel<0>, cudaFuncAttributeMaxDynamicSharedMemorySize, G_SMEM);
    cudaFuncSetAttribute(gemm_mma_kernel<1>, cudaFuncAttributeMaxDynamicSharedMemorySize, G_SMEM);
    cudaFuncSetAttribute(gemm_mma_kernel<2>, cudaFuncAttributeMaxDynamicSharedMemorySize, G_SMEM);
    cudaFuncSetAttribute(flash_mma_kernel,   cudaFuncAttributeMaxDynamicSharedMemorySize, FA_SMEM);

    gemm_mma_kernel<0><<<dim3(1024/128, M_/128), 256, G_SMEM>>>(nullptr);
    gemm_mma_kernel<1><<<dim3( 512/128, M_/128), 256, G_SMEM>>>(nullptr);

    rms_rope_kernel<true ><<<(M_*H_)  / 8, 256>>>(gain);
    rms_rope_kernel<false><<<(M_*KVH_)/ 8, 256>>>(nullptr);

    flash_mma_kernel<<<dim3(S_/128, H_, B_), 256, FA_SMEM>>>();

    gemm_mma_kernel<2><<<dim3(1024/128, M_/128), 256, G_SMEM>>>(out);
}

// round 6
// speedup vs baseline: 3.6410x; 1.0293x over previous
#include <cuda_runtime.h>
#include <cuda_bf16.h>
#include <math.h>
#include <stdint.h>

#define B_      2
#define S_      2048
#define DIM_    1024
#define H_      16
#define KVH_    4
#define HD_     64
#define KVDIM_  256
#define R_      4
#define NSTEPS_ 2
#define M_      (B_*S_)
#define WROWS_  2560   // [0,1024): Wq+lora | [1024,1280): Wk | [1280,1536): Wv+lora | [1536,2560): Wp

#define QSCALE_ (0.125f * 1.4426950408889634f)

__device__ __forceinline__ uint32_t smem_u32(const void* p) {
    uint32_t a;
    asm("{ .reg .u64 t; cvta.to.shared.u64 t, %1; cvt.u32.u64 %0, t; }" : "=r"(a) : "l"(p));
    return a;
}

#define LDSM4(r, addr) \
    asm volatile("ldmatrix.sync.aligned.m8n8.x4.shared.b16 {%0,%1,%2,%3}, [%4];" \
        : "=r"((r)[0]),"=r"((r)[1]),"=r"((r)[2]),"=r"((r)[3]) : "r"(addr))
#define LDSM4T(r, addr) \
    asm volatile("ldmatrix.sync.aligned.m8n8.x4.trans.shared.b16 {%0,%1,%2,%3}, [%4];" \
        : "=r"((r)[0]),"=r"((r)[1]),"=r"((r)[2]),"=r"((r)[3]) : "r"(addr))

#define MMA_BF16(c, a, b0v, b1v) \
    asm volatile("mma.sync.aligned.m16n8k16.row.col.f32.bf16.bf16.f32 " \
        "{%0,%1,%2,%3}, {%4,%5,%6,%7}, {%8,%9}, {%0,%1,%2,%3};" \
        : "+f"((c)[0]),"+f"((c)[1]),"+f"((c)[2]),"+f"((c)[3]) \
        : "r"((a)[0]),"r"((a)[1]),"r"((a)[2]),"r"((a)[3]), "r"(b0v),"r"(b1v))

#define CP_ASYNC16(dst, src) \
    asm volatile("cp.async.cg.shared.global [%0], [%1], 16;" :: "r"(dst), "l"(src) : "memory")
#define CP_COMMIT() asm volatile("cp.async.commit_group;" ::: "memory")
#define CP_WAIT(n)  asm volatile("cp.async.wait_group %0;" :: "n"(n) : "memory")

__device__ __forceinline__ uint32_t pkbf(float lo, float hi) {
    uint32_t r; asm("cvt.rn.bf16x2.f32 %0, %1, %2;" : "=r"(r) : "f"(hi), "f"(lo)); return r;
}

__device__ __forceinline__ float exp2_fast(float y) {
    y = fmaxf(y, -80.f);
    float fl = floorf(y);
    float t = y - fl;
    float p = 1.5403530e-4f;
    p = fmaf(p, t, 1.3333558e-3f);
    p = fmaf(p, t, 9.6181291e-3f);
    p = fmaf(p, t, 5.5504109e-2f);
    p = fmaf(p, t, 2.4022651e-1f);
    p = fmaf(p, t, 6.9314718e-1f);
    p = fmaf(p, t, 1.0f);
    return __int_as_float(((int)fl + 127) << 23) * p;
}

// ---------------- scratch ----------------
__device__ float g_q[M_*DIM_];
__device__ float g_k[M_*KVDIM_];
__device__ __nv_bfloat16 g_xhi[M_*DIM_], g_xlo[M_*DIM_];
__device__ __nv_bfloat16 g_yhi[M_*DIM_], g_ylo[M_*DIM_];
__device__ __nv_bfloat16 g_whi[WROWS_*DIM_], g_wlo[WROWS_*DIM_];
__device__ unsigned short g_qhi[M_*DIM_],  g_qlo[M_*DIM_];
__device__ unsigned short g_khi[M_*KVDIM_], g_klo[M_*KVDIM_];
__device__ unsigned short g_vhi[M_*KVDIM_], g_vlo[M_*KVDIM_];

__device__ __forceinline__ void f2bf2(float x, unsigned short& h, unsigned short& l) {
    __nv_bfloat16 hb = __float2bfloat16_rn(x);
    __nv_bfloat16 lb = __float2bfloat16_rn(x - __bfloat162float(hb));
    h = __bfloat16_as_ushort(hb);
    l = __bfloat16_as_ushort(lb);
}

// ---------------- prep: x -> hi/lo bf16 ----------------
__global__ void prep_split_kernel(const float* __restrict__ src,
                                  __nv_bfloat16* __restrict__ hi,
                                  __nv_bfloat16* __restrict__ lo, int n4) {
    int t = blockIdx.x * blockDim.x + threadIdx.x;
    if (t >= n4) return;
    float4 v = ((const float4*)src)[t];
    unsigned short h0,h1,h2,h3,l0,l1,l2,l3;
    f2bf2(v.x,h0,l0); f2bf2(v.y,h1,l1); f2bf2(v.z,h2,l2); f2bf2(v.w,h3,l3);
    uint2 hp, lp;
    hp.x = (uint32_t)h0 | ((uint32_t)h1 << 16); hp.y = (uint32_t)h2 | ((uint32_t)h3 << 16);
    lp.x = (uint32_t)l0 | ((uint32_t)l1 << 16); lp.y = (uint32_t)l2 | ((uint32_t)l3 << 16);
    ((uint2*)hi)[t] = hp;
    ((uint2*)lo)[t] = lp;
}

// ---------------- prep: fold LoRA, pack weights, split hi/lo ----------------
__global__ void prep_w_kernel(const float* __restrict__ Wq, const float* __restrict__ Wk,
                              const float* __restrict__ Wv, const float* __restrict__ Wp,
                              const float* __restrict__ Aq, const float* __restrict__ Bq,
                              const float* __restrict__ Av, const float* __restrict__ Bv,
                              const int*   __restrict__ stepp) {
    int t = blockIdx.x * blockDim.x + threadIdx.x;
    if (t >= WROWS_ * 256) return;
    int row = t >> 8, k4 = t & 255;
    int step = *stepp;
    bool ok = (step >= 0 && step < NSTEPS_);
    float4 w;
    if (row < 1024) {
        w = ((const float4*)(Wq + (size_t)row * DIM_))[k4];
        if (ok) {
            const float* Ab = Aq + (size_t)step * R_ * DIM_;
            const float* Bb = Bq + ((size_t)step * DIM_ + row) * R_;
            #pragma unroll
            for (int r = 0; r < R_; r++) {
                float b = Bb[r];
                float4 a = ((const float4*)(Ab + (size_t)r * DIM_))[k4];
                w.x += b*a.x; w.y += b*a.y; w.z += b*a.z; w.w += b*a.w;
            }
        }
    } else if (row < 1280) {
        w = ((const float4*)(Wk + (size_t)(row - 1024) * DIM_))[k4];
    } else if (row < 1536) {
        int vr = row - 1280;
        w = ((const float4*)(Wv + (size_t)vr * DIM_))[k4];
        if (ok) {
            const float* Ab = Av + (size_t)step * R_ * DIM_;
            const float* Bb = Bv + ((size_t)step * KVDIM_ + vr) * R_;
            #pragma unroll
            for (int r = 0; r < R_; r++) {
                float b = Bb[r];
                float4 a = ((const float4*)(Ab + (size_t)r * DIM_))[k4];
                w.x += b*a.x; w.y += b*a.y; w.z += b*a.z; w.w += b*a.w;
            }
        }
    } else {
        w = ((const float4*)(Wp + (size_t)(row - 1536) * DIM_))[k4];
    }
    unsigned short h0,h1,h2,h3,l0,l1,l2,l3;
    f2bf2(w.x,h0,l0); f2bf2(w.y,h1,l1); f2bf2(w.z,h2,l2); f2bf2(w.w,h3,l3);
    uint2 hp, lp;
    hp.x = (uint32_t)h0 | ((uint32_t)h1 << 16); hp.y = (uint32_t)h2 | ((uint32_t)h3 << 16);
    lp.x = (uint32_t)l0 | ((uint32_t)l1 << 16); lp.y = (uint32_t)l2 | ((uint32_t)l3 << 16);
    ((uint2*)g_whi)[t] = hp;
    ((uint2*)g_wlo)[t] = lp;
}

// ---------------- mma.sync split GEMM, term-outer MMA ordering ----------------
#define GT_      10240
#define GSTAGE_  (4*GT_)
#define G_SMEM   (2*GSTAGE_)

// MODE 0: merged QKV (N=1536, Woff=0) | MODE 2: proj (N=1024, Woff=1536)
template<int MODE>
__global__ void __launch_bounds__(256, 2)
gemm_mma_kernel(float* __restrict__ outp) {
    extern __shared__ char smem[];
    uint32_t sb = smem_u32(smem);
    constexpr int WOFF = (MODE == 0) ? 0 : 1536;
    const __nv_bfloat16* Xhi = (MODE == 2) ? g_yhi : g_xhi;
    const __nv_bfloat16* Xlo = (MODE == 2) ? g_ylo : g_xlo;

    int m0 = blockIdx.y * 128, n0 = blockIdx.x * 128;
    int tid = threadIdx.x;
    int wid = tid >> 5, lane = tid & 31;
    int m_base = (wid >> 1) * 32, n_base = (wid & 1) * 64;
    int lrow = (lane & 7) + ((lane >> 3) & 1) * 8;
    int lcol = (lane >> 4) * 8;

    auto load_stage = [&](int it, int s) {
        int k0 = it * 32;
        int row_half = tid >> 2;
        int q = tid & 3;
        #pragma unroll
        for (int t = 0; t < 8; t++) {
            int tile = t >> 1;
            int row = (t & 1) * 64 + row_half;
            const __nv_bfloat16* src;
            if (tile == 0)      src = Xhi  + (size_t)(m0 + row) * DIM_ + k0 + q * 8;
            else if (tile == 1) src = Xlo  + (size_t)(m0 + row) * DIM_ + k0 + q * 8;
            else if (tile == 2) src = g_whi + (size_t)(WOFF + n0 + row) * DIM_ + k0 + q * 8;
            else                src = g_wlo + (size_t)(WOFF + n0 + row) * DIM_ + k0 + q * 8;
            uint32_t dst = sb + s * GSTAGE_ + tile * GT_ + row * 80 + q * 16;
            CP_ASYNC16(dst, src);
        }
        CP_COMMIT();
    };

    float c[2][8][4];
    #pragma unroll
    for (int i = 0; i < 2; i++)
        #pragma unroll
        for (int j = 0; j < 8; j++)
            #pragma unroll
            for (int p = 0; p < 4; p++) c[i][j][p] = 0.f;

    load_stage(0, 0);

    for (int it = 0; it < 32; it++) {
        if (it < 31) { load_stage(it + 1, (it + 1) & 1); CP_WAIT(1); }
        else         { CP_WAIT(0); }
        __syncthreads();

        uint32_t base = sb + (it & 1) * GSTAGE_;
        uint32_t sXhi = base, sWhi = base + 2 * GT_;

        #pragma unroll
        for (int ks = 0; ks < 2; ks++) {
            int kb = ks * 16;
            uint32_t ahi[2][4], alo[2][4];
            #pragma unroll
            for (int mc = 0; mc < 2; mc++) {
                uint32_t aaddr = sXhi + (m_base + mc * 16 + lrow) * 80 + (kb + lcol) * 2;
                LDSM4(ahi[mc], aaddr);
                LDSM4(alo[mc], aaddr + GT_);
            }
            #pragma unroll
            for (int ncp = 0; ncp < 4; ncp += 2) {
                uint32_t bh[2][4], bl[2][4];
                #pragma unroll
                for (int p = 0; p < 2; p++) {
                    uint32_t baddr = sWhi + (n_base + (ncp+p) * 16 + lrow) * 80 + (kb + lcol) * 2;
                    LDSM4(bh[p], baddr);
                    LDSM4(bl[p], baddr + GT_);
                }
                // term hi*hi (8 distinct accumulators)
                #pragma unroll
                for (int p = 0; p < 2; p++)
                    #pragma unroll
                    for (int mc = 0; mc < 2; mc++) {
                        MMA_BF16(c[mc][(ncp+p)*2],   ahi[mc], bh[p][0], bh[p][2]);
                        MMA_BF16(c[mc][(ncp+p)*2+1], ahi[mc], bh[p][1], bh[p][3]);
                    }
                // term hi*lo
                #pragma unroll
                for (int p = 0; p < 2; p++)
                    #pragma unroll
                    for (int mc = 0; mc < 2; mc++) {
                        MMA_BF16(c[mc][(ncp+p)*2],   ahi[mc], bl[p][0], bl[p][2]);
                        MMA_BF16(c[mc][(ncp+p)*2+1], ahi[mc], bl[p][1], bl[p][3]);
                    }
                // term lo*hi
                #pragma unroll
                for (int p = 0; p < 2; p++)
                    #pragma unroll
                    for (int mc = 0; mc < 2; mc++) {
                        MMA_BF16(c[mc][(ncp+p)*2],   alo[mc], bh[p][0], bh[p][2]);
                        MMA_BF16(c[mc][(ncp+p)*2+1], alo[mc], bh[p][1], bh[p][3]);
                    }
            }
        }
        __syncthreads();
    }

    #pragma unroll
    for (int mc = 0; mc < 2; mc++) {
        #pragma unroll
        for (int nf = 0; nf < 8; nf++) {
            int gr = m0 + m_base + mc * 16 + (lane >> 2);
            int gc = n0 + n_base + nf * 8 + (lane & 3) * 2;
            float2 v0 = make_float2(c[mc][nf][0], c[mc][nf][1]);
            float2 v1 = make_float2(c[mc][nf][2], c[mc][nf][3]);
            if (MODE == 2) {
                *(float2*)&outp[(size_t)gr * 1024 + gc] = v0;
                *(float2*)&outp[(size_t)(gr + 8) * 1024 + gc] = v1;
            } else {
                if (gc < 1024) {
                    *(float2*)&g_q[(size_t)gr * 1024 + gc] = v0;
                    *(float2*)&g_q[(size_t)(gr + 8) * 1024 + gc] = v1;
                } else if (gc < 1280) {
                    int kc = gc - 1024;
                    *(float2*)&g_k[(size_t)gr * 256 + kc] = v0;
                    *(float2*)&g_k[(size_t)(gr + 8) * 256 + kc] = v1;
                } else {
                    int vc = gc - 1280;
                    unsigned short h0,h1,l0,l1;
                    f2bf2(v0.x,h0,l0); f2bf2(v0.y,h1,l1);
                    *(uint32_t*)&g_vhi[(size_t)gr*256 + vc] = (uint32_t)h0 | ((uint32_t)h1<<16);
                    *(uint32_t*)&g_vlo[(size_t)gr*256 + vc] = (uint32_t)l0 | ((uint32_t)l1<<16);
                    f2bf2(v1.x,h0,l0); f2bf2(v1.y,h1,l1);
                    *(uint32_t*)&g_vhi[(size_t)(gr+8)*256 + vc] = (uint32_t)h0 | ((uint32_t)h1<<16);
                    *(uint32_t*)&g_vlo[(size_t)(gr+8)*256 + vc] = (uint32_t)l0 | ((uint32_t)l1<<16);
                }
            }
        }
    }
}

// ---------------- RMSNorm + partial RoPE + gain -> split bf16 ----------------
template<bool QSIDE>
__global__ void rms_rope_kernel(const float* __restrict__ gain) {
    const int NH = QSIDE ? H_ : KVH_;
    const float* buf = QSIDE ? g_q : g_k;
    int gw = blockIdx.x * (blockDim.x >> 5) + (threadIdx.x >> 5);
    int lane = threadIdx.x & 31;
    if (gw >= M_ * NH) return;
    int h = gw % NH, ms = gw / NH, s = ms % S_;
    const float* p = buf + (size_t)ms * (NH*HD_) + h * HD_;
    float v0 = p[lane], v1 = p[lane + 32];
    float ss = v0*v0 + v1*v1;
    #pragma unroll
    for (int o = 16; o; o >>= 1) ss += __shfl_xor_sync(0xffffffffu, ss, o);
    float r = rsqrtf(ss * (1.0f/64.0f) + 1.1920929e-7f);
    v0 *= r; v1 *= r;
    int i = lane & 15;
    float invf = exp2f(-0.83048202372184059f * (float)i);  // 10000^(-2i/32)
    float ang = (float)s * invf;
    float cc = cosf(ang), sn = sinf(ang);
    float other = __shfl_xor_sync(0xffffffffu, v0, 16);
    float nv0 = (lane < 16) ? (v0*cc + other*sn) : (-other*sn + v0*cc);
    float g = QSIDE ? (gain[h] * QSCALE_) : 1.0f;
    nv0 *= g; v1 *= g;
    unsigned short h0,l0,h1,l1;
    f2bf2(nv0,h0,l0); f2bf2(v1,h1,l1);
    size_t base = (size_t)ms * (NH*HD_) + h * HD_;
    if (QSIDE) {
        g_qhi[base + lane] = h0;   g_qlo[base + lane] = l0;
        g_qhi[base + lane + 32] = h1; g_qlo[base + lane + 32] = l1;
    } else {
        g_khi[base + lane] = h0;   g_klo[base + lane] = l0;
        g_khi[base + lane + 32] = h1; g_klo[base + lane + 32] = l1;
    }
}

// ---------------- tensor-core causal flash attention ----------------
#define FA_KH   0
#define FA_KL   18432
#define FA_VH   36864
#define FA_VL   55296
#define FA_SMEM 73728

__global__ void __launch_bounds__(256, 2)
flash_mma_kernel() {
    extern __shared__ char smem[];
    uint32_t sb = smem_u32(smem);

    int b = blockIdx.z, h = blockIdx.y;
    int q0 = (gridDim.x - 1 - blockIdx.x) * 128;
    int kvh = h >> 2;
    int tid = threadIdx.x;
    int wid = tid >> 5, lane = tid & 31;
    int r = lane >> 2, c2 = (lane & 3) * 2;
    int lrow = (lane & 7) + ((lane >> 3) & 1) * 8;
    int lcol = (lane >> 4) * 8;

    int qg0 = q0 + wid * 16 + r;
    int qg1 = qg0 + 8;
    size_t tok0 = (size_t)(b * S_) + qg0;
    size_t tok1 = tok0 + 8;
    int qmaxw = q0 + wid * 16 + 15;

    uint32_t qh[4][4], ql[4][4];
    #pragma unroll
    for (int t = 0; t < 4; t++) {
        size_t c0 = (size_t)h * 64 + t * 16 + c2;
        qh[t][0] = *(const uint32_t*)&g_qhi[tok0 * 1024 + c0];
        qh[t][1] = *(const uint32_t*)&g_qhi[tok1 * 1024 + c0];
        qh[t][2] = *(const uint32_t*)&g_qhi[tok0 * 1024 + c0 + 8];
        qh[t][3] = *(const uint32_t*)&g_qhi[tok1 * 1024 + c0 + 8];
        ql[t][0] = *(const uint32_t*)&g_qlo[tok0 * 1024 + c0];
        ql[t][1] = *(const uint32_t*)&g_qlo[tok1 * 1024 + c0];
        ql[t][2] = *(const uint32_t*)&g_qlo[tok0 * 1024 + c0 + 8];
        ql[t][3] = *(const uint32_t*)&g_qlo[tok1 * 1024 + c0 + 8];
    }

    float oc[8][4];
    #pragma unroll
    for (int j = 0; j < 8; j++)
        #pragma unroll
        for (int p = 0; p < 4; p++) oc[j][p] = 0.f;
    float mrow[2] = {-INFINITY, -INFINITY};
    float lrw[2]  = {0.f, 0.f};

    int q8 = tid & 7, rr = tid >> 3;

    for (int j0 = 0; j0 <= q0; j0 += 128) {
        __syncthreads();
        // K group first, then V group (two commit groups)
        #pragma unroll
        for (int arr = 0; arr < 2; arr++) {
            const unsigned short* s0 = arr ? g_klo : g_khi;
            #pragma unroll
            for (int p = 0; p < 4; p++) {
                int row = p * 32 + rr;
                CP_ASYNC16(sb + arr * 18432 + row * 144 + q8 * 16,
                           s0 + (size_t)(b * S_ + j0 + row) * 256 + kvh * 64 + q8 * 8);
            }
        }
        CP_COMMIT();
        #pragma unroll
        for (int arr = 0; arr < 2; arr++) {
            const unsigned short* s0 = arr ? g_vlo : g_vhi;
            #pragma unroll
            for (int p = 0; p < 4; p++) {
                int row = p * 32 + rr;
                CP_ASYNC16(sb + (arr + 2) * 18432 + row * 144 + q8 * 16,
                           s0 + (size_t)(b * S_ + j0 + row) * 256 + kvh * 64 + q8 * 8);
            }
        }
        CP_COMMIT();
        CP_WAIT(1);          // K ready; V still in flight
        __syncthreads();

        #pragma unroll
        for (int half = 0; half < 2; half++) {
            int kg0 = j0 + half * 64;
            bool active = (kg0 <= qmaxw);
            int ks = half * 64;

            float sc[8][4];
            #pragma unroll
            for (int j = 0; j < 8; j++)
                #pragma unroll
                for (int p = 0; p < 4; p++) sc[j][p] = 0.f;

            if (active) {
                #pragma unroll
                for (int ncp = 0; ncp < 4; ncp += 2) {
                    #pragma unroll
                    for (int t = 0; t < 4; t++) {
                        uint32_t bh[2][4], bl[2][4];
                        #pragma unroll
                        for (int p = 0; p < 2; p++) {
                            uint32_t ka = sb + FA_KH + (ks + (ncp+p) * 16 + lrow) * 144
                                         + (t * 16 + lcol) * 2;
                            LDSM4(bh[p], ka);
                            LDSM4(bl[p], ka + (FA_KL - FA_KH));
                        }
                        // hi*hi (4 distinct accum pairs)
                        #pragma unroll
                        for (int p = 0; p < 2; p++) {
                            MMA_BF16(sc[(ncp+p)*2],   qh[t], bh[p][0], bh[p][2]);
                            MMA_BF16(sc[(ncp+p)*2+1], qh[t], bh[p][1], bh[p][3]);
                        }
                        // lo*hi
                        #pragma unroll
                        for (int p = 0; p < 2; p++) {
                            MMA_BF16(sc[(ncp+p)*2],   ql[t], bh[p][0], bh[p][2]);
                            MMA_BF16(sc[(ncp+p)*2+1], ql[t], bh[p][1], bh[p][3]);
                        }
                        // hi*lo
                        #pragma unroll
                        for (int p = 0; p < 2; p++) {
                            MMA_BF16(sc[(ncp+p)*2],   qh[t], bl[p][0], bl[p][2]);
                            MMA_BF16(sc[(ncp+p)*2+1], qh[t], bl[p][1], bl[p][3]);
                        }
                    }
                }

                if (kg0 + 63 > q0 + wid * 16) {
                    #pragma unroll
                    for (int j = 0; j < 8; j++) {
                        int key = kg0 + 8 * j + c2;
                        if (key     > qg0) sc[j][0] = -1e30f;
                        if (key + 1 > qg0) sc[j][1] = -1e30f;
                        if (key     > qg1) sc[j][2] = -1e30f;
                        if (key + 1 > qg1) sc[j][3] = -1e30f;
                    }
                }

                #pragma unroll
                for (int rh = 0; rh < 2; rh++) {
                    float rm = sc[0][rh*2];
                    #pragma unroll
                    for (int j = 0; j < 8; j++) {
                        rm = fmaxf(rm, sc[j][rh*2]);
                        rm = fmaxf(rm, sc[j][rh*2+1]);
                    }
                    rm = fmaxf(rm, __shfl_xor_sync(0xffffffffu, rm, 1));
                    rm = fmaxf(rm, __shfl_xor_sync(0xffffffffu, rm, 2));
                    float mn = fmaxf(mrow[rh], rm);
                    float alpha = exp2_fast(mrow[rh] - mn);
                    mrow[rh] = mn;
                    float rs = 0.f;
                    #pragma unroll
                    for (int j = 0; j < 8; j++) {
                        sc[j][rh*2]   = exp2_fast(sc[j][rh*2]   - mn);
                        sc[j][rh*2+1] = exp2_fast(sc[j][rh*2+1] - mn);
                        rs += sc[j][rh*2] + sc[j][rh*2+1];
                    }
                    rs += __shfl_xor_sync(0xffffffffu, rs, 1);
                    rs += __shfl_xor_sync(0xffffffffu, rs, 2);
                    lrw[rh] = lrw[rh] * alpha + rs;
                    #pragma unroll
                    for (int j = 0; j < 8; j++) {
                        oc[j][rh*2]   *= alpha;
                        oc[j][rh*2+1] *= alpha;
                    }
                }
            }

            if (half == 0) {     // all warps execute half 0: safe collective point
                CP_WAIT(0);      // V ready
                __syncthreads();
            }

            if (active) {
                #pragma unroll
                for (int u = 0; u < 4; u++) {
                    uint32_t A_hi[4], A_lo[4];
                    #pragma unroll
                    for (int fr = 0; fr < 4; fr++) {
                        int cj = 2*u + (fr >> 1);
                        int po = (fr & 1) * 2;
                        float p0 = sc[cj][po], p1 = sc[cj][po+1];
                        uint32_t hp = pkbf(p0, p1);
                        float h0 = __uint_as_float(hp << 16);
                        float h1 = __uint_as_float(hp & 0xffff0000u);
                        A_hi[fr] = hp;
                        A_lo[fr] = pkbf(p0 - h0, p1 - h1);
                    }
                    #pragma unroll
                    for (int dvp = 0; dvp < 4; dvp += 2) {
                        uint32_t vh[2][4], vl[2][4];
                        #pragma unroll
                        for (int p = 0; p < 2; p++) {
                            uint32_t va = sb + FA_VH + (ks + u * 16 + (lane & 15)) * 144
                                         + ((dvp+p) * 16 + (lane >> 4) * 8) * 2;
                            LDSM4T(vh[p], va);
                            LDSM4T(vl[p], va + (FA_VL - FA_VH));
                        }
                        // hi*hi
                        #pragma unroll
                        for (int p = 0; p < 2; p++) {
                            MMA_BF16(oc[(dvp+p)*2],   A_hi, vh[p][0], vh[p][1]);
                            MMA_BF16(oc[(dvp+p)*2+1], A_hi, vh[p][2], vh[p][3]);
                        }
                        // lo*hi
                        #pragma unroll
                        for (int p = 0; p < 2; p++) {
                            MMA_BF16(oc[(dvp+p)*2],   A_lo, vh[p][0], vh[p][1]);
                            MMA_BF16(oc[(dvp+p)*2+1], A_lo, vh[p][2], vh[p][3]);
                        }
                        // hi*lo
                        #pragma unroll
                        for (int p = 0; p < 2; p++) {
                            MMA_BF16(oc[(dvp+p)*2],   A_hi, vl[p][0], vl[p][1]);
                            MMA_BF16(oc[(dvp+p)*2+1], A_hi, vl[p][2], vl[p][3]);
                        }
                    }
                }
            }
        }
    }

    float inv0 = 1.0f / lrw[0], inv1 = 1.0f / lrw[1];
    #pragma unroll
    for (int j = 0; j < 8; j++) {
        size_t col = (size_t)h * 64 + 8 * j + c2;
        float y0 = oc[j][0] * inv0, y1 = oc[j][1] * inv0;
        float y2 = oc[j][2] * inv1, y3 = oc[j][3] * inv1;
        uint32_t hp0 = pkbf(y0, y1);
        uint32_t lp0 = pkbf(y0 - __uint_as_float(hp0 << 16),
                            y1 - __uint_as_float(hp0 & 0xffff0000u));
        uint32_t hp1 = pkbf(y2, y3);
        uint32_t lp1 = pkbf(y2 - __uint_as_float(hp1 << 16),
                            y3 - __uint_as_float(hp1 & 0xffff0000u));
        *(uint32_t*)&g_yhi[tok0 * 1024 + col] = hp0;
        *(uint32_t*)&g_ylo[tok0 * 1024 + col] = lp0;
        *(uint32_t*)&g_yhi[tok1 * 1024 + col] = hp1;
        *(uint32_t*)&g_ylo[tok1 * 1024 + col] = lp1;
    }
}

// ---------------- launch ----------------
extern "C" void kernel_launch(void* const* d_in, const int* in_sizes, int n_in,
                              void* d_out, int out_size) {
    const float* x    = (const float*)d_in[0];
    const float* Wq   = (const float*)d_in[1];
    const float* Wk   = (const float*)d_in[2];
    const float* Wv   = (const float*)d_in[3];
    const float* Wp   = (const float*)d_in[4];
    const float* gain = (const float*)d_in[5];
    const float* Aq   = (const float*)d_in[6];
    const float* Bq   = (const float*)d_in[7];
    const float* Av   = (const float*)d_in[8];
    const float* Bv   = (const float*)d_in[9];
    const int*   step = (const int*)d_in[10];
    float* out = (float*)d_out;

    __nv_bfloat16 *xh, *xl;
    cudaGetSymbolAddress((void**)&xh, g_xhi);
    cudaGetSymbolAddress((void**)&xl, g_xlo);

    prep_w_kernel<<<(WROWS_*256 + 255)/256, 256>>>(Wq, Wk, Wv, Wp, Aq, Bq, Av, Bv, step);
    prep_split_kernel<<<(M_*DIM_/4 + 255)/256, 256>>>(x, xh, xl, M_*DIM_/4);

    cudaFuncSetAttribute(gemm_mma_kernel<0>, cudaFuncAttributeMaxDynamicSharedMemorySize, G_SMEM);
    cudaFuncSetAttribute(gemm_mma_kernel<2>, cudaFuncAttributeMaxDynamicSharedMemorySize, G_SMEM);
    cudaFuncSetAttribute(flash_mma_kernel,   cudaFuncAttributeMaxDynamicSharedMemorySize, FA_SMEM);

    gemm_mma_kernel<0><<<dim3(1536/128, M_/128), 256, G_SMEM>>>(nullptr);

    rms_rope_kernel<true ><<<(M_*H_)  / 8, 256>>>(gain);
    rms_rope_kernel<false><<<(M_*KVH_)/ 8, 256>>>(nullptr);

    flash_mma_kernel<<<dim3(S_/128, H_, B_), 256, FA_SMEM>>>();

    gemm_mma_kernel<2><<<dim3(1024/128, M_/128), 256, G_SMEM>>>(out);
}

// round 7
// speedup vs baseline: 5.2954x; 1.4544x over previous
#include <cuda_runtime.h>
#include <cuda_fp16.h>
#include <math.h>
#include <stdint.h>

#define B_      2
#define S_      2048
#define DIM_    1024
#define H_      16
#define KVH_    4
#define HD_     64
#define KVDIM_  256
#define R_      4
#define NSTEPS_ 2
#define M_      (B_*S_)
#define WROWS_  2560   // [0,1024): Wq+lora | [1024,1280): Wk | [1280,1536): Wv+lora | [1536,2560): Wp
#define WSCALE_    256.0f
#define WSCALE_INV (1.0f/256.0f)

#define QSCALE_ (0.125f * 1.4426950408889634f)

typedef unsigned short ushort_t;

__device__ __forceinline__ uint32_t smem_u32(const void* p) {
    uint32_t a;
    asm("{ .reg .u64 t; cvta.to.shared.u64 t, %1; cvt.u32.u64 %0, t; }" : "=r"(a) : "l"(p));
    return a;
}

#define LDSM4(r, addr) \
    asm volatile("ldmatrix.sync.aligned.m8n8.x4.shared.b16 {%0,%1,%2,%3}, [%4];" \
        : "=r"((r)[0]),"=r"((r)[1]),"=r"((r)[2]),"=r"((r)[3]) : "r"(addr))
#define LDSM4T(r, addr) \
    asm volatile("ldmatrix.sync.aligned.m8n8.x4.trans.shared.b16 {%0,%1,%2,%3}, [%4];" \
        : "=r"((r)[0]),"=r"((r)[1]),"=r"((r)[2]),"=r"((r)[3]) : "r"(addr))

#define MMA_F16(c, a, b0v, b1v) \
    asm volatile("mma.sync.aligned.m16n8k16.row.col.f32.f16.f16.f32 " \
        "{%0,%1,%2,%3}, {%4,%5,%6,%7}, {%8,%9}, {%0,%1,%2,%3};" \
        : "+f"((c)[0]),"+f"((c)[1]),"+f"((c)[2]),"+f"((c)[3]) \
        : "r"((a)[0]),"r"((a)[1]),"r"((a)[2]),"r"((a)[3]), "r"(b0v),"r"(b1v))

#define CP_ASYNC16(dst, src) \
    asm volatile("cp.async.cg.shared.global [%0], [%1], 16;" :: "r"(dst), "l"(src) : "memory")
#define CP_COMMIT() asm volatile("cp.async.commit_group;" ::: "memory")
#define CP_WAIT(n)  asm volatile("cp.async.wait_group %0;" :: "n"(n) : "memory")

// pack two fp32 -> half2 (first arg -> low half)
__device__ __forceinline__ uint32_t pkhf(float lo, float hi) {
    uint32_t r; asm("cvt.rn.f16x2.f32 %0, %1, %2;" : "=r"(r) : "f"(hi), "f"(lo)); return r;
}

__device__ __forceinline__ float exp2_fast(float y) {
    y = fmaxf(y, -80.f);
    float fl = floorf(y);
    float t = y - fl;
    float p = 1.5403530e-4f;
    p = fmaf(p, t, 1.3333558e-3f);
    p = fmaf(p, t, 9.6181291e-3f);
    p = fmaf(p, t, 5.5504109e-2f);
    p = fmaf(p, t, 2.4022651e-1f);
    p = fmaf(p, t, 6.9314718e-1f);
    p = fmaf(p, t, 1.0f);
    return __int_as_float(((int)fl + 127) << 23) * p;
}

// ---------------- scratch ----------------
__device__ float    g_q[M_*DIM_];        // raw Q gemm out, pre-norm
__device__ float    g_k[M_*KVDIM_];      // raw K gemm out, pre-norm
__device__ ushort_t g_xf[M_*DIM_];       // x fp16
__device__ ushort_t g_yf[M_*DIM_];       // attention out fp16
__device__ ushort_t g_whf[WROWS_*DIM_], g_wlf[WROWS_*DIM_];  // W*256 hi/lo fp16
__device__ ushort_t g_qf[M_*DIM_];       // normed+roped+scaled Q fp16
__device__ ushort_t g_kf[M_*KVDIM_];     // normed+roped K fp16
__device__ ushort_t g_vf[M_*KVDIM_];     // V fp16

// ---------------- prep: x -> fp16 ----------------
__global__ void prep_xf_kernel(const float* __restrict__ src,
                               ushort_t* __restrict__ dst, int n4) {
    int t = blockIdx.x * blockDim.x + threadIdx.x;
    if (t >= n4) return;
    float4 v = ((const float4*)src)[t];
    uint2 o;
    o.x = pkhf(v.x, v.y);
    o.y = pkhf(v.z, v.w);
    ((uint2*)dst)[t] = o;
}

// ---------------- prep: fold LoRA, scale, split fp16 hi/lo ----------------
__global__ void prep_w_kernel(const float* __restrict__ Wq, const float* __restrict__ Wk,
                              const float* __restrict__ Wv, const float* __restrict__ Wp,
                              const float* __restrict__ Aq, const float* __restrict__ Bq,
                              const float* __restrict__ Av, const float* __restrict__ Bv,
                              const int*   __restrict__ stepp) {
    int t = blockIdx.x * blockDim.x + threadIdx.x;
    if (t >= WROWS_ * 256) return;
    int row = t >> 8, k4 = t & 255;
    int step = *stepp;
    bool ok = (step >= 0 && step < NSTEPS_);
    float4 w;
    if (row < 1024) {
        w = ((const float4*)(Wq + (size_t)row * DIM_))[k4];
        if (ok) {
            const float* Ab = Aq + (size_t)step * R_ * DIM_;
            const float* Bb = Bq + ((size_t)step * DIM_ + row) * R_;
            #pragma unroll
            for (int r = 0; r < R_; r++) {
                float b = Bb[r];
                float4 a = ((const float4*)(Ab + (size_t)r * DIM_))[k4];
                w.x += b*a.x; w.y += b*a.y; w.z += b*a.z; w.w += b*a.w;
            }
        }
    } else if (row < 1280) {
        w = ((const float4*)(Wk + (size_t)(row - 1024) * DIM_))[k4];
    } else if (row < 1536) {
        int vr = row - 1280;
        w = ((const float4*)(Wv + (size_t)vr * DIM_))[k4];
        if (ok) {
            const float* Ab = Av + (size_t)step * R_ * DIM_;
            const float* Bb = Bv + ((size_t)step * KVDIM_ + vr) * R_;
            #pragma unroll
            for (int r = 0; r < R_; r++) {
                float b = Bb[r];
                float4 a = ((const float4*)(Ab + (size_t)r * DIM_))[k4];
                w.x += b*a.x; w.y += b*a.y; w.z += b*a.z; w.w += b*a.w;
            }
        }
    } else {
        w = ((const float4*)(Wp + (size_t)(row - 1536) * DIM_))[k4];
    }
    w.x *= WSCALE_; w.y *= WSCALE_; w.z *= WSCALE_; w.w *= WSCALE_;
    float hx = __half2float(__float2half_rn(w.x));
    float hy = __half2float(__float2half_rn(w.y));
    float hz = __half2float(__float2half_rn(w.z));
    float hw = __half2float(__float2half_rn(w.w));
    uint2 hp, lp;
    hp.x = pkhf(hx, hy);          hp.y = pkhf(hz, hw);
    lp.x = pkhf(w.x - hx, w.y - hy);
    lp.y = pkhf(w.z - hz, w.w - hw);
    ((uint2*)g_whf)[t] = hp;
    ((uint2*)g_wlf)[t] = lp;
}

// ---------------- fp16 2-product GEMM: Y[m,n] = X[m,:] . W[n,:] ----------------
// smem/stage: A (10240) + Whi (10240) + Wlo (10240) = 30720; 2 stages.
#define GT_      10240
#define GSTAGE_  (3*GT_)
#define G_SMEM   (2*GSTAGE_)

// MODE 0: merged QKV (N=1536, Woff=0) | MODE 2: proj (N=1024, Woff=1536, A=g_yf)
template<int MODE>
__global__ void __launch_bounds__(256, 2)
gemm_mma_kernel(float* __restrict__ outp) {
    extern __shared__ char smem[];
    uint32_t sb = smem_u32(smem);
    constexpr int WOFF = (MODE == 0) ? 0 : 1536;
    const ushort_t* Xf = (MODE == 2) ? g_yf : g_xf;

    int m0 = blockIdx.y * 128, n0 = blockIdx.x * 128;
    int tid = threadIdx.x;
    int wid = tid >> 5, lane = tid & 31;
    int m_base = (wid >> 1) * 32, n_base = (wid & 1) * 64;
    int lrow = (lane & 7) + ((lane >> 3) & 1) * 8;
    int lcol = (lane >> 4) * 8;

    auto load_stage = [&](int it, int s) {
        int k0 = it * 32;
        int row_half = tid >> 2;   // 0..63
        int q = tid & 3;
        #pragma unroll
        for (int t = 0; t < 6; t++) {
            int tile = t >> 1;     // 0:A 1:Whi 2:Wlo
            int row = (t & 1) * 64 + row_half;
            const ushort_t* src;
            if (tile == 0)      src = Xf   + (size_t)(m0 + row) * DIM_ + k0 + q * 8;
            else if (tile == 1) src = g_whf + (size_t)(WOFF + n0 + row) * DIM_ + k0 + q * 8;
            else                src = g_wlf + (size_t)(WOFF + n0 + row) * DIM_ + k0 + q * 8;
            CP_ASYNC16(sb + s * GSTAGE_ + tile * GT_ + row * 80 + q * 16, src);
        }
        CP_COMMIT();
    };

    float c[2][8][4];
    #pragma unroll
    for (int i = 0; i < 2; i++)
        #pragma unroll
        for (int j = 0; j < 8; j++)
            #pragma unroll
            for (int p = 0; p < 4; p++) c[i][j][p] = 0.f;

    load_stage(0, 0);

    for (int it = 0; it < 32; it++) {
        if (it < 31) { load_stage(it + 1, (it + 1) & 1); CP_WAIT(1); }
        else         { CP_WAIT(0); }
        __syncthreads();

        uint32_t base = sb + (it & 1) * GSTAGE_;

        #pragma unroll
        for (int ks = 0; ks < 2; ks++) {
            int kb = ks * 16;
            uint32_t a[2][4];
            #pragma unroll
            for (int mc = 0; mc < 2; mc++)
                LDSM4(a[mc], base + (m_base + mc * 16 + lrow) * 80 + (kb + lcol) * 2);
            #pragma unroll
            for (int ncp = 0; ncp < 4; ncp += 2) {
                uint32_t bh[2][4], bl[2][4];
                #pragma unroll
                for (int p = 0; p < 2; p++) {
                    uint32_t baddr = base + GT_ + (n_base + (ncp+p) * 16 + lrow) * 80 + (kb + lcol) * 2;
                    LDSM4(bh[p], baddr);
                    LDSM4(bl[p], baddr + GT_);
                }
                // term W_hi
                #pragma unroll
                for (int p = 0; p < 2; p++)
                    #pragma unroll
                    for (int mc = 0; mc < 2; mc++) {
                        MMA_F16(c[mc][(ncp+p)*2],   a[mc], bh[p][0], bh[p][2]);
                        MMA_F16(c[mc][(ncp+p)*2+1], a[mc], bh[p][1], bh[p][3]);
                    }
                // term W_lo
                #pragma unroll
                for (int p = 0; p < 2; p++)
                    #pragma unroll
                    for (int mc = 0; mc < 2; mc++) {
                        MMA_F16(c[mc][(ncp+p)*2],   a[mc], bl[p][0], bl[p][2]);
                        MMA_F16(c[mc][(ncp+p)*2+1], a[mc], bl[p][1], bl[p][3]);
                    }
            }
        }
        __syncthreads();
    }

    #pragma unroll
    for (int mc = 0; mc < 2; mc++) {
        #pragma unroll
        for (int nf = 0; nf < 8; nf++) {
            int gr = m0 + m_base + mc * 16 + (lane >> 2);
            int gc = n0 + n_base + nf * 8 + (lane & 3) * 2;
            float2 v0 = make_float2(c[mc][nf][0] * WSCALE_INV, c[mc][nf][1] * WSCALE_INV);
            float2 v1 = make_float2(c[mc][nf][2] * WSCALE_INV, c[mc][nf][3] * WSCALE_INV);
            if (MODE == 2) {
                *(float2*)&outp[(size_t)gr * 1024 + gc] = v0;
                *(float2*)&outp[(size_t)(gr + 8) * 1024 + gc] = v1;
            } else {
                if (gc < 1024) {
                    *(float2*)&g_q[(size_t)gr * 1024 + gc] = v0;
                    *(float2*)&g_q[(size_t)(gr + 8) * 1024 + gc] = v1;
                } else if (gc < 1280) {
                    int kc = gc - 1024;
                    *(float2*)&g_k[(size_t)gr * 256 + kc] = v0;
                    *(float2*)&g_k[(size_t)(gr + 8) * 256 + kc] = v1;
                } else {
                    int vc = gc - 1280;
                    *(uint32_t*)&g_vf[(size_t)gr*256 + vc]     = pkhf(v0.x, v0.y);
                    *(uint32_t*)&g_vf[(size_t)(gr+8)*256 + vc] = pkhf(v1.x, v1.y);
                }
            }
        }
    }
}

// ---------------- RMSNorm + partial RoPE + gain -> fp16 ----------------
template<bool QSIDE>
__global__ void rms_rope_kernel(const float* __restrict__ gain) {
    const int NH = QSIDE ? H_ : KVH_;
    const float* buf = QSIDE ? g_q : g_k;
    int gw = blockIdx.x * (blockDim.x >> 5) + (threadIdx.x >> 5);
    int lane = threadIdx.x & 31;
    if (gw >= M_ * NH) return;
    int h = gw % NH, ms = gw / NH, s = ms % S_;
    const float* p = buf + (size_t)ms * (NH*HD_) + h * HD_;
    float v0 = p[lane], v1 = p[lane + 32];
    float ss = v0*v0 + v1*v1;
    #pragma unroll
    for (int o = 16; o; o >>= 1) ss += __shfl_xor_sync(0xffffffffu, ss, o);
    float r = rsqrtf(ss * (1.0f/64.0f) + 1.1920929e-7f);
    v0 *= r; v1 *= r;
    int i = lane & 15;
    float invf = exp2f(-0.83048202372184059f * (float)i);  // 10000^(-2i/32)
    float ang = (float)s * invf;
    float cc = cosf(ang), sn = sinf(ang);
    float other = __shfl_xor_sync(0xffffffffu, v0, 16);
    float nv0 = (lane < 16) ? (v0*cc + other*sn) : (-other*sn + v0*cc);
    float g = QSIDE ? (gain[h] * QSCALE_) : 1.0f;
    nv0 *= g; v1 *= g;
    size_t base = (size_t)ms * (NH*HD_) + h * HD_;
    ushort_t* dst = QSIDE ? g_qf : g_kf;
    dst[base + lane]      = __half_as_ushort(__float2half_rn(nv0));
    dst[base + lane + 32] = __half_as_ushort(__float2half_rn(v1));
}

// ---------------- tensor-core causal flash attention (fp16) ----------------
// double-buffered K/V tiles: per stage K[128][72] + V[128][72] fp16 (144B rows)
#define FA_TILE  18432
#define FA_STG   (2*FA_TILE)
#define FA_SMEM  (2*FA_STG)    // 73728

__global__ void __launch_bounds__(256, 2)
flash_mma_kernel() {
    extern __shared__ char smem[];
    uint32_t sb = smem_u32(smem);

    int b = blockIdx.z, h = blockIdx.y;
    int q0 = (gridDim.x - 1 - blockIdx.x) * 128;
    int kvh = h >> 2;
    int tid = threadIdx.x;
    int wid = tid >> 5, lane = tid & 31;
    int r = lane >> 2, c2 = (lane & 3) * 2;
    int lrow = (lane & 7) + ((lane >> 3) & 1) * 8;
    int lcol = (lane >> 4) * 8;

    int qg0 = q0 + wid * 16 + r;
    int qg1 = qg0 + 8;
    size_t tok0 = (size_t)(b * S_) + qg0;
    size_t tok1 = tok0 + 8;
    int qmaxw = q0 + wid * 16 + 15;

    // Q fragments (fp16, single)
    uint32_t qf[4][4];
    #pragma unroll
    for (int t = 0; t < 4; t++) {
        size_t c0 = (size_t)h * 64 + t * 16 + c2;
        qf[t][0] = *(const uint32_t*)&g_qf[tok0 * 1024 + c0];
        qf[t][1] = *(const uint32_t*)&g_qf[tok1 * 1024 + c0];
        qf[t][2] = *(const uint32_t*)&g_qf[tok0 * 1024 + c0 + 8];
        qf[t][3] = *(const uint32_t*)&g_qf[tok1 * 1024 + c0 + 8];
    }

    float oc[8][4];
    #pragma unroll
    for (int j = 0; j < 8; j++)
        #pragma unroll
        for (int p = 0; p < 4; p++) oc[j][p] = 0.f;
    float mrow[2] = {-INFINITY, -INFINITY};
    float lrw[2]  = {0.f, 0.f};

    int q8 = tid & 7, rr = tid >> 3;

    auto load_tile = [&](int j0, int s) {
        #pragma unroll
        for (int p = 0; p < 4; p++) {
            int row = p * 32 + rr;
            size_t gsrc = (size_t)(b * S_ + j0 + row) * 256 + kvh * 64 + q8 * 8;
            CP_ASYNC16(sb + s * FA_STG + row * 144 + q8 * 16, g_kf + gsrc);
            CP_ASYNC16(sb + s * FA_STG + FA_TILE + row * 144 + q8 * 16, g_vf + gsrc);
        }
        CP_COMMIT();
    };

    load_tile(0, 0);

    for (int j0 = 0; j0 <= q0; j0 += 128) {
        int buf = (j0 >> 7) & 1;
        if (j0 + 128 <= q0) { load_tile(j0 + 128, buf ^ 1); CP_WAIT(1); }
        else                { CP_WAIT(0); }
        __syncthreads();

        uint32_t kbank = sb + buf * FA_STG;
        uint32_t vbank = kbank + FA_TILE;

        #pragma unroll
        for (int half = 0; half < 2; half++) {
            int kg0 = j0 + half * 64;
            bool active = (kg0 <= qmaxw);
            int ks = half * 64;

            if (active) {
                float sc[8][4];
                #pragma unroll
                for (int j = 0; j < 8; j++)
                    #pragma unroll
                    for (int p = 0; p < 4; p++) sc[j][p] = 0.f;

                // scores = Q.K^T (single product)
                #pragma unroll
                for (int ncp = 0; ncp < 4; ncp += 2) {
                    #pragma unroll
                    for (int t = 0; t < 4; t++) {
                        uint32_t bk[2][4];
                        #pragma unroll
                        for (int p = 0; p < 2; p++)
                            LDSM4(bk[p], kbank + (ks + (ncp+p) * 16 + lrow) * 144
                                         + (t * 16 + lcol) * 2);
                        #pragma unroll
                        for (int p = 0; p < 2; p++) {
                            MMA_F16(sc[(ncp+p)*2],   qf[t], bk[p][0], bk[p][2]);
                            MMA_F16(sc[(ncp+p)*2+1], qf[t], bk[p][1], bk[p][3]);
                        }
                    }
                }

                if (kg0 + 63 > q0 + wid * 16) {
                    #pragma unroll
                    for (int j = 0; j < 8; j++) {
                        int key = kg0 + 8 * j + c2;
                        if (key     > qg0) sc[j][0] = -1e30f;
                        if (key + 1 > qg0) sc[j][1] = -1e30f;
                        if (key     > qg1) sc[j][2] = -1e30f;
                        if (key + 1 > qg1) sc[j][3] = -1e30f;
                    }
                }

                // online softmax (base-2)
                #pragma unroll
                for (int rh = 0; rh < 2; rh++) {
                    float rm = sc[0][rh*2];
                    #pragma unroll
                    for (int j = 0; j < 8; j++) {
                        rm = fmaxf(rm, sc[j][rh*2]);
                        rm = fmaxf(rm, sc[j][rh*2+1]);
                    }
                    rm = fmaxf(rm, __shfl_xor_sync(0xffffffffu, rm, 1));
                    rm = fmaxf(rm, __shfl_xor_sync(0xffffffffu, rm, 2));
                    float mn = fmaxf(mrow[rh], rm);
                    float alpha = exp2_fast(mrow[rh] - mn);
                    mrow[rh] = mn;
                    float rs = 0.f;
                    #pragma unroll
                    for (int j = 0; j < 8; j++) {
                        sc[j][rh*2]   = exp2_fast(sc[j][rh*2]   - mn);
                        sc[j][rh*2+1] = exp2_fast(sc[j][rh*2+1] - mn);
                        rs += sc[j][rh*2] + sc[j][rh*2+1];
                    }
                    rs += __shfl_xor_sync(0xffffffffu, rs, 1);
                    rs += __shfl_xor_sync(0xffffffffu, rs, 2);
                    lrw[rh] = lrw[rh] * alpha + rs;
                    #pragma unroll
                    for (int j = 0; j < 8; j++) {
                        oc[j][rh*2]   *= alpha;
                        oc[j][rh*2+1] *= alpha;
                    }
                }

                // O += P @ V : P split hi/lo fp16, V single fp16 (2 products)
                #pragma unroll
                for (int u = 0; u < 4; u++) {
                    uint32_t A_hi[4], A_lo[4];
                    #pragma unroll
                    for (int fr = 0; fr < 4; fr++) {
                        int cj = 2*u + (fr >> 1);
                        int po = (fr & 1) * 2;
                        float p0 = sc[cj][po], p1 = sc[cj][po+1];
                        uint32_t hp = pkhf(p0, p1);
                        __half2 h2 = *reinterpret_cast<__half2*>(&hp);
                        A_hi[fr] = hp;
                        A_lo[fr] = pkhf(p0 - __low2float(h2), p1 - __high2float(h2));
                    }
                    #pragma unroll
                    for (int dvp = 0; dvp < 4; dvp += 2) {
                        uint32_t vv[2][4];
                        #pragma unroll
                        for (int p = 0; p < 2; p++)
                            LDSM4T(vv[p], vbank + (ks + u * 16 + (lane & 15)) * 144
                                          + ((dvp+p) * 16 + (lane >> 4) * 8) * 2);
                        #pragma unroll
                        for (int p = 0; p < 2; p++) {
                            MMA_F16(oc[(dvp+p)*2],   A_hi, vv[p][0], vv[p][1]);
                            MMA_F16(oc[(dvp+p)*2+1], A_hi, vv[p][2], vv[p][3]);
                        }
                        #pragma unroll
                        for (int p = 0; p < 2; p++) {
                            MMA_F16(oc[(dvp+p)*2],   A_lo, vv[p][0], vv[p][1]);
                            MMA_F16(oc[(dvp+p)*2+1], A_lo, vv[p][2], vv[p][3]);
                        }
                    }
                }
            }
        }
        __syncthreads();   // compute on this buffer done before next-next load
    }

    // epilogue: y = O / l -> fp16
    float inv0 = 1.0f / lrw[0], inv1 = 1.0f / lrw[1];
    #pragma unroll
    for (int j = 0; j < 8; j++) {
        size_t col = (size_t)h * 64 + 8 * j + c2;
        *(uint32_t*)&g_yf[tok0 * 1024 + col] = pkhf(oc[j][0] * inv0, oc[j][1] * inv0);
        *(uint32_t*)&g_yf[tok1 * 1024 + col] = pkhf(oc[j][2] * inv1, oc[j][3] * inv1);
    }
}

// ---------------- launch ----------------
extern "C" void kernel_launch(void* const* d_in, const int* in_sizes, int n_in,
                              void* d_out, int out_size) {
    const float* x    = (const float*)d_in[0];
    const float* Wq   = (const float*)d_in[1];
    const float* Wk   = (const float*)d_in[2];
    const float* Wv   = (const float*)d_in[3];
    const float* Wp   = (const float*)d_in[4];
    const float* gain = (const float*)d_in[5];
    const float* Aq   = (const float*)d_in[6];
    const float* Bq   = (const float*)d_in[7];
    const float* Av   = (const float*)d_in[8];
    const float* Bv   = (const float*)d_in[9];
    const int*   step = (const int*)d_in[10];
    float* out = (float*)d_out;

    ushort_t* xf;
    cudaGetSymbolAddress((void**)&xf, g_xf);

    prep_w_kernel<<<(WROWS_*256 + 255)/256, 256>>>(Wq, Wk, Wv, Wp, Aq, Bq, Av, Bv, step);
    prep_xf_kernel<<<(M_*DIM_/4 + 255)/256, 256>>>(x, xf, M_*DIM_/4);

    cudaFuncSetAttribute(gemm_mma_kernel<0>, cudaFuncAttributeMaxDynamicSharedMemorySize, G_SMEM);
    cudaFuncSetAttribute(gemm_mma_kernel<2>, cudaFuncAttributeMaxDynamicSharedMemorySize, G_SMEM);
    cudaFuncSetAttribute(flash_mma_kernel,   cudaFuncAttributeMaxDynamicSharedMemorySize, FA_SMEM);

    gemm_mma_kernel<0><<<dim3(1536/128, M_/128), 256, G_SMEM>>>(nullptr);

    rms_rope_kernel<true ><<<(M_*H_)  / 8, 256>>>(gain);
    rms_rope_kernel<false><<<(M_*KVH_)/ 8, 256>>>(nullptr);

    flash_mma_kernel<<<dim3(S_/128, H_, B_), 256, FA_SMEM>>>();

    gemm_mma_kernel<2><<<dim3(1024/128, M_/128), 256, G_SMEM>>>(out);
}

// round 8
// speedup vs baseline: 5.3759x; 1.0152x over previous
#include <cuda_runtime.h>
#include <cuda_fp16.h>
#include <math.h>
#include <stdint.h>

#define B_      2
#define S_      2048
#define DIM_    1024
#define H_      16
#define KVH_    4
#define HD_     64
#define KVDIM_  256
#define R_      4
#define NSTEPS_ 2
#define M_      (B_*S_)
#define WROWS_  2560   // [0,1024): Wq+lora | [1024,1280): Wk | [1280,1536): Wv+lora | [1536,2560): Wp
#define WSCALE_    256.0f
#define WSCALE_INV (1.0f/256.0f)

#define QSCALE_ (0.125f * 1.4426950408889634f)

typedef unsigned short ushort_t;

__device__ __forceinline__ uint32_t smem_u32(const void* p) {
    uint32_t a;
    asm("{ .reg .u64 t; cvta.to.shared.u64 t, %1; cvt.u32.u64 %0, t; }" : "=r"(a) : "l"(p));
    return a;
}

#define LDSM4(r, addr) \
    asm volatile("ldmatrix.sync.aligned.m8n8.x4.shared.b16 {%0,%1,%2,%3}, [%4];" \
        : "=r"((r)[0]),"=r"((r)[1]),"=r"((r)[2]),"=r"((r)[3]) : "r"(addr))
#define LDSM4T(r, addr) \
    asm volatile("ldmatrix.sync.aligned.m8n8.x4.trans.shared.b16 {%0,%1,%2,%3}, [%4];" \
        : "=r"((r)[0]),"=r"((r)[1]),"=r"((r)[2]),"=r"((r)[3]) : "r"(addr))

#define MMA_F16(c, a, b0v, b1v) \
    asm volatile("mma.sync.aligned.m16n8k16.row.col.f32.f16.f16.f32 " \
        "{%0,%1,%2,%3}, {%4,%5,%6,%7}, {%8,%9}, {%0,%1,%2,%3};" \
        : "+f"((c)[0]),"+f"((c)[1]),"+f"((c)[2]),"+f"((c)[3]) \
        : "r"((a)[0]),"r"((a)[1]),"r"((a)[2]),"r"((a)[3]), "r"(b0v),"r"(b1v))

#define CP_ASYNC16(dst, src) \
    asm volatile("cp.async.cg.shared.global [%0], [%1], 16;" :: "r"(dst), "l"(src) : "memory")
#define CP_COMMIT() asm volatile("cp.async.commit_group;" ::: "memory")
#define CP_WAIT(n)  asm volatile("cp.async.wait_group %0;" :: "n"(n) : "memory")

__device__ __forceinline__ uint32_t pkhf(float lo, float hi) {
    uint32_t r; asm("cvt.rn.f16x2.f32 %0, %1, %2;" : "=r"(r) : "f"(hi), "f"(lo)); return r;
}

__device__ __forceinline__ float exp2_fast(float y) {
    y = fmaxf(y, -80.f);
    float fl = floorf(y);
    float t = y - fl;
    float p = 1.5403530e-4f;
    p = fmaf(p, t, 1.3333558e-3f);
    p = fmaf(p, t, 9.6181291e-3f);
    p = fmaf(p, t, 5.5504109e-2f);
    p = fmaf(p, t, 2.4022651e-1f);
    p = fmaf(p, t, 6.9314718e-1f);
    p = fmaf(p, t, 1.0f);
    return __int_as_float(((int)fl + 127) << 23) * p;
}

// ---------------- scratch ----------------
__device__ float    g_q[M_*DIM_];
__device__ float    g_k[M_*KVDIM_];
__device__ ushort_t g_xf[M_*DIM_];
__device__ ushort_t g_yf[M_*DIM_];
__device__ ushort_t g_whf[WROWS_*DIM_], g_wlf[WROWS_*DIM_];
__device__ ushort_t g_qf[M_*DIM_];
__device__ ushort_t g_kf[M_*KVDIM_];
__device__ ushort_t g_vf[M_*KVDIM_];

// ---------------- prep: x -> fp16 ----------------
__global__ void prep_xf_kernel(const float* __restrict__ src,
                               ushort_t* __restrict__ dst, int n4) {
    int t = blockIdx.x * blockDim.x + threadIdx.x;
    if (t >= n4) return;
    float4 v = ((const float4*)src)[t];
    uint2 o;
    o.x = pkhf(v.x, v.y);
    o.y = pkhf(v.z, v.w);
    ((uint2*)dst)[t] = o;
}

// ---------------- prep: fold LoRA, scale, split fp16 hi/lo ----------------
__global__ void prep_w_kernel(const float* __restrict__ Wq, const float* __restrict__ Wk,
                              const float* __restrict__ Wv, const float* __restrict__ Wp,
                              const float* __restrict__ Aq, const float* __restrict__ Bq,
                              const float* __restrict__ Av, const float* __restrict__ Bv,
                              const int*   __restrict__ stepp) {
    int t = blockIdx.x * blockDim.x + threadIdx.x;
    if (t >= WROWS_ * 256) return;
    int row = t >> 8, k4 = t & 255;
    int step = *stepp;
    bool ok = (step >= 0 && step < NSTEPS_);
    float4 w;
    if (row < 1024) {
        w = ((const float4*)(Wq + (size_t)row * DIM_))[k4];
        if (ok) {
            const float* Ab = Aq + (size_t)step * R_ * DIM_;
            const float* Bb = Bq + ((size_t)step * DIM_ + row) * R_;
            #pragma unroll
            for (int r = 0; r < R_; r++) {
                float b = Bb[r];
                float4 a = ((const float4*)(Ab + (size_t)r * DIM_))[k4];
                w.x += b*a.x; w.y += b*a.y; w.z += b*a.z; w.w += b*a.w;
            }
        }
    } else if (row < 1280) {
        w = ((const float4*)(Wk + (size_t)(row - 1024) * DIM_))[k4];
    } else if (row < 1536) {
        int vr = row - 1280;
        w = ((const float4*)(Wv + (size_t)vr * DIM_))[k4];
        if (ok) {
            const float* Ab = Av + (size_t)step * R_ * DIM_;
            const float* Bb = Bv + ((size_t)step * KVDIM_ + vr) * R_;
            #pragma unroll
            for (int r = 0; r < R_; r++) {
                float b = Bb[r];
                float4 a = ((const float4*)(Ab + (size_t)r * DIM_))[k4];
                w.x += b*a.x; w.y += b*a.y; w.z += b*a.z; w.w += b*a.w;
            }
        }
    } else {
        w = ((const float4*)(Wp + (size_t)(row - 1536) * DIM_))[k4];
    }
    w.x *= WSCALE_; w.y *= WSCALE_; w.z *= WSCALE_; w.w *= WSCALE_;
    float hx = __half2float(__float2half_rn(w.x));
    float hy = __half2float(__float2half_rn(w.y));
    float hz = __half2float(__float2half_rn(w.z));
    float hw = __half2float(__float2half_rn(w.w));
    uint2 hp, lp;
    hp.x = pkhf(hx, hy);          hp.y = pkhf(hz, hw);
    lp.x = pkhf(w.x - hx, w.y - hy);
    lp.y = pkhf(w.z - hz, w.w - hw);
    ((uint2*)g_whf)[t] = hp;
    ((uint2*)g_wlf)[t] = lp;
}

// ---------------- fp16 2-product GEMM: 128x128 CTA, 4 warps of 64x64, 3 stages ----------------
#define GT_      10240            // 128 rows x 80B
#define GSTAGE_  (3*GT_)          // A, Whi, Wlo
#define G_SMEM   (3*GSTAGE_)      // 3 stages = 92160

// MODE 0: merged QKV (N=1536, Woff=0) | MODE 2: proj (N=1024, Woff=1536, A=g_yf)
template<int MODE>
__global__ void __launch_bounds__(128, 2)
gemm_mma_kernel(float* __restrict__ outp) {
    extern __shared__ char smem[];
    uint32_t sb = smem_u32(smem);
    constexpr int WOFF = (MODE == 0) ? 0 : 1536;
    const ushort_t* Xf = (MODE == 2) ? g_yf : g_xf;

    int m0 = blockIdx.y * 128, n0 = blockIdx.x * 128;
    int tid = threadIdx.x;
    int wid = tid >> 5, lane = tid & 31;
    int wm = (wid >> 1) * 64, wn = (wid & 1) * 64;
    int lrow = (lane & 7) + ((lane >> 3) & 1) * 8;
    int lcol = (lane >> 4) * 8;

    auto load_stage = [&](int it, int s) {
        int k0 = it * 32;
        int q = tid & 3;
        int r0 = tid >> 2;        // 0..31
        #pragma unroll
        for (int t = 0; t < 12; t++) {
            int tile = t >> 2;    // 0:A 1:Whi 2:Wlo
            int row = (t & 3) * 32 + r0;
            const ushort_t* src;
            if (tile == 0)      src = Xf    + (size_t)(m0 + row) * DIM_ + k0 + q * 8;
            else if (tile == 1) src = g_whf + (size_t)(WOFF + n0 + row) * DIM_ + k0 + q * 8;
            else                src = g_wlf + (size_t)(WOFF + n0 + row) * DIM_ + k0 + q * 8;
            CP_ASYNC16(sb + s * GSTAGE_ + tile * GT_ + row * 80 + q * 16, src);
        }
        CP_COMMIT();
    };

    float c[4][8][4];
    #pragma unroll
    for (int i = 0; i < 4; i++)
        #pragma unroll
        for (int j = 0; j < 8; j++)
            #pragma unroll
            for (int p = 0; p < 4; p++) c[i][j][p] = 0.f;

    load_stage(0, 0);
    load_stage(1, 1);

    int slot = 2;
    for (int it = 0; it < 32; it++) {
        if (it + 2 < 32) load_stage(it + 2, slot);
        else             CP_COMMIT();          // keep group-count arithmetic
        if (++slot == 3) slot = 0;
        CP_WAIT(2);
        __syncthreads();

        uint32_t base = sb + (it % 3) * GSTAGE_;

        #pragma unroll
        for (int ks = 0; ks < 2; ks++) {
            int kb = ks * 16;
            uint32_t a[4][4];
            #pragma unroll
            for (int mf = 0; mf < 4; mf++)
                LDSM4(a[mf], base + (wm + mf * 16 + lrow) * 80 + (kb + lcol) * 2);
            #pragma unroll
            for (int nt = 0; nt < 4; nt++) {
                uint32_t bh[4], bl[4];
                uint32_t baddr = base + GT_ + (wn + nt * 16 + lrow) * 80 + (kb + lcol) * 2;
                LDSM4(bh, baddr);
                LDSM4(bl, baddr + GT_);
                #pragma unroll
                for (int mf = 0; mf < 4; mf++) {
                    MMA_F16(c[mf][nt*2],   a[mf], bh[0], bh[2]);
                    MMA_F16(c[mf][nt*2+1], a[mf], bh[1], bh[3]);
                }
                #pragma unroll
                for (int mf = 0; mf < 4; mf++) {
                    MMA_F16(c[mf][nt*2],   a[mf], bl[0], bl[2]);
                    MMA_F16(c[mf][nt*2+1], a[mf], bl[1], bl[3]);
                }
            }
        }
        __syncthreads();
    }

    #pragma unroll
    for (int mf = 0; mf < 4; mf++) {
        #pragma unroll
        for (int nf = 0; nf < 8; nf++) {
            int gr = m0 + wm + mf * 16 + (lane >> 2);
            int gc = n0 + wn + nf * 8 + (lane & 3) * 2;
            float2 v0 = make_float2(c[mf][nf][0] * WSCALE_INV, c[mf][nf][1] * WSCALE_INV);
            float2 v1 = make_float2(c[mf][nf][2] * WSCALE_INV, c[mf][nf][3] * WSCALE_INV);
            if (MODE == 2) {
                *(float2*)&outp[(size_t)gr * 1024 + gc] = v0;
                *(float2*)&outp[(size_t)(gr + 8) * 1024 + gc] = v1;
            } else {
                if (gc < 1024) {
                    *(float2*)&g_q[(size_t)gr * 1024 + gc] = v0;
                    *(float2*)&g_q[(size_t)(gr + 8) * 1024 + gc] = v1;
                } else if (gc < 1280) {
                    int kc = gc - 1024;
                    *(float2*)&g_k[(size_t)gr * 256 + kc] = v0;
                    *(float2*)&g_k[(size_t)(gr + 8) * 256 + kc] = v1;
                } else {
                    int vc = gc - 1280;
                    *(uint32_t*)&g_vf[(size_t)gr*256 + vc]     = pkhf(v0.x, v0.y);
                    *(uint32_t*)&g_vf[(size_t)(gr+8)*256 + vc] = pkhf(v1.x, v1.y);
                }
            }
        }
    }
}

// ---------------- RMSNorm + partial RoPE + gain -> fp16 ----------------
template<bool QSIDE>
__global__ void rms_rope_kernel(const float* __restrict__ gain) {
    const int NH = QSIDE ? H_ : KVH_;
    const float* buf = QSIDE ? g_q : g_k;
    int gw = blockIdx.x * (blockDim.x >> 5) + (threadIdx.x >> 5);
    int lane = threadIdx.x & 31;
    if (gw >= M_ * NH) return;
    int h = gw % NH, ms = gw / NH, s = ms % S_;
    const float* p = buf + (size_t)ms * (NH*HD_) + h * HD_;
    float v0 = p[lane], v1 = p[lane + 32];
    float ss = v0*v0 + v1*v1;
    #pragma unroll
    for (int o = 16; o; o >>= 1) ss += __shfl_xor_sync(0xffffffffu, ss, o);
    float r = rsqrtf(ss * (1.0f/64.0f) + 1.1920929e-7f);
    v0 *= r; v1 *= r;
    int i = lane & 15;
    float invf = exp2f(-0.83048202372184059f * (float)i);  // 10000^(-2i/32)
    float ang = (float)s * invf;
    float cc = cosf(ang), sn = sinf(ang);
    float other = __shfl_xor_sync(0xffffffffu, v0, 16);
    float nv0 = (lane < 16) ? (v0*cc + other*sn) : (-other*sn + v0*cc);
    float g = QSIDE ? (gain[h] * QSCALE_) : 1.0f;
    nv0 *= g; v1 *= g;
    size_t base = (size_t)ms * (NH*HD_) + h * HD_;
    ushort_t* dst = QSIDE ? g_qf : g_kf;
    dst[base + lane]      = __half_as_ushort(__float2half_rn(nv0));
    dst[base + lane + 32] = __half_as_ushort(__float2half_rn(v1));
}

// ---------------- tensor-core causal flash attention: 4 warps x 32q ----------------
#define FA_TILE  18432
#define FA_STG   (2*FA_TILE)
#define FA_SMEM  (2*FA_STG)    // 73728

__global__ void __launch_bounds__(128, 2)
flash_mma_kernel() {
    extern __shared__ char smem[];
    uint32_t sb = smem_u32(smem);

    int b = blockIdx.z, h = blockIdx.y;
    int q0 = (gridDim.x - 1 - blockIdx.x) * 128;
    int kvh = h >> 2;
    int tid = threadIdx.x;
    int wid = tid >> 5, lane = tid & 31;
    int r = lane >> 2, c2 = (lane & 3) * 2;
    int lrow = (lane & 7) + ((lane >> 3) & 1) * 8;
    int lcol = (lane >> 4) * 8;

    int wq = wid * 32;                      // warp q offset in tile
    int qmaxw = q0 + wq + 31;

    size_t tok[2][2];                       // [mf][row-half]
    #pragma unroll
    for (int mf = 0; mf < 2; mf++) {
        tok[mf][0] = (size_t)(b * S_) + q0 + wq + mf * 16 + r;
        tok[mf][1] = tok[mf][0] + 8;
    }

    // Q fragments: qf[mf][d-tile][4]
    uint32_t qf[2][4][4];
    #pragma unroll
    for (int mf = 0; mf < 2; mf++)
        #pragma unroll
        for (int t = 0; t < 4; t++) {
            size_t c0 = (size_t)h * 64 + t * 16 + c2;
            qf[mf][t][0] = *(const uint32_t*)&g_qf[tok[mf][0] * 1024 + c0];
            qf[mf][t][1] = *(const uint32_t*)&g_qf[tok[mf][1] * 1024 + c0];
            qf[mf][t][2] = *(const uint32_t*)&g_qf[tok[mf][0] * 1024 + c0 + 8];
            qf[mf][t][3] = *(const uint32_t*)&g_qf[tok[mf][1] * 1024 + c0 + 8];
        }

    float oc[2][8][4];
    #pragma unroll
    for (int mf = 0; mf < 2; mf++)
        #pragma unroll
        for (int j = 0; j < 8; j++)
            #pragma unroll
            for (int p = 0; p < 4; p++) oc[mf][j][p] = 0.f;
    float mrow[2][2] = {{-INFINITY,-INFINITY},{-INFINITY,-INFINITY}};
    float lrw[2][2]  = {{0.f,0.f},{0.f,0.f}};

    int q8 = tid & 7, rr = tid >> 3;   // loader: 8 col-chunks, 16 row-groups

    auto load_tile = [&](int j0, int s) {
        #pragma unroll
        for (int p = 0; p < 8; p++) {
            int row = p * 16 + rr;
            size_t gsrc = (size_t)(b * S_ + j0 + row) * 256 + kvh * 64 + q8 * 8;
            CP_ASYNC16(sb + s * FA_STG + row * 144 + q8 * 16, g_kf + gsrc);
            CP_ASYNC16(sb + s * FA_STG + FA_TILE + row * 144 + q8 * 16, g_vf + gsrc);
        }
        CP_COMMIT();
    };

    load_tile(0, 0);

    for (int j0 = 0; j0 <= q0; j0 += 128) {
        int buf = (j0 >> 7) & 1;
        if (j0 + 128 <= q0) { load_tile(j0 + 128, buf ^ 1); CP_WAIT(1); }
        else                { CP_WAIT(0); }
        __syncthreads();

        uint32_t kbank = sb + buf * FA_STG;
        uint32_t vbank = kbank + FA_TILE;

        #pragma unroll
        for (int half = 0; half < 2; half++) {
            int kg0 = j0 + half * 64;
            bool active = (kg0 <= qmaxw);
            int ks = half * 64;

            if (active) {
                float sc[2][8][4];
                #pragma unroll
                for (int mf = 0; mf < 2; mf++)
                    #pragma unroll
                    for (int j = 0; j < 8; j++)
                        #pragma unroll
                        for (int p = 0; p < 4; p++) sc[mf][j][p] = 0.f;

                // scores = Q.K^T (single fp16 product)
                #pragma unroll
                for (int nt = 0; nt < 4; nt++) {
                    #pragma unroll
                    for (int t = 0; t < 4; t++) {
                        uint32_t bk[4];
                        LDSM4(bk, kbank + (ks + nt * 16 + lrow) * 144 + (t * 16 + lcol) * 2);
                        #pragma unroll
                        for (int mf = 0; mf < 2; mf++) {
                            MMA_F16(sc[mf][nt*2],   qf[mf][t], bk[0], bk[2]);
                            MMA_F16(sc[mf][nt*2+1], qf[mf][t], bk[1], bk[3]);
                        }
                    }
                }

                // causal mask
                if (kg0 + 63 > q0 + wq) {
                    #pragma unroll
                    for (int mf = 0; mf < 2; mf++) {
                        int qg0 = q0 + wq + mf * 16 + r;
                        int qg1 = qg0 + 8;
                        #pragma unroll
                        for (int j = 0; j < 8; j++) {
                            int key = kg0 + 8 * j + c2;
                            if (key     > qg0) sc[mf][j][0] = -1e30f;
                            if (key + 1 > qg0) sc[mf][j][1] = -1e30f;
                            if (key     > qg1) sc[mf][j][2] = -1e30f;
                            if (key + 1 > qg1) sc[mf][j][3] = -1e30f;
                        }
                    }
                }

                // online softmax (base-2)
                #pragma unroll
                for (int mf = 0; mf < 2; mf++)
                    #pragma unroll
                    for (int rh = 0; rh < 2; rh++) {
                        float rm = sc[mf][0][rh*2];
                        #pragma unroll
                        for (int j = 0; j < 8; j++) {
                            rm = fmaxf(rm, sc[mf][j][rh*2]);
                            rm = fmaxf(rm, sc[mf][j][rh*2+1]);
                        }
                        rm = fmaxf(rm, __shfl_xor_sync(0xffffffffu, rm, 1));
                        rm = fmaxf(rm, __shfl_xor_sync(0xffffffffu, rm, 2));
                        float mn = fmaxf(mrow[mf][rh], rm);
                        float alpha = exp2_fast(mrow[mf][rh] - mn);
                        mrow[mf][rh] = mn;
                        float rs = 0.f;
                        #pragma unroll
                        for (int j = 0; j < 8; j++) {
                            sc[mf][j][rh*2]   = exp2_fast(sc[mf][j][rh*2]   - mn);
                            sc[mf][j][rh*2+1] = exp2_fast(sc[mf][j][rh*2+1] - mn);
                            rs += sc[mf][j][rh*2] + sc[mf][j][rh*2+1];
                        }
                        rs += __shfl_xor_sync(0xffffffffu, rs, 1);
                        rs += __shfl_xor_sync(0xffffffffu, rs, 2);
                        lrw[mf][rh] = lrw[mf][rh] * alpha + rs;
                        #pragma unroll
                        for (int j = 0; j < 8; j++) {
                            oc[mf][j][rh*2]   *= alpha;
                            oc[mf][j][rh*2+1] *= alpha;
                        }
                    }

                // O += P @ V : P split hi/lo fp16, V single fp16
                #pragma unroll
                for (int u = 0; u < 4; u++) {
                    uint32_t A_hi[2][4], A_lo[2][4];
                    #pragma unroll
                    for (int mf = 0; mf < 2; mf++)
                        #pragma unroll
                        for (int fr = 0; fr < 4; fr++) {
                            int cj = 2*u + (fr >> 1);
                            int po = (fr & 1) * 2;
                            float p0 = sc[mf][cj][po], p1 = sc[mf][cj][po+1];
                            uint32_t hp = pkhf(p0, p1);
                            __half2 h2 = *reinterpret_cast<__half2*>(&hp);
                            A_hi[mf][fr] = hp;
                            A_lo[mf][fr] = pkhf(p0 - __low2float(h2), p1 - __high2float(h2));
                        }
                    #pragma unroll
                    for (int dv = 0; dv < 4; dv++) {
                        uint32_t vv[4];
                        LDSM4T(vv, vbank + (ks + u * 16 + (lane & 15)) * 144
                                   + (dv * 16 + (lane >> 4) * 8) * 2);
                        #pragma unroll
                        for (int mf = 0; mf < 2; mf++) {
                            MMA_F16(oc[mf][dv*2],   A_hi[mf], vv[0], vv[1]);
                            MMA_F16(oc[mf][dv*2+1], A_hi[mf], vv[2], vv[3]);
                        }
                        #pragma unroll
                        for (int mf = 0; mf < 2; mf++) {
                            MMA_F16(oc[mf][dv*2],   A_lo[mf], vv[0], vv[1]);
                            MMA_F16(oc[mf][dv*2+1], A_lo[mf], vv[2], vv[3]);
                        }
                    }
                }
            }
        }
        __syncthreads();
    }

    // epilogue: y = O / l -> fp16
    #pragma unroll
    for (int mf = 0; mf < 2; mf++) {
        float inv0 = 1.0f / lrw[mf][0], inv1 = 1.0f / lrw[mf][1];
        #pragma unroll
        for (int j = 0; j < 8; j++) {
            size_t col = (size_t)h * 64 + 8 * j + c2;
            *(uint32_t*)&g_yf[tok[mf][0] * 1024 + col] = pkhf(oc[mf][j][0] * inv0, oc[mf][j][1] * inv0);
            *(uint32_t*)&g_yf[tok[mf][1] * 1024 + col] = pkhf(oc[mf][j][2] * inv1, oc[mf][j][3] * inv1);
        }
    }
}

// ---------------- launch ----------------
extern "C" void kernel_launch(void* const* d_in, const int* in_sizes, int n_in,
                              void* d_out, int out_size) {
    const float* x    = (const float*)d_in[0];
    const float* Wq   = (const float*)d_in[1];
    const float* Wk   = (const float*)d_in[2];
    const float* Wv   = (const float*)d_in[3];
    const float* Wp   = (const float*)d_in[4];
    const float* gain = (const float*)d_in[5];
    const float* Aq   = (const float*)d_in[6];
    const float* Bq   = (const float*)d_in[7];
    const float* Av   = (const float*)d_in[8];
    const float* Bv   = (const float*)d_in[9];
    const int*   step = (const int*)d_in[10];
    float* out = (float*)d_out;

    ushort_t* xf;
    cudaGetSymbolAddress((void**)&xf, g_xf);

    prep_w_kernel<<<(WROWS_*256 + 255)/256, 256>>>(Wq, Wk, Wv, Wp, Aq, Bq, Av, Bv, step);
    prep_xf_kernel<<<(M_*DIM_/4 + 255)/256, 256>>>(x, xf, M_*DIM_/4);

    cudaFuncSetAttribute(gemm_mma_kernel<0>, cudaFuncAttributeMaxDynamicSharedMemorySize, G_SMEM);
    cudaFuncSetAttribute(gemm_mma_kernel<2>, cudaFuncAttributeMaxDynamicSharedMemorySize, G_SMEM);
    cudaFuncSetAttribute(flash_mma_kernel,   cudaFuncAttributeMaxDynamicSharedMemorySize, FA_SMEM);

    gemm_mma_kernel<0><<<dim3(1536/128, M_/128), 128, G_SMEM>>>(nullptr);

    rms_rope_kernel<true ><<<(M_*H_)  / 8, 256>>>(gain);
    rms_rope_kernel<false><<<(M_*KVH_)/ 8, 256>>>(nullptr);

    flash_mma_kernel<<<dim3(S_/128, H_, B_), 128, FA_SMEM>>>();

    gemm_mma_kernel<2><<<dim3(1024/128, M_/128), 128, G_SMEM>>>(out);
}

// round 9
// speedup vs baseline: 6.9080x; 1.2850x over previous
#include <cuda_runtime.h>
#include <cuda_fp16.h>
#include <math.h>
#include <stdint.h>

#define B_      2
#define S_      2048
#define DIM_    1024
#define H_      16
#define KVH_    4
#define HD_     64
#define KVDIM_  256
#define R_      4
#define NSTEPS_ 2
#define M_      (B_*S_)
#define WROWS_  2560   // [0,1024): Wq+lora | [1024,1280): Wk | [1280,1536): Wv+lora | [1536,2560): Wp

#define QSCALE_ (0.125f * 1.4426950408889634f)

typedef unsigned short ushort_t;

__device__ __forceinline__ uint32_t smem_u32(const void* p) {
    uint32_t a;
    asm("{ .reg .u64 t; cvta.to.shared.u64 t, %1; cvt.u32.u64 %0, t; }" : "=r"(a) : "l"(p));
    return a;
}

#define LDSM4(r, addr) \
    asm volatile("ldmatrix.sync.aligned.m8n8.x4.shared.b16 {%0,%1,%2,%3}, [%4];" \
        : "=r"((r)[0]),"=r"((r)[1]),"=r"((r)[2]),"=r"((r)[3]) : "r"(addr))
#define LDSM4T(r, addr) \
    asm volatile("ldmatrix.sync.aligned.m8n8.x4.trans.shared.b16 {%0,%1,%2,%3}, [%4];" \
        : "=r"((r)[0]),"=r"((r)[1]),"=r"((r)[2]),"=r"((r)[3]) : "r"(addr))

#define MMA_F16(c, a, b0v, b1v) \
    asm volatile("mma.sync.aligned.m16n8k16.row.col.f32.f16.f16.f32 " \
        "{%0,%1,%2,%3}, {%4,%5,%6,%7}, {%8,%9}, {%0,%1,%2,%3};" \
        : "+f"((c)[0]),"+f"((c)[1]),"+f"((c)[2]),"+f"((c)[3]) \
        : "r"((a)[0]),"r"((a)[1]),"r"((a)[2]),"r"((a)[3]), "r"(b0v),"r"(b1v))

#define CP_ASYNC16(dst, src) \
    asm volatile("cp.async.cg.shared.global [%0], [%1], 16;" :: "r"(dst), "l"(src) : "memory")
#define CP_COMMIT() asm volatile("cp.async.commit_group;" ::: "memory")
#define CP_WAIT(n)  asm volatile("cp.async.wait_group %0;" :: "n"(n) : "memory")

__device__ __forceinline__ uint32_t pkhf(float lo, float hi) {
    uint32_t r; asm("cvt.rn.f16x2.f32 %0, %1, %2;" : "=r"(r) : "f"(hi), "f"(lo)); return r;
}

__device__ __forceinline__ float exp2_fast(float y) {
    y = fmaxf(y, -80.f);
    float fl = floorf(y);
    float t = y - fl;
    float p = 1.5403530e-4f;
    p = fmaf(p, t, 1.3333558e-3f);
    p = fmaf(p, t, 9.6181291e-3f);
    p = fmaf(p, t, 5.5504109e-2f);
    p = fmaf(p, t, 2.4022651e-1f);
    p = fmaf(p, t, 6.9314718e-1f);
    p = fmaf(p, t, 1.0f);
    return __int_as_float(((int)fl + 127) << 23) * p;
}

// ---------------- scratch ----------------
__device__ float    g_q[M_*DIM_];
__device__ float    g_k[M_*KVDIM_];
__device__ ushort_t g_xf[M_*DIM_];
__device__ ushort_t g_yf[M_*DIM_];
__device__ ushort_t g_whf[WROWS_*DIM_];
__device__ ushort_t g_qf[M_*DIM_];
__device__ ushort_t g_kf[M_*KVDIM_];
__device__ ushort_t g_vf[M_*KVDIM_];

// ---------------- prep: x -> fp16 ----------------
__global__ void prep_xf_kernel(const float* __restrict__ src,
                               ushort_t* __restrict__ dst, int n4) {
    int t = blockIdx.x * blockDim.x + threadIdx.x;
    if (t >= n4) return;
    float4 v = ((const float4*)src)[t];
    uint2 o;
    o.x = pkhf(v.x, v.y);
    o.y = pkhf(v.z, v.w);
    ((uint2*)dst)[t] = o;
}

// ---------------- prep: fold LoRA, pack, fp16 ----------------
__global__ void prep_w_kernel(const float* __restrict__ Wq, const float* __restrict__ Wk,
                              const float* __restrict__ Wv, const float* __restrict__ Wp,
                              const float* __restrict__ Aq, const float* __restrict__ Bq,
                              const float* __restrict__ Av, const float* __restrict__ Bv,
                              const int*   __restrict__ stepp) {
    int t = blockIdx.x * blockDim.x + threadIdx.x;
    if (t >= WROWS_ * 256) return;
    int row = t >> 8, k4 = t & 255;
    int step = *stepp;
    bool ok = (step >= 0 && step < NSTEPS_);
    float4 w;
    if (row < 1024) {
        w = ((const float4*)(Wq + (size_t)row * DIM_))[k4];
        if (ok) {
            const float* Ab = Aq + (size_t)step * R_ * DIM_;
            const float* Bb = Bq + ((size_t)step * DIM_ + row) * R_;
            #pragma unroll
            for (int r = 0; r < R_; r++) {
                float b = Bb[r];
                float4 a = ((const float4*)(Ab + (size_t)r * DIM_))[k4];
                w.x += b*a.x; w.y += b*a.y; w.z += b*a.z; w.w += b*a.w;
            }
        }
    } else if (row < 1280) {
        w = ((const float4*)(Wk + (size_t)(row - 1024) * DIM_))[k4];
    } else if (row < 1536) {
        int vr = row - 1280;
        w = ((const float4*)(Wv + (size_t)vr * DIM_))[k4];
        if (ok) {
            const float* Ab = Av + (size_t)step * R_ * DIM_;
            const float* Bb = Bv + ((size_t)step * KVDIM_ + vr) * R_;
            #pragma unroll
            for (int r = 0; r < R_; r++) {
                float b = Bb[r];
                float4 a = ((const float4*)(Ab + (size_t)r * DIM_))[k4];
                w.x += b*a.x; w.y += b*a.y; w.z += b*a.z; w.w += b*a.w;
            }
        }
    } else {
        w = ((const float4*)(Wp + (size_t)(row - 1536) * DIM_))[k4];
    }
    uint2 hp;
    hp.x = pkhf(w.x, w.y);
    hp.y = pkhf(w.z, w.w);
    ((uint2*)g_whf)[t] = hp;
}

// ---------------- fp16 single-product GEMM: 128x128 CTA, 4 warps 64x64, 4 stages ----------------
#define GT_      10240            // 128 rows x 80B
#define GSTAGE_  (2*GT_)          // A, W
#define G_SMEM   (4*GSTAGE_)      // 81920

// MODE 0: merged QKV (N=1536, Woff=0) | MODE 2: proj (N=1024, Woff=1536, A=g_yf)
template<int MODE>
__global__ void __launch_bounds__(128, 2)
gemm_mma_kernel(float* __restrict__ outp) {
    extern __shared__ char smem[];
    uint32_t sb = smem_u32(smem);
    constexpr int WOFF = (MODE == 0) ? 0 : 1536;
    const ushort_t* Xf = (MODE == 2) ? g_yf : g_xf;

    int m0 = blockIdx.y * 128, n0 = blockIdx.x * 128;
    int tid = threadIdx.x;
    int wid = tid >> 5, lane = tid & 31;
    int wm = (wid >> 1) * 64, wn = (wid & 1) * 64;
    int lrow = (lane & 7) + ((lane >> 3) & 1) * 8;
    int lcol = (lane >> 4) * 8;

    auto load_stage = [&](int it, int s) {
        int k0 = it * 32;
        int q = tid & 3;
        int r0 = tid >> 2;        // 0..31
        #pragma unroll
        for (int t = 0; t < 8; t++) {
            int tile = t >> 2;    // 0:A 1:W
            int row = (t & 3) * 32 + r0;
            const ushort_t* src;
            if (tile == 0) src = Xf    + (size_t)(m0 + row) * DIM_ + k0 + q * 8;
            else           src = g_whf + (size_t)(WOFF + n0 + row) * DIM_ + k0 + q * 8;
            CP_ASYNC16(sb + s * GSTAGE_ + tile * GT_ + row * 80 + q * 16, src);
        }
        CP_COMMIT();
    };

    float c[4][8][4];
    #pragma unroll
    for (int i = 0; i < 4; i++)
        #pragma unroll
        for (int j = 0; j < 8; j++)
            #pragma unroll
            for (int p = 0; p < 4; p++) c[i][j][p] = 0.f;

    load_stage(0, 0);
    load_stage(1, 1);
    load_stage(2, 2);

    for (int it = 0; it < 32; it++) {
        if (it + 3 < 32) { load_stage(it + 3, (it + 3) & 3); CP_WAIT(3); }
        else             { CP_WAIT(0); }
        __syncthreads();

        uint32_t base = sb + (it & 3) * GSTAGE_;

        #pragma unroll
        for (int ks = 0; ks < 2; ks++) {
            int kb = ks * 16;
            uint32_t a[4][4];
            #pragma unroll
            for (int mf = 0; mf < 4; mf++)
                LDSM4(a[mf], base + (wm + mf * 16 + lrow) * 80 + (kb + lcol) * 2);
            #pragma unroll
            for (int nt = 0; nt < 4; nt++) {
                uint32_t bh[4];
                LDSM4(bh, base + GT_ + (wn + nt * 16 + lrow) * 80 + (kb + lcol) * 2);
                #pragma unroll
                for (int mf = 0; mf < 4; mf++) {
                    MMA_F16(c[mf][nt*2],   a[mf], bh[0], bh[2]);
                    MMA_F16(c[mf][nt*2+1], a[mf], bh[1], bh[3]);
                }
            }
        }
        __syncthreads();
    }

    #pragma unroll
    for (int mf = 0; mf < 4; mf++) {
        #pragma unroll
        for (int nf = 0; nf < 8; nf++) {
            int gr = m0 + wm + mf * 16 + (lane >> 2);
            int gc = n0 + wn + nf * 8 + (lane & 3) * 2;
            float2 v0 = make_float2(c[mf][nf][0], c[mf][nf][1]);
            float2 v1 = make_float2(c[mf][nf][2], c[mf][nf][3]);
            if (MODE == 2) {
                *(float2*)&outp[(size_t)gr * 1024 + gc] = v0;
                *(float2*)&outp[(size_t)(gr + 8) * 1024 + gc] = v1;
            } else {
                if (gc < 1024) {
                    *(float2*)&g_q[(size_t)gr * 1024 + gc] = v0;
                    *(float2*)&g_q[(size_t)(gr + 8) * 1024 + gc] = v1;
                } else if (gc < 1280) {
                    int kc = gc - 1024;
                    *(float2*)&g_k[(size_t)gr * 256 + kc] = v0;
                    *(float2*)&g_k[(size_t)(gr + 8) * 256 + kc] = v1;
                } else {
                    int vc = gc - 1280;
                    *(uint32_t*)&g_vf[(size_t)gr*256 + vc]     = pkhf(v0.x, v0.y);
                    *(uint32_t*)&g_vf[(size_t)(gr+8)*256 + vc] = pkhf(v1.x, v1.y);
                }
            }
        }
    }
}

// ---------------- RMSNorm + partial RoPE + gain -> fp16 ----------------
template<bool QSIDE>
__global__ void rms_rope_kernel(const float* __restrict__ gain) {
    const int NH = QSIDE ? H_ : KVH_;
    const float* buf = QSIDE ? g_q : g_k;
    int gw = blockIdx.x * (blockDim.x >> 5) + (threadIdx.x >> 5);
    int lane = threadIdx.x & 31;
    if (gw >= M_ * NH) return;
    int h = gw % NH, ms = gw / NH, s = ms % S_;
    const float* p = buf + (size_t)ms * (NH*HD_) + h * HD_;
    float v0 = p[lane], v1 = p[lane + 32];
    float ss = v0*v0 + v1*v1;
    #pragma unroll
    for (int o = 16; o; o >>= 1) ss += __shfl_xor_sync(0xffffffffu, ss, o);
    float r = rsqrtf(ss * (1.0f/64.0f) + 1.1920929e-7f);
    v0 *= r; v1 *= r;
    int i = lane & 15;
    float invf = exp2f(-0.83048202372184059f * (float)i);  // 10000^(-2i/32)
    float ang = (float)s * invf;
    float cc = cosf(ang), sn = sinf(ang);
    float other = __shfl_xor_sync(0xffffffffu, v0, 16);
    float nv0 = (lane < 16) ? (v0*cc + other*sn) : (-other*sn + v0*cc);
    float g = QSIDE ? (gain[h] * QSCALE_) : 1.0f;
    nv0 *= g; v1 *= g;
    size_t base = (size_t)ms * (NH*HD_) + h * HD_;
    ushort_t* dst = QSIDE ? g_qf : g_kf;
    dst[base + lane]      = __half_as_ushort(__float2half_rn(nv0));
    dst[base + lane + 32] = __half_as_ushort(__float2half_rn(v1));
}

// ---------------- tensor-core causal flash attention: 4 warps x 32q ----------------
#define FA_TILE  18432
#define FA_STG   (2*FA_TILE)
#define FA_SMEM  (2*FA_STG)    // 73728

__global__ void __launch_bounds__(128, 2)
flash_mma_kernel() {
    extern __shared__ char smem[];
    uint32_t sb = smem_u32(smem);

    int b = blockIdx.z, h = blockIdx.y;
    int q0 = (gridDim.x - 1 - blockIdx.x) * 128;
    int kvh = h >> 2;
    int tid = threadIdx.x;
    int wid = tid >> 5, lane = tid & 31;
    int r = lane >> 2, c2 = (lane & 3) * 2;
    int lrow = (lane & 7) + ((lane >> 3) & 1) * 8;
    int lcol = (lane >> 4) * 8;

    int wq = wid * 32;
    int qmaxw = q0 + wq + 31;

    size_t tok[2][2];
    #pragma unroll
    for (int mf = 0; mf < 2; mf++) {
        tok[mf][0] = (size_t)(b * S_) + q0 + wq + mf * 16 + r;
        tok[mf][1] = tok[mf][0] + 8;
    }

    uint32_t qf[2][4][4];
    #pragma unroll
    for (int mf = 0; mf < 2; mf++)
        #pragma unroll
        for (int t = 0; t < 4; t++) {
            size_t c0 = (size_t)h * 64 + t * 16 + c2;
            qf[mf][t][0] = *(const uint32_t*)&g_qf[tok[mf][0] * 1024 + c0];
            qf[mf][t][1] = *(const uint32_t*)&g_qf[tok[mf][1] * 1024 + c0];
            qf[mf][t][2] = *(const uint32_t*)&g_qf[tok[mf][0] * 1024 + c0 + 8];
            qf[mf][t][3] = *(const uint32_t*)&g_qf[tok[mf][1] * 1024 + c0 + 8];
        }

    float oc[2][8][4];
    #pragma unroll
    for (int mf = 0; mf < 2; mf++)
        #pragma unroll
        for (int j = 0; j < 8; j++)
            #pragma unroll
            for (int p = 0; p < 4; p++) oc[mf][j][p] = 0.f;
    float mrow[2][2] = {{-INFINITY,-INFINITY},{-INFINITY,-INFINITY}};
    float lrw[2][2]  = {{0.f,0.f},{0.f,0.f}};

    int q8 = tid & 7, rr = tid >> 3;

    auto load_tile = [&](int j0, int s) {
        #pragma unroll
        for (int p = 0; p < 8; p++) {
            int row = p * 16 + rr;
            size_t gsrc = (size_t)(b * S_ + j0 + row) * 256 + kvh * 64 + q8 * 8;
            CP_ASYNC16(sb + s * FA_STG + row * 144 + q8 * 16, g_kf + gsrc);
            CP_ASYNC16(sb + s * FA_STG + FA_TILE + row * 144 + q8 * 16, g_vf + gsrc);
        }
        CP_COMMIT();
    };

    load_tile(0, 0);

    for (int j0 = 0; j0 <= q0; j0 += 128) {
        int buf = (j0 >> 7) & 1;
        if (j0 + 128 <= q0) { load_tile(j0 + 128, buf ^ 1); CP_WAIT(1); }
        else                { CP_WAIT(0); }
        __syncthreads();

        uint32_t kbank = sb + buf * FA_STG;
        uint32_t vbank = kbank + FA_TILE;

        #pragma unroll
        for (int half = 0; half < 2; half++) {
            int kg0 = j0 + half * 64;
            bool active = (kg0 <= qmaxw);
            int ks = half * 64;

            if (active) {
                float sc[2][8][4];
                #pragma unroll
                for (int mf = 0; mf < 2; mf++)
                    #pragma unroll
                    for (int j = 0; j < 8; j++)
                        #pragma unroll
                        for (int p = 0; p < 4; p++) sc[mf][j][p] = 0.f;

                // scores = Q.K^T
                #pragma unroll
                for (int nt = 0; nt < 4; nt++) {
                    #pragma unroll
                    for (int t = 0; t < 4; t++) {
                        uint32_t bk[4];
                        LDSM4(bk, kbank + (ks + nt * 16 + lrow) * 144 + (t * 16 + lcol) * 2);
                        #pragma unroll
                        for (int mf = 0; mf < 2; mf++) {
                            MMA_F16(sc[mf][nt*2],   qf[mf][t], bk[0], bk[2]);
                            MMA_F16(sc[mf][nt*2+1], qf[mf][t], bk[1], bk[3]);
                        }
                    }
                }

                // causal mask
                if (kg0 + 63 > q0 + wq) {
                    #pragma unroll
                    for (int mf = 0; mf < 2; mf++) {
                        int qg0 = q0 + wq + mf * 16 + r;
                        int qg1 = qg0 + 8;
                        #pragma unroll
                        for (int j = 0; j < 8; j++) {
                            int key = kg0 + 8 * j + c2;
                            if (key     > qg0) sc[mf][j][0] = -1e30f;
                            if (key + 1 > qg0) sc[mf][j][1] = -1e30f;
                            if (key     > qg1) sc[mf][j][2] = -1e30f;
                            if (key + 1 > qg1) sc[mf][j][3] = -1e30f;
                        }
                    }
                }

                // online softmax (base-2)
                #pragma unroll
                for (int mf = 0; mf < 2; mf++)
                    #pragma unroll
                    for (int rh = 0; rh < 2; rh++) {
                        float rm = sc[mf][0][rh*2];
                        #pragma unroll
                        for (int j = 0; j < 8; j++) {
                            rm = fmaxf(rm, sc[mf][j][rh*2]);
                            rm = fmaxf(rm, sc[mf][j][rh*2+1]);
                        }
                        rm = fmaxf(rm, __shfl_xor_sync(0xffffffffu, rm, 1));
                        rm = fmaxf(rm, __shfl_xor_sync(0xffffffffu, rm, 2));
                        float mn = fmaxf(mrow[mf][rh], rm);
                        float alpha = exp2_fast(mrow[mf][rh] - mn);
                        mrow[mf][rh] = mn;
                        float rs = 0.f;
                        #pragma unroll
                        for (int j = 0; j < 8; j++) {
                            sc[mf][j][rh*2]   = exp2_fast(sc[mf][j][rh*2]   - mn);
                            sc[mf][j][rh*2+1] = exp2_fast(sc[mf][j][rh*2+1] - mn);
                            rs += sc[mf][j][rh*2] + sc[mf][j][rh*2+1];
                        }
                        rs += __shfl_xor_sync(0xffffffffu, rs, 1);
                        rs += __shfl_xor_sync(0xffffffffu, rs, 2);
                        lrw[mf][rh] = lrw[mf][rh] * alpha + rs;
                        #pragma unroll
                        for (int j = 0; j < 8; j++) {
                            oc[mf][j][rh*2]   *= alpha;
                            oc[mf][j][rh*2+1] *= alpha;
                        }
                    }

                // O += P @ V : single fp16 product
                #pragma unroll
                for (int u = 0; u < 4; u++) {
                    uint32_t A_hi[2][4];
                    #pragma unroll
                    for (int mf = 0; mf < 2; mf++)
                        #pragma unroll
                        for (int fr = 0; fr < 4; fr++) {
                            int cj = 2*u + (fr >> 1);
                            int po = (fr & 1) * 2;
                            A_hi[mf][fr] = pkhf(sc[mf][cj][po], sc[mf][cj][po+1]);
                        }
                    #pragma unroll
                    for (int dv = 0; dv < 4; dv++) {
                        uint32_t vv[4];
                        LDSM4T(vv, vbank + (ks + u * 16 + (lane & 15)) * 144
                                   + (dv * 16 + (lane >> 4) * 8) * 2);
                        #pragma unroll
                        for (int mf = 0; mf < 2; mf++) {
                            MMA_F16(oc[mf][dv*2],   A_hi[mf], vv[0], vv[1]);
                            MMA_F16(oc[mf][dv*2+1], A_hi[mf], vv[2], vv[3]);
                        }
                    }
                }
            }
        }
        __syncthreads();
    }

    // epilogue: y = O / l -> fp16
    #pragma unroll
    for (int mf = 0; mf < 2; mf++) {
        float inv0 = 1.0f / lrw[mf][0], inv1 = 1.0f / lrw[mf][1];
        #pragma unroll
        for (int j = 0; j < 8; j++) {
            size_t col = (size_t)h * 64 + 8 * j + c2;
            *(uint32_t*)&g_yf[tok[mf][0] * 1024 + col] = pkhf(oc[mf][j][0] * inv0, oc[mf][j][1] * inv0);
            *(uint32_t*)&g_yf[tok[mf][1] * 1024 + col] = pkhf(oc[mf][j][2] * inv1, oc[mf][j][3] * inv1);
        }
    }
}

// ---------------- launch ----------------
extern "C" void kernel_launch(void* const* d_in, const int* in_sizes, int n_in,
                              void* d_out, int out_size) {
    const float* x    = (const float*)d_in[0];
    const float* Wq   = (const float*)d_in[1];
    const float* Wk   = (const float*)d_in[2];
    const float* Wv   = (const float*)d_in[3];
    const float* Wp   = (const float*)d_in[4];
    const float* gain = (const float*)d_in[5];
    const float* Aq   = (const float*)d_in[6];
    const float* Bq   = (const float*)d_in[7];
    const float* Av   = (const float*)d_in[8];
    const float* Bv   = (const float*)d_in[9];
    const int*   step = (const int*)d_in[10];
    float* out = (float*)d_out;

    ushort_t* xf;
    cudaGetSymbolAddress((void**)&xf, g_xf);

    prep_w_kernel<<<(WROWS_*256 + 255)/256, 256>>>(Wq, Wk, Wv, Wp, Aq, Bq, Av, Bv, step);
    prep_xf_kernel<<<(M_*DIM_/4 + 255)/256, 256>>>(x, xf, M_*DIM_/4);

    cudaFuncSetAttribute(gemm_mma_kernel<0>, cudaFuncAttributeMaxDynamicSharedMemorySize, G_SMEM);
    cudaFuncSetAttribute(gemm_mma_kernel<2>, cudaFuncAttributeMaxDynamicSharedMemorySize, G_SMEM);
    cudaFuncSetAttribute(flash_mma_kernel,   cudaFuncAttributeMaxDynamicSharedMemorySize, FA_SMEM);

    gemm_mma_kernel<0><<<dim3(1536/128, M_/128), 128, G_SMEM>>>(nullptr);

    rms_rope_kernel<true ><<<(M_*H_)  / 8, 256>>>(gain);
    rms_rope_kernel<false><<<(M_*KVH_)/ 8, 256>>>(nullptr);

    flash_mma_kernel<<<dim3(S_/128, H_, B_), 128, FA_SMEM>>>();

    gemm_mma_kernel<2><<<dim3(1024/128, M_/128), 128, G_SMEM>>>(out);
}

// round 10
// speedup vs baseline: 8.3416x; 1.2075x over previous
#include <cuda_runtime.h>
#include <cuda_fp16.h>
#include <math.h>
#include <stdint.h>

#define B_      2
#define S_      2048
#define DIM_    1024
#define H_      16
#define KVH_    4
#define HD_     64
#define KVDIM_  256
#define R_      4
#define NSTEPS_ 2
#define M_      (B_*S_)
#define WROWS_  2560   // [0,1024): Wq+lora | [1024,1280): Wk | [1280,1536): Wv+lora | [1536,2560): Wp

#define QSCALE_ (0.125f * 1.4426950408889634f)

typedef unsigned short ushort_t;
typedef unsigned long long ull;

__device__ __forceinline__ uint32_t smem_u32(const void* p) {
    uint32_t a;
    asm("{ .reg .u64 t; cvta.to.shared.u64 t, %1; cvt.u32.u64 %0, t; }" : "=r"(a) : "l"(p));
    return a;
}

#define LDSM4(r, addr) \
    asm volatile("ldmatrix.sync.aligned.m8n8.x4.shared.b16 {%0,%1,%2,%3}, [%4];" \
        : "=r"((r)[0]),"=r"((r)[1]),"=r"((r)[2]),"=r"((r)[3]) : "r"(addr))
#define LDSM4T(r, addr) \
    asm volatile("ldmatrix.sync.aligned.m8n8.x4.trans.shared.b16 {%0,%1,%2,%3}, [%4];" \
        : "=r"((r)[0]),"=r"((r)[1]),"=r"((r)[2]),"=r"((r)[3]) : "r"(addr))

#define MMA_F16(c, a, b0v, b1v) \
    asm volatile("mma.sync.aligned.m16n8k16.row.col.f32.f16.f16.f32 " \
        "{%0,%1,%2,%3}, {%4,%5,%6,%7}, {%8,%9}, {%0,%1,%2,%3};" \
        : "+f"((c)[0]),"+f"((c)[1]),"+f"((c)[2]),"+f"((c)[3]) \
        : "r"((a)[0]),"r"((a)[1]),"r"((a)[2]),"r"((a)[3]), "r"(b0v),"r"(b1v))

#define CP_ASYNC16(dst, src) \
    asm volatile("cp.async.cg.shared.global [%0], [%1], 16;" :: "r"(dst), "l"(src) : "memory")
#define CP_COMMIT() asm volatile("cp.async.commit_group;" ::: "memory")
#define CP_WAIT(n)  asm volatile("cp.async.wait_group %0;" :: "n"(n) : "memory")

__device__ __forceinline__ uint32_t pkhf(float lo, float hi) {
    uint32_t r; asm("cvt.rn.f16x2.f32 %0, %1, %2;" : "=r"(r) : "f"(hi), "f"(lo)); return r;
}

// ---- packed f32x2 helpers ----
__device__ __forceinline__ ull pk2(float x, float y) {
    ull r; asm("mov.b64 %0, {%1, %2};" : "=l"(r) : "f"(x), "f"(y)); return r;
}
__device__ __forceinline__ ull pk2u(uint32_t x, uint32_t y) {
    ull r; asm("mov.b64 %0, {%1, %2};" : "=l"(r) : "r"(x), "r"(y)); return r;
}
__device__ __forceinline__ void up2(float& x, float& y, ull v) {
    asm("mov.b64 {%0, %1}, %2;" : "=f"(x), "=f"(y) : "l"(v));
}
__device__ __forceinline__ void up2u(uint32_t& x, uint32_t& y, ull v) {
    asm("mov.b64 {%0, %1}, %2;" : "=r"(x), "=r"(y) : "l"(v));
}
__device__ __forceinline__ ull add2_(ull a, ull b) {
    ull d; asm("add.rn.f32x2 %0, %1, %2;" : "=l"(d) : "l"(a), "l"(b)); return d;
}
__device__ __forceinline__ ull mul2_(ull a, ull b) {
    ull d; asm("mul.rn.f32x2 %0, %1, %2;" : "=l"(d) : "l"(a), "l"(b)); return d;
}
__device__ __forceinline__ ull fma2_(ull a, ull b, ull c) {
    ull d; asm("fma.rn.f32x2 %0, %1, %2, %3;" : "=l"(d) : "l"(a), "l"(b), "l"(c)); return d;
}

// scalar exp2 (used only for alpha; input bounded in [-62, 0])
__device__ __forceinline__ float exp2_fast(float y) {
    float fl = floorf(y);
    float t = y - fl;
    float p = 1.5403530e-4f;
    p = fmaf(p, t, 1.3333558e-3f);
    p = fmaf(p, t, 9.6181291e-3f);
    p = fmaf(p, t, 5.5504109e-2f);
    p = fmaf(p, t, 2.4022651e-1f);
    p = fmaf(p, t, 6.9314718e-1f);
    p = fmaf(p, t, 1.0f);
    return __int_as_float(((int)fl + 127) << 23) * p;
}

// ---------------- scratch ----------------
__device__ ushort_t g_xf[M_*DIM_];
__device__ ushort_t g_yf[M_*DIM_];
__device__ ushort_t g_whf[WROWS_*DIM_];
__device__ ushort_t g_qf[M_*DIM_];
__device__ ushort_t g_kf[M_*KVDIM_];
__device__ ushort_t g_vf[M_*KVDIM_];
__device__ float    g_rope[S_*16*2];   // [s][i] -> (cos, sin)

// ---------------- prep: x -> fp16 ----------------
__global__ void prep_xf_kernel(const float* __restrict__ src,
                               ushort_t* __restrict__ dst, int n4) {
    int t = blockIdx.x * blockDim.x + threadIdx.x;
    if (t >= n4) return;
    float4 v = ((const float4*)src)[t];
    uint2 o;
    o.x = pkhf(v.x, v.y);
    o.y = pkhf(v.z, v.w);
    ((uint2*)dst)[t] = o;
}

// ---------------- prep: rope cos/sin table ----------------
__global__ void prep_rope_kernel() {
    int t = blockIdx.x * blockDim.x + threadIdx.x;
    if (t >= S_ * 16) return;
    int s = t >> 4, i = t & 15;
    float invf = exp2f(-0.83048202372184059f * (float)i);  // 10000^(-2i/32)
    float ang = (float)s * invf;
    g_rope[t * 2]     = cosf(ang);
    g_rope[t * 2 + 1] = sinf(ang);
}

// ---------------- prep: fold LoRA, pack, fp16 ----------------
__global__ void prep_w_kernel(const float* __restrict__ Wq, const float* __restrict__ Wk,
                              const float* __restrict__ Wv, const float* __restrict__ Wp,
                              const float* __restrict__ Aq, const float* __restrict__ Bq,
                              const float* __restrict__ Av, const float* __restrict__ Bv,
                              const int*   __restrict__ stepp) {
    int t = blockIdx.x * blockDim.x + threadIdx.x;
    if (t >= WROWS_ * 256) return;
    int row = t >> 8, k4 = t & 255;
    int step = *stepp;
    bool ok = (step >= 0 && step < NSTEPS_);
    float4 w;
    if (row < 1024) {
        w = ((const float4*)(Wq + (size_t)row * DIM_))[k4];
        if (ok) {
            const float* Ab = Aq + (size_t)step * R_ * DIM_;
            const float* Bb = Bq + ((size_t)step * DIM_ + row) * R_;
            #pragma unroll
            for (int r = 0; r < R_; r++) {
                float b = Bb[r];
                float4 a = ((const float4*)(Ab + (size_t)r * DIM_))[k4];
                w.x += b*a.x; w.y += b*a.y; w.z += b*a.z; w.w += b*a.w;
            }
        }
    } else if (row < 1280) {
        w = ((const float4*)(Wk + (size_t)(row - 1024) * DIM_))[k4];
    } else if (row < 1536) {
        int vr = row - 1280;
        w = ((const float4*)(Wv + (size_t)vr * DIM_))[k4];
        if (ok) {
            const float* Ab = Av + (size_t)step * R_ * DIM_;
            const float* Bb = Bv + ((size_t)step * KVDIM_ + vr) * R_;
            #pragma unroll
            for (int r = 0; r < R_; r++) {
                float b = Bb[r];
                float4 a = ((const float4*)(Ab + (size_t)r * DIM_))[k4];
                w.x += b*a.x; w.y += b*a.y; w.z += b*a.z; w.w += b*a.w;
            }
        }
    } else {
        w = ((const float4*)(Wp + (size_t)(row - 1536) * DIM_))[k4];
    }
    uint2 hp;
    hp.x = pkhf(w.x, w.y);
    hp.y = pkhf(w.z, w.w);
    ((uint2*)g_whf)[t] = hp;
}

// ---------------- fp16 GEMM with fused RMS+RoPE epilogue ----------------
#define GT_      10240            // 128 rows x 80B
#define GSTAGE_  (2*GT_)
#define G_SMEM   (4*GSTAGE_)      // 81920

// MODE 0: merged QKV (N=1536) with fused rms/rope epilogue | MODE 2: proj (A=g_yf, fp32 out)
template<int MODE>
__global__ void __launch_bounds__(128, 2)
gemm_mma_kernel(const float* __restrict__ gainp, float* __restrict__ outp) {
    extern __shared__ char smem[];
    uint32_t sb = smem_u32(smem);
    constexpr int WOFF = (MODE == 0) ? 0 : 1536;
    const ushort_t* Xf = (MODE == 2) ? g_yf : g_xf;

    int m0 = blockIdx.y * 128, n0 = blockIdx.x * 128;
    int tid = threadIdx.x;
    int wid = tid >> 5, lane = tid & 31;
    int wm = (wid >> 1) * 64, wn = (wid & 1) * 64;
    int lrow = (lane & 7) + ((lane >> 3) & 1) * 8;
    int lcol = (lane >> 4) * 8;

    auto load_stage = [&](int it, int s) {
        int k0 = it * 32;
        int q = tid & 3;
        int r0 = tid >> 2;
        #pragma unroll
        for (int t = 0; t < 8; t++) {
            int tile = t >> 2;
            int row = (t & 3) * 32 + r0;
            const ushort_t* src;
            if (tile == 0) src = Xf    + (size_t)(m0 + row) * DIM_ + k0 + q * 8;
            else           src = g_whf + (size_t)(WOFF + n0 + row) * DIM_ + k0 + q * 8;
            CP_ASYNC16(sb + s * GSTAGE_ + tile * GT_ + row * 80 + q * 16, src);
        }
        CP_COMMIT();
    };

    float c[4][8][4];
    #pragma unroll
    for (int i = 0; i < 4; i++)
        #pragma unroll
        for (int j = 0; j < 8; j++)
            #pragma unroll
            for (int p = 0; p < 4; p++) c[i][j][p] = 0.f;

    load_stage(0, 0);
    load_stage(1, 1);
    load_stage(2, 2);

    for (int it = 0; it < 32; it++) {
        if (it + 3 < 32) { load_stage(it + 3, (it + 3) & 3); CP_WAIT(3); }
        else             { CP_WAIT(0); }
        __syncthreads();

        uint32_t base = sb + (it & 3) * GSTAGE_;

        #pragma unroll
        for (int ks = 0; ks < 2; ks++) {
            int kb = ks * 16;
            uint32_t a[4][4];
            #pragma unroll
            for (int mf = 0; mf < 4; mf++)
                LDSM4(a[mf], base + (wm + mf * 16 + lrow) * 80 + (kb + lcol) * 2);
            #pragma unroll
            for (int nt = 0; nt < 4; nt++) {
                uint32_t bh[4];
                LDSM4(bh, base + GT_ + (wn + nt * 16 + lrow) * 80 + (kb + lcol) * 2);
                #pragma unroll
                for (int mf = 0; mf < 4; mf++) {
                    MMA_F16(c[mf][nt*2],   a[mf], bh[0], bh[2]);
                    MMA_F16(c[mf][nt*2+1], a[mf], bh[1], bh[3]);
                }
            }
        }
        __syncthreads();
    }

    if (MODE == 2) {
        #pragma unroll
        for (int mf = 0; mf < 4; mf++) {
            #pragma unroll
            for (int nf = 0; nf < 8; nf++) {
                int gr = m0 + wm + mf * 16 + (lane >> 2);
                int gc = n0 + wn + nf * 8 + (lane & 3) * 2;
                *(float2*)&outp[(size_t)gr * 1024 + gc]       = make_float2(c[mf][nf][0], c[mf][nf][1]);
                *(float2*)&outp[(size_t)(gr + 8) * 1024 + gc] = make_float2(c[mf][nf][2], c[mf][nf][3]);
            }
        }
        return;
    }

    // ---- MODE 0 epilogue ----
    int nglob = n0 + wn;                 // warp-constant, multiple of 64
    if (nglob >= 1280) {
        // V rows: straight fp16
        #pragma unroll
        for (int mf = 0; mf < 4; mf++) {
            #pragma unroll
            for (int nf = 0; nf < 8; nf++) {
                int gr = m0 + wm + mf * 16 + (lane >> 2);
                int vc = nglob - 1280 + nf * 8 + (lane & 3) * 2;
                *(uint32_t*)&g_vf[(size_t)gr * 256 + vc]       = pkhf(c[mf][nf][0], c[mf][nf][1]);
                *(uint32_t*)&g_vf[(size_t)(gr + 8) * 256 + vc] = pkhf(c[mf][nf][2], c[mf][nf][3]);
            }
        }
        return;
    }

    // Q or K head: fused RMSNorm + partial RoPE + gain -> fp16
    bool isQ = (nglob < 1024);
    float gsc = isQ ? (gainp[nglob >> 6] * QSCALE_) : 1.0f;
    int q2 = (lane & 3) * 2;

    #pragma unroll
    for (int mf = 0; mf < 4; mf++) {
        #pragma unroll
        for (int rr = 0; rr < 2; rr++) {
            float v[8][2];
            #pragma unroll
            for (int nf = 0; nf < 8; nf++) {
                v[nf][0] = c[mf][nf][rr * 2];
                v[nf][1] = c[mf][nf][rr * 2 + 1];
            }
            float ss = 0.f;
            #pragma unroll
            for (int nf = 0; nf < 8; nf++)
                ss += v[nf][0] * v[nf][0] + v[nf][1] * v[nf][1];
            ss += __shfl_xor_sync(0xffffffffu, ss, 1);
            ss += __shfl_xor_sync(0xffffffffu, ss, 2);
            float scl = rsqrtf(ss * (1.0f / 64.0f) + 1.1920929e-7f) * gsc;
            #pragma unroll
            for (int nf = 0; nf < 8; nf++) { v[nf][0] *= scl; v[nf][1] *= scl; }

            int m = m0 + wm + mf * 16 + (lane >> 2) + rr * 8;
            int s = m & (S_ - 1);
            float4 r0 = *(const float4*)&g_rope[(s * 16 + q2) * 2];
            float4 r1 = *(const float4*)&g_rope[(s * 16 + 8 + q2) * 2];
            // rope: cols (nf=0)<->(nf=2), (nf=1)<->(nf=3)
            float x1, x2;
            x1 = v[0][0]; x2 = v[2][0];
            v[0][0] = x1 * r0.x + x2 * r0.y;  v[2][0] = -x1 * r0.y + x2 * r0.x;
            x1 = v[0][1]; x2 = v[2][1];
            v[0][1] = x1 * r0.z + x2 * r0.w;  v[2][1] = -x1 * r0.w + x2 * r0.z;
            x1 = v[1][0]; x2 = v[3][0];
            v[1][0] = x1 * r1.x + x2 * r1.y;  v[3][0] = -x1 * r1.y + x2 * r1.x;
            x1 = v[1][1]; x2 = v[3][1];
            v[1][1] = x1 * r1.z + x2 * r1.w;  v[3][1] = -x1 * r1.w + x2 * r1.z;

            if (isQ) {
                size_t bix = (size_t)m * 1024 + nglob + q2;
                #pragma unroll
                for (int nf = 0; nf < 8; nf++)
                    *(uint32_t*)&g_qf[bix + nf * 8] = pkhf(v[nf][0], v[nf][1]);
            } else {
                size_t bix = (size_t)m * 256 + (nglob - 1024) + q2;
                #pragma unroll
                for (int nf = 0; nf < 8; nf++)
                    *(uint32_t*)&g_kf[bix + nf * 8] = pkhf(v[nf][0], v[nf][1]);
            }
        }
    }
}

// ---------------- tensor-core causal flash attention: 4 warps x 32q ----------------
#define FA_TILE  18432
#define FA_STG   (2*FA_TILE)
#define FA_SMEM  (2*FA_STG)    // 73728
#define MASKV_   (-50.0f)

__global__ void __launch_bounds__(128, 2)
flash_mma_kernel() {
    extern __shared__ char smem[];
    uint32_t sb = smem_u32(smem);

    int b = blockIdx.z, h = blockIdx.y;
    int q0 = (gridDim.x - 1 - blockIdx.x) * 128;
    int kvh = h >> 2;
    int tid = threadIdx.x;
    int wid = tid >> 5, lane = tid & 31;
    int r = lane >> 2, c2 = (lane & 3) * 2;
    int lrow = (lane & 7) + ((lane >> 3) & 1) * 8;
    int lcol = (lane >> 4) * 8;

    int wq = wid * 32;
    int qmaxw = q0 + wq + 31;

    size_t tok[2][2];
    #pragma unroll
    for (int mf = 0; mf < 2; mf++) {
        tok[mf][0] = (size_t)(b * S_) + q0 + wq + mf * 16 + r;
        tok[mf][1] = tok[mf][0] + 8;
    }

    uint32_t qf[2][4][4];
    #pragma unroll
    for (int mf = 0; mf < 2; mf++)
        #pragma unroll
        for (int t = 0; t < 4; t++) {
            size_t c0 = (size_t)h * 64 + t * 16 + c2;
            qf[mf][t][0] = *(const uint32_t*)&g_qf[tok[mf][0] * 1024 + c0];
            qf[mf][t][1] = *(const uint32_t*)&g_qf[tok[mf][1] * 1024 + c0];
            qf[mf][t][2] = *(const uint32_t*)&g_qf[tok[mf][0] * 1024 + c0 + 8];
            qf[mf][t][3] = *(const uint32_t*)&g_qf[tok[mf][1] * 1024 + c0 + 8];
        }

    float oc[2][8][4];
    #pragma unroll
    for (int mf = 0; mf < 2; mf++)
        #pragma unroll
        for (int j = 0; j < 8; j++)
            #pragma unroll
            for (int p = 0; p < 4; p++) oc[mf][j][p] = 0.f;
    float mrow[2][2] = {{MASKV_, MASKV_}, {MASKV_, MASKV_}};
    float lrw[2][2]  = {{0.f, 0.f}, {0.f, 0.f}};

    // packed exp2 constants
    const ull MAGIC2  = pk2(12582912.f, 12582912.f);
    const ull NMAGIC2 = pk2(-12582912.f, -12582912.f);
    const ull NONE2   = pk2(-1.f, -1.f);
    const ull ONE2    = pk2(1.f, 1.f);
    const ull EC1 = pk2(0.69314718f,  0.69314718f);
    const ull EC2 = pk2(0.24022651f,  0.24022651f);
    const ull EC3 = pk2(0.055504109f, 0.055504109f);
    const ull EC4 = pk2(0.0096181291f, 0.0096181291f);

    auto exp2pair = [&](float y0, float y1, float& e0, float& e1) {
        ull y = pk2(y0, y1);
        ull t = add2_(y, MAGIC2);
        ull rr_ = add2_(t, NMAGIC2);
        ull f = fma2_(rr_, NONE2, y);       // f = y - round(y), in [-0.5, 0.5]
        ull p = fma2_(EC4, f, EC3);
        p = fma2_(p, f, EC2);
        p = fma2_(p, f, EC1);
        p = fma2_(p, f, ONE2);
        uint32_t tl, th; up2u(tl, th, t);
        ull es = pk2u((tl << 23) + 0x3F800000u, (th << 23) + 0x3F800000u);
        ull res = mul2_(p, es);
        up2(e0, e1, res);
    };

    int q8 = tid & 7, rr = tid >> 3;

    auto load_tile = [&](int j0, int s) {
        #pragma unroll
        for (int p = 0; p < 8; p++) {
            int row = p * 16 + rr;
            size_t gsrc = (size_t)(b * S_ + j0 + row) * 256 + kvh * 64 + q8 * 8;
            CP_ASYNC16(sb + s * FA_STG + row * 144 + q8 * 16, g_kf + gsrc);
            CP_ASYNC16(sb + s * FA_STG + FA_TILE + row * 144 + q8 * 16, g_vf + gsrc);
        }
        CP_COMMIT();
    };

    load_tile(0, 0);

    for (int j0 = 0; j0 <= q0; j0 += 128) {
        int buf = (j0 >> 7) & 1;
        if (j0 + 128 <= q0) { load_tile(j0 + 128, buf ^ 1); CP_WAIT(1); }
        else                { CP_WAIT(0); }
        __syncthreads();

        uint32_t kbank = sb + buf * FA_STG;
        uint32_t vbank = kbank + FA_TILE;

        #pragma unroll
        for (int half = 0; half < 2; half++) {
            int kg0 = j0 + half * 64;
            bool active = (kg0 <= qmaxw);
            int ks = half * 64;

            if (active) {
                float sc[2][8][4];
                #pragma unroll
                for (int mf = 0; mf < 2; mf++)
                    #pragma unroll
                    for (int j = 0; j < 8; j++)
                        #pragma unroll
                        for (int p = 0; p < 4; p++) sc[mf][j][p] = 0.f;

                #pragma unroll
                for (int nt = 0; nt < 4; nt++) {
                    #pragma unroll
                    for (int t = 0; t < 4; t++) {
                        uint32_t bk[4];
                        LDSM4(bk, kbank + (ks + nt * 16 + lrow) * 144 + (t * 16 + lcol) * 2);
                        #pragma unroll
                        for (int mf = 0; mf < 2; mf++) {
                            MMA_F16(sc[mf][nt*2],   qf[mf][t], bk[0], bk[2]);
                            MMA_F16(sc[mf][nt*2+1], qf[mf][t], bk[1], bk[3]);
                        }
                    }
                }

                if (kg0 + 63 > q0 + wq) {
                    #pragma unroll
                    for (int mf = 0; mf < 2; mf++) {
                        int qg0 = q0 + wq + mf * 16 + r;
                        int qg1 = qg0 + 8;
                        #pragma unroll
                        for (int j = 0; j < 8; j++) {
                            int key = kg0 + 8 * j + c2;
                            if (key     > qg0) sc[mf][j][0] = MASKV_;
                            if (key + 1 > qg0) sc[mf][j][1] = MASKV_;
                            if (key     > qg1) sc[mf][j][2] = MASKV_;
                            if (key + 1 > qg1) sc[mf][j][3] = MASKV_;
                        }
                    }
                }

                #pragma unroll
                for (int mf = 0; mf < 2; mf++)
                    #pragma unroll
                    for (int rh = 0; rh < 2; rh++) {
                        float rm = sc[mf][0][rh*2];
                        #pragma unroll
                        for (int j = 0; j < 8; j++) {
                            rm = fmaxf(rm, sc[mf][j][rh*2]);
                            rm = fmaxf(rm, sc[mf][j][rh*2+1]);
                        }
                        rm = fmaxf(rm, __shfl_xor_sync(0xffffffffu, rm, 1));
                        rm = fmaxf(rm, __shfl_xor_sync(0xffffffffu, rm, 2));
                        float mn = fmaxf(mrow[mf][rh], rm);
                        float alpha = exp2_fast(mrow[mf][rh] - mn);
                        mrow[mf][rh] = mn;
                        float rs = 0.f;
                        #pragma unroll
                        for (int j = 0; j < 8; j++) {
                            float e0, e1;
                            exp2pair(sc[mf][j][rh*2] - mn, sc[mf][j][rh*2+1] - mn, e0, e1);
                            sc[mf][j][rh*2]   = e0;
                            sc[mf][j][rh*2+1] = e1;
                            rs += e0 + e1;
                        }
                        rs += __shfl_xor_sync(0xffffffffu, rs, 1);
                        rs += __shfl_xor_sync(0xffffffffu, rs, 2);
                        lrw[mf][rh] = lrw[mf][rh] * alpha + rs;
                        #pragma unroll
                        for (int j = 0; j < 8; j++) {
                            oc[mf][j][rh*2]   *= alpha;
                            oc[mf][j][rh*2+1] *= alpha;
                        }
                    }

                // O += P @ V
                #pragma unroll
                for (int u = 0; u < 4; u++) {
                    uint32_t A_hi[2][4];
                    #pragma unroll
                    for (int mf = 0; mf < 2; mf++)
                        #pragma unroll
                        for (int fr = 0; fr < 4; fr++) {
                            int cj = 2*u + (fr >> 1);
                            int po = (fr & 1) * 2;
                            A_hi[mf][fr] = pkhf(sc[mf][cj][po], sc[mf][cj][po+1]);
                        }
                    #pragma unroll
                    for (int dv = 0; dv < 4; dv++) {
                        uint32_t vv[4];
                        LDSM4T(vv, vbank + (ks + u * 16 + (lane & 15)) * 144
                                   + (dv * 16 + (lane >> 4) * 8) * 2);
                        #pragma unroll
                        for (int mf = 0; mf < 2; mf++) {
                            MMA_F16(oc[mf][dv*2],   A_hi[mf], vv[0], vv[1]);
                            MMA_F16(oc[mf][dv*2+1], A_hi[mf], vv[2], vv[3]);
                        }
                    }
                }
            }
        }
        __syncthreads();
    }

    #pragma unroll
    for (int mf = 0; mf < 2; mf++) {
        float inv0 = 1.0f / lrw[mf][0], inv1 = 1.0f / lrw[mf][1];
        #pragma unroll
        for (int j = 0; j < 8; j++) {
            size_t col = (size_t)h * 64 + 8 * j + c2;
            *(uint32_t*)&g_yf[tok[mf][0] * 1024 + col] = pkhf(oc[mf][j][0] * inv0, oc[mf][j][1] * inv0);
            *(uint32_t*)&g_yf[tok[mf][1] * 1024 + col] = pkhf(oc[mf][j][2] * inv1, oc[mf][j][3] * inv1);
        }
    }
}

// ---------------- launch ----------------
extern "C" void kernel_launch(void* const* d_in, const int* in_sizes, int n_in,
                              void* d_out, int out_size) {
    const float* x    = (const float*)d_in[0];
    const float* Wq   = (const float*)d_in[1];
    const float* Wk   = (const float*)d_in[2];
    const float* Wv   = (const float*)d_in[3];
    const float* Wp   = (const float*)d_in[4];
    const float* gain = (const float*)d_in[5];
    const float* Aq   = (const float*)d_in[6];
    const float* Bq   = (const float*)d_in[7];
    const float* Av   = (const float*)d_in[8];
    const float* Bv   = (const float*)d_in[9];
    const int*   step = (const int*)d_in[10];
    float* out = (float*)d_out;

    ushort_t* xf;
    cudaGetSymbolAddress((void**)&xf, g_xf);

    prep_w_kernel<<<(WROWS_*256 + 255)/256, 256>>>(Wq, Wk, Wv, Wp, Aq, Bq, Av, Bv, step);
    prep_xf_kernel<<<(M_*DIM_/4 + 255)/256, 256>>>(x, xf, M_*DIM_/4);
    prep_rope_kernel<<<(S_*16 + 255)/256, 256>>>();

    cudaFuncSetAttribute(gemm_mma_kernel<0>, cudaFuncAttributeMaxDynamicSharedMemorySize, G_SMEM);
    cudaFuncSetAttribute(gemm_mma_kernel<2>, cudaFuncAttributeMaxDynamicSharedMemorySize, G_SMEM);
    cudaFuncSetAttribute(flash_mma_kernel,   cudaFuncAttributeMaxDynamicSharedMemorySize, FA_SMEM);

    gemm_mma_kernel<0><<<dim3(1536/128, M_/128), 128, G_SMEM>>>(gain, nullptr);

    flash_mma_kernel<<<dim3(S_/128, H_, B_), 128, FA_SMEM>>>();

    gemm_mma_kernel<2><<<dim3(1024/128, M_/128), 128, G_SMEM>>>(gain, out);
}

// round 11
// speedup vs baseline: 8.7650x; 1.0508x over previous
#include <cuda_runtime.h>
#include <cuda_fp16.h>
#include <math.h>
#include <stdint.h>

#define B_      2
#define S_      2048
#define DIM_    1024
#define H_      16
#define KVH_    4
#define HD_     64
#define KVDIM_  256
#define R_      4
#define NSTEPS_ 2
#define M_      (B_*S_)
#define WROWS_  2560   // [0,1024): Wq+lora | [1024,1280): Wk | [1280,1536): Wv+lora | [1536,2560): Wp

#define QSCALE_ (0.125f * 1.4426950408889634f)

typedef unsigned short ushort_t;
typedef unsigned long long ull;

__device__ __forceinline__ uint32_t smem_u32(const void* p) {
    uint32_t a;
    asm("{ .reg .u64 t; cvta.to.shared.u64 t, %1; cvt.u32.u64 %0, t; }" : "=r"(a) : "l"(p));
    return a;
}

#define LDSM4(r, addr) \
    asm volatile("ldmatrix.sync.aligned.m8n8.x4.shared.b16 {%0,%1,%2,%3}, [%4];" \
        : "=r"((r)[0]),"=r"((r)[1]),"=r"((r)[2]),"=r"((r)[3]) : "r"(addr))
#define LDSM4T(r, addr) \
    asm volatile("ldmatrix.sync.aligned.m8n8.x4.trans.shared.b16 {%0,%1,%2,%3}, [%4];" \
        : "=r"((r)[0]),"=r"((r)[1]),"=r"((r)[2]),"=r"((r)[3]) : "r"(addr))

#define MMA_F16(c, a, b0v, b1v) \
    asm volatile("mma.sync.aligned.m16n8k16.row.col.f32.f16.f16.f32 " \
        "{%0,%1,%2,%3}, {%4,%5,%6,%7}, {%8,%9}, {%0,%1,%2,%3};" \
        : "+f"((c)[0]),"+f"((c)[1]),"+f"((c)[2]),"+f"((c)[3]) \
        : "r"((a)[0]),"r"((a)[1]),"r"((a)[2]),"r"((a)[3]), "r"(b0v),"r"(b1v))

#define CP_ASYNC16(dst, src) \
    asm volatile("cp.async.cg.shared.global [%0], [%1], 16;" :: "r"(dst), "l"(src) : "memory")
#define CP_COMMIT() asm volatile("cp.async.commit_group;" ::: "memory")
#define CP_WAIT(n)  asm volatile("cp.async.wait_group %0;" :: "n"(n) : "memory")

__device__ __forceinline__ uint32_t pkhf(float lo, float hi) {
    uint32_t r; asm("cvt.rn.f16x2.f32 %0, %1, %2;" : "=r"(r) : "f"(hi), "f"(lo)); return r;
}

// ---- packed f32x2 helpers ----
__device__ __forceinline__ ull pk2(float x, float y) {
    ull r; asm("mov.b64 %0, {%1, %2};" : "=l"(r) : "f"(x), "f"(y)); return r;
}
__device__ __forceinline__ ull pk2u(uint32_t x, uint32_t y) {
    ull r; asm("mov.b64 %0, {%1, %2};" : "=l"(r) : "r"(x), "r"(y)); return r;
}
__device__ __forceinline__ void up2(float& x, float& y, ull v) {
    asm("mov.b64 {%0, %1}, %2;" : "=f"(x), "=f"(y) : "l"(v));
}
__device__ __forceinline__ void up2u(uint32_t& x, uint32_t& y, ull v) {
    asm("mov.b64 {%0, %1}, %2;" : "=r"(x), "=r"(y) : "l"(v));
}
__device__ __forceinline__ ull add2_(ull a, ull b) {
    ull d; asm("add.rn.f32x2 %0, %1, %2;" : "=l"(d) : "l"(a), "l"(b)); return d;
}
__device__ __forceinline__ ull mul2_(ull a, ull b) {
    ull d; asm("mul.rn.f32x2 %0, %1, %2;" : "=l"(d) : "l"(a), "l"(b)); return d;
}
__device__ __forceinline__ ull fma2_(ull a, ull b, ull c) {
    ull d; asm("fma.rn.f32x2 %0, %1, %2, %3;" : "=l"(d) : "l"(a), "l"(b), "l"(c)); return d;
}

// scalar exp2 (alpha only; input bounded)
__device__ __forceinline__ float exp2_fast(float y) {
    float fl = floorf(y);
    float t = y - fl;
    float p = 1.5403530e-4f;
    p = fmaf(p, t, 1.3333558e-3f);
    p = fmaf(p, t, 9.6181291e-3f);
    p = fmaf(p, t, 5.5504109e-2f);
    p = fmaf(p, t, 2.4022651e-1f);
    p = fmaf(p, t, 6.9314718e-1f);
    p = fmaf(p, t, 1.0f);
    return __int_as_float(((int)fl + 127) << 23) * p;
}

// ---------------- scratch ----------------
__device__ ushort_t g_xf[M_*DIM_];
__device__ ushort_t g_yf[M_*DIM_];
__device__ ushort_t g_whf[WROWS_*DIM_];
__device__ ushort_t g_qf[M_*DIM_];
__device__ ushort_t g_kf[M_*KVDIM_];
__device__ ushort_t g_vf[M_*KVDIM_];
__device__ float    g_rope[S_*16*2];   // [s][i] -> (cos, sin)

// ---------------- fused prep: W-fold+pack | x->fp16 | rope table ----------------
#define NBW_ ((WROWS_*256)/256)       // 2560 blocks
#define NBX_ ((M_*DIM_/4)/256)        // 4096 blocks
#define NBR_ ((S_*16+255)/256)        // 128 blocks
__global__ void prep_all_kernel(const float* __restrict__ x,
                                const float* __restrict__ Wq, const float* __restrict__ Wk,
                                const float* __restrict__ Wv, const float* __restrict__ Wp,
                                const float* __restrict__ Aq, const float* __restrict__ Bq,
                                const float* __restrict__ Av, const float* __restrict__ Bv,
                                const int*   __restrict__ stepp) {
    int blk = blockIdx.x;
    if (blk < NBW_) {
        int t = blk * 256 + threadIdx.x;
        int row = t >> 8, k4 = t & 255;
        int step = *stepp;
        bool ok = (step >= 0 && step < NSTEPS_);
        float4 w;
        if (row < 1024) {
            w = ((const float4*)(Wq + (size_t)row * DIM_))[k4];
            if (ok) {
                const float* Ab = Aq + (size_t)step * R_ * DIM_;
                const float* Bb = Bq + ((size_t)step * DIM_ + row) * R_;
                #pragma unroll
                for (int r = 0; r < R_; r++) {
                    float b = Bb[r];
                    float4 a = ((const float4*)(Ab + (size_t)r * DIM_))[k4];
                    w.x += b*a.x; w.y += b*a.y; w.z += b*a.z; w.w += b*a.w;
                }
            }
        } else if (row < 1280) {
            w = ((const float4*)(Wk + (size_t)(row - 1024) * DIM_))[k4];
        } else if (row < 1536) {
            int vr = row - 1280;
            w = ((const float4*)(Wv + (size_t)vr * DIM_))[k4];
            if (ok) {
                const float* Ab = Av + (size_t)step * R_ * DIM_;
                const float* Bb = Bv + ((size_t)step * KVDIM_ + vr) * R_;
                #pragma unroll
                for (int r = 0; r < R_; r++) {
                    float b = Bb[r];
                    float4 a = ((const float4*)(Ab + (size_t)r * DIM_))[k4];
                    w.x += b*a.x; w.y += b*a.y; w.z += b*a.z; w.w += b*a.w;
                }
            }
        } else {
            w = ((const float4*)(Wp + (size_t)(row - 1536) * DIM_))[k4];
        }
        uint2 hp;
        hp.x = pkhf(w.x, w.y);
        hp.y = pkhf(w.z, w.w);
        ((uint2*)g_whf)[t] = hp;
    } else if (blk < NBW_ + NBX_) {
        int t = (blk - NBW_) * 256 + threadIdx.x;
        float4 v = ((const float4*)x)[t];
        uint2 o;
        o.x = pkhf(v.x, v.y);
        o.y = pkhf(v.z, v.w);
        ((uint2*)g_xf)[t] = o;
    } else {
        int t = (blk - NBW_ - NBX_) * 256 + threadIdx.x;
        if (t < S_ * 16) {
            int s = t >> 4, i = t & 15;
            float invf = exp2f(-0.83048202372184059f * (float)i);
            float ang = (float)s * invf;
            g_rope[t * 2]     = cosf(ang);
            g_rope[t * 2 + 1] = sinf(ang);
        }
    }
}

// ---------------- fp16 GEMM, single-barrier pipeline, fused RMS+RoPE epilogue ----------------
#define GT_      10240            // 128 rows x 80B
#define GSTAGE_  (2*GT_)
#define G_SMEM   (4*GSTAGE_)      // 81920

// MODE 0: merged QKV (N=1536) | MODE 2: proj (A=g_yf, fp32 out)
template<int MODE>
__global__ void __launch_bounds__(128, 2)
gemm_mma_kernel(const float* __restrict__ gainp, float* __restrict__ outp) {
    extern __shared__ char smem[];
    uint32_t sb = smem_u32(smem);
    constexpr int WOFF = (MODE == 0) ? 0 : 1536;
    const ushort_t* Xf = (MODE == 2) ? g_yf : g_xf;

    int m0 = blockIdx.y * 128, n0 = blockIdx.x * 128;
    int tid = threadIdx.x;
    int wid = tid >> 5, lane = tid & 31;
    int wm = (wid >> 1) * 64, wn = (wid & 1) * 64;
    int lrow = (lane & 7) + ((lane >> 3) & 1) * 8;
    int lcol = (lane >> 4) * 8;

    auto load_stage = [&](int it, int s) {
        int k0 = it * 32;
        int q = tid & 3;
        int r0 = tid >> 2;
        #pragma unroll
        for (int t = 0; t < 8; t++) {
            int tile = t >> 2;
            int row = (t & 3) * 32 + r0;
            const ushort_t* src;
            if (tile == 0) src = Xf    + (size_t)(m0 + row) * DIM_ + k0 + q * 8;
            else           src = g_whf + (size_t)(WOFF + n0 + row) * DIM_ + k0 + q * 8;
            CP_ASYNC16(sb + s * GSTAGE_ + tile * GT_ + row * 80 + q * 16, src);
        }
        CP_COMMIT();
    };

    float c[4][8][4];
    #pragma unroll
    for (int i = 0; i < 4; i++)
        #pragma unroll
        for (int j = 0; j < 8; j++)
            #pragma unroll
            for (int p = 0; p < 4; p++) c[i][j][p] = 0.f;

    load_stage(0, 0);
    load_stage(1, 1);
    load_stage(2, 2);

    for (int it = 0; it < 32; it++) {
        // wait for stage `it`, THEN sync, THEN prefetch (slot provably free), then compute
        if (it < 30)      CP_WAIT(2);
        else if (it == 30) CP_WAIT(1);
        else               CP_WAIT(0);
        __syncthreads();
        if (it + 3 < 32) load_stage(it + 3, (it + 3) & 3);

        uint32_t base = sb + (it & 3) * GSTAGE_;

        #pragma unroll
        for (int ks = 0; ks < 2; ks++) {
            int kb = ks * 16;
            uint32_t a[4][4];
            #pragma unroll
            for (int mf = 0; mf < 4; mf++)
                LDSM4(a[mf], base + (wm + mf * 16 + lrow) * 80 + (kb + lcol) * 2);
            #pragma unroll
            for (int nt = 0; nt < 4; nt++) {
                uint32_t bh[4];
                LDSM4(bh, base + GT_ + (wn + nt * 16 + lrow) * 80 + (kb + lcol) * 2);
                #pragma unroll
                for (int mf = 0; mf < 4; mf++) {
                    MMA_F16(c[mf][nt*2],   a[mf], bh[0], bh[2]);
                    MMA_F16(c[mf][nt*2+1], a[mf], bh[1], bh[3]);
                }
            }
        }
    }

    if (MODE == 2) {
        #pragma unroll
        for (int mf = 0; mf < 4; mf++) {
            #pragma unroll
            for (int nf = 0; nf < 8; nf++) {
                int gr = m0 + wm + mf * 16 + (lane >> 2);
                int gc = n0 + wn + nf * 8 + (lane & 3) * 2;
                *(float2*)&outp[(size_t)gr * 1024 + gc]       = make_float2(c[mf][nf][0], c[mf][nf][1]);
                *(float2*)&outp[(size_t)(gr + 8) * 1024 + gc] = make_float2(c[mf][nf][2], c[mf][nf][3]);
            }
        }
        return;
    }

    // ---- MODE 0 epilogue ----
    int nglob = n0 + wn;
    if (nglob >= 1280) {
        #pragma unroll
        for (int mf = 0; mf < 4; mf++) {
            #pragma unroll
            for (int nf = 0; nf < 8; nf++) {
                int gr = m0 + wm + mf * 16 + (lane >> 2);
                int vc = nglob - 1280 + nf * 8 + (lane & 3) * 2;
                *(uint32_t*)&g_vf[(size_t)gr * 256 + vc]       = pkhf(c[mf][nf][0], c[mf][nf][1]);
                *(uint32_t*)&g_vf[(size_t)(gr + 8) * 256 + vc] = pkhf(c[mf][nf][2], c[mf][nf][3]);
            }
        }
        return;
    }

    bool isQ = (nglob < 1024);
    float gsc = isQ ? (gainp[nglob >> 6] * QSCALE_) : 1.0f;
    int q2 = (lane & 3) * 2;

    #pragma unroll
    for (int mf = 0; mf < 4; mf++) {
        #pragma unroll
        for (int rr = 0; rr < 2; rr++) {
            float v[8][2];
            #pragma unroll
            for (int nf = 0; nf < 8; nf++) {
                v[nf][0] = c[mf][nf][rr * 2];
                v[nf][1] = c[mf][nf][rr * 2 + 1];
            }
            float ss = 0.f;
            #pragma unroll
            for (int nf = 0; nf < 8; nf++)
                ss += v[nf][0] * v[nf][0] + v[nf][1] * v[nf][1];
            ss += __shfl_xor_sync(0xffffffffu, ss, 1);
            ss += __shfl_xor_sync(0xffffffffu, ss, 2);
            float scl = rsqrtf(ss * (1.0f / 64.0f) + 1.1920929e-7f) * gsc;
            #pragma unroll
            for (int nf = 0; nf < 8; nf++) { v[nf][0] *= scl; v[nf][1] *= scl; }

            int m = m0 + wm + mf * 16 + (lane >> 2) + rr * 8;
            int s = m & (S_ - 1);
            float4 r0 = *(const float4*)&g_rope[(s * 16 + q2) * 2];
            float4 r1 = *(const float4*)&g_rope[(s * 16 + 8 + q2) * 2];
            float x1, x2;
            x1 = v[0][0]; x2 = v[2][0];
            v[0][0] = x1 * r0.x + x2 * r0.y;  v[2][0] = -x1 * r0.y + x2 * r0.x;
            x1 = v[0][1]; x2 = v[2][1];
            v[0][1] = x1 * r0.z + x2 * r0.w;  v[2][1] = -x1 * r0.w + x2 * r0.z;
            x1 = v[1][0]; x2 = v[3][0];
            v[1][0] = x1 * r1.x + x2 * r1.y;  v[3][0] = -x1 * r1.y + x2 * r1.x;
            x1 = v[1][1]; x2 = v[3][1];
            v[1][1] = x1 * r1.z + x2 * r1.w;  v[3][1] = -x1 * r1.w + x2 * r1.z;

            if (isQ) {
                size_t bix = (size_t)m * 1024 + nglob + q2;
                #pragma unroll
                for (int nf = 0; nf < 8; nf++)
                    *(uint32_t*)&g_qf[bix + nf * 8] = pkhf(v[nf][0], v[nf][1]);
            } else {
                size_t bix = (size_t)m * 256 + (nglob - 1024) + q2;
                #pragma unroll
                for (int nf = 0; nf < 8; nf++)
                    *(uint32_t*)&g_kf[bix + nf * 8] = pkhf(v[nf][0], v[nf][1]);
            }
        }
    }
}

// ---------------- tensor-core causal flash attention: 4 warps x 32q ----------------
#define FA_TILE  18432
#define FA_STG   (2*FA_TILE)
#define FA_SMEM  (2*FA_STG)    // 73728
#define MASKV_   (-50.0f)

__global__ void __launch_bounds__(128, 2)
flash_mma_kernel() {
    extern __shared__ char smem[];
    uint32_t sb = smem_u32(smem);

    int b = blockIdx.z, h = blockIdx.y;
    int q0 = (gridDim.x - 1 - blockIdx.x) * 128;
    int kvh = h >> 2;
    int tid = threadIdx.x;
    int wid = tid >> 5, lane = tid & 31;
    int r = lane >> 2, c2 = (lane & 3) * 2;
    int lrow = (lane & 7) + ((lane >> 3) & 1) * 8;
    int lcol = (lane >> 4) * 8;

    int wq = wid * 32;
    int qmaxw = q0 + wq + 31;

    size_t tok[2][2];
    #pragma unroll
    for (int mf = 0; mf < 2; mf++) {
        tok[mf][0] = (size_t)(b * S_) + q0 + wq + mf * 16 + r;
        tok[mf][1] = tok[mf][0] + 8;
    }

    uint32_t qf[2][4][4];
    #pragma unroll
    for (int mf = 0; mf < 2; mf++)
        #pragma unroll
        for (int t = 0; t < 4; t++) {
            size_t c0 = (size_t)h * 64 + t * 16 + c2;
            qf[mf][t][0] = *(const uint32_t*)&g_qf[tok[mf][0] * 1024 + c0];
            qf[mf][t][1] = *(const uint32_t*)&g_qf[tok[mf][1] * 1024 + c0];
            qf[mf][t][2] = *(const uint32_t*)&g_qf[tok[mf][0] * 1024 + c0 + 8];
            qf[mf][t][3] = *(const uint32_t*)&g_qf[tok[mf][1] * 1024 + c0 + 8];
        }

    float oc[2][8][4];
    #pragma unroll
    for (int mf = 0; mf < 2; mf++)
        #pragma unroll
        for (int j = 0; j < 8; j++)
            #pragma unroll
            for (int p = 0; p < 4; p++) oc[mf][j][p] = 0.f;
    float mrow[2][2] = {{MASKV_, MASKV_}, {MASKV_, MASKV_}};
    float lrw[2][2]  = {{0.f, 0.f}, {0.f, 0.f}};

    const ull MAGIC2  = pk2(12582912.f, 12582912.f);
    const ull NMAGIC2 = pk2(-12582912.f, -12582912.f);
    const ull NONE2   = pk2(-1.f, -1.f);
    const ull ONE2    = pk2(1.f, 1.f);
    const ull EC1 = pk2(0.69314718f,  0.69314718f);
    const ull EC2 = pk2(0.24022651f,  0.24022651f);
    const ull EC3 = pk2(0.055504109f, 0.055504109f);
    const ull EC4 = pk2(0.0096181291f, 0.0096181291f);

    auto exp2pair = [&](float y0, float y1, float& e0, float& e1) {
        ull y = pk2(y0, y1);
        ull t = add2_(y, MAGIC2);
        ull rr_ = add2_(t, NMAGIC2);
        ull f = fma2_(rr_, NONE2, y);
        ull p = fma2_(EC4, f, EC3);
        p = fma2_(p, f, EC2);
        p = fma2_(p, f, EC1);
        p = fma2_(p, f, ONE2);
        uint32_t tl, th; up2u(tl, th, t);
        ull es = pk2u((tl << 23) + 0x3F800000u, (th << 23) + 0x3F800000u);
        ull res = mul2_(p, es);
        up2(e0, e1, res);
    };

    int q8 = tid & 7, rr = tid >> 3;

    auto load_tile = [&](int j0, int s) {
        #pragma unroll
        for (int p = 0; p < 8; p++) {
            int row = p * 16 + rr;
            size_t gsrc = (size_t)(b * S_ + j0 + row) * 256 + kvh * 64 + q8 * 8;
            CP_ASYNC16(sb + s * FA_STG + row * 144 + q8 * 16, g_kf + gsrc);
            CP_ASYNC16(sb + s * FA_STG + FA_TILE + row * 144 + q8 * 16, g_vf + gsrc);
        }
        CP_COMMIT();
    };

    load_tile(0, 0);

    for (int j0 = 0; j0 <= q0; j0 += 128) {
        int buf = (j0 >> 7) & 1;
        CP_WAIT(0);
        __syncthreads();
        if (j0 + 128 <= q0) load_tile(j0 + 128, buf ^ 1);

        uint32_t kbank = sb + buf * FA_STG;
        uint32_t vbank = kbank + FA_TILE;

        #pragma unroll
        for (int half = 0; half < 2; half++) {
            int kg0 = j0 + half * 64;
            bool active = (kg0 <= qmaxw);
            int ks = half * 64;

            if (active) {
                float sc[2][8][4];
                #pragma unroll
                for (int mf = 0; mf < 2; mf++)
                    #pragma unroll
                    for (int j = 0; j < 8; j++)
                        #pragma unroll
                        for (int p = 0; p < 4; p++) sc[mf][j][p] = 0.f;

                #pragma unroll
                for (int nt = 0; nt < 4; nt++) {
                    #pragma unroll
                    for (int t = 0; t < 4; t++) {
                        uint32_t bk[4];
                        LDSM4(bk, kbank + (ks + nt * 16 + lrow) * 144 + (t * 16 + lcol) * 2);
                        #pragma unroll
                        for (int mf = 0; mf < 2; mf++) {
                            MMA_F16(sc[mf][nt*2],   qf[mf][t], bk[0], bk[2]);
                            MMA_F16(sc[mf][nt*2+1], qf[mf][t], bk[1], bk[3]);
                        }
                    }
                }

                if (kg0 + 63 > q0 + wq) {
                    #pragma unroll
                    for (int mf = 0; mf < 2; mf++) {
                        int qg0 = q0 + wq + mf * 16 + r;
                        int qg1 = qg0 + 8;
                        #pragma unroll
                        for (int j = 0; j < 8; j++) {
                            int key = kg0 + 8 * j + c2;
                            if (key     > qg0) sc[mf][j][0] = MASKV_;
                            if (key + 1 > qg0) sc[mf][j][1] = MASKV_;
                            if (key     > qg1) sc[mf][j][2] = MASKV_;
                            if (key + 1 > qg1) sc[mf][j][3] = MASKV_;
                        }
                    }
                }

                #pragma unroll
                for (int mf = 0; mf < 2; mf++)
                    #pragma unroll
                    for (int rh = 0; rh < 2; rh++) {
                        float rm = sc[mf][0][rh*2];
                        #pragma unroll
                        for (int j = 0; j < 8; j++) {
                            rm = fmaxf(rm, sc[mf][j][rh*2]);
                            rm = fmaxf(rm, sc[mf][j][rh*2+1]);
                        }
                        rm = fmaxf(rm, __shfl_xor_sync(0xffffffffu, rm, 1));
                        rm = fmaxf(rm, __shfl_xor_sync(0xffffffffu, rm, 2));
                        float mn = fmaxf(mrow[mf][rh], rm);
                        float alpha = exp2_fast(mrow[mf][rh] - mn);
                        mrow[mf][rh] = mn;
                        float rs = 0.f;
                        #pragma unroll
                        for (int j = 0; j < 8; j++) {
                            float e0, e1;
                            exp2pair(sc[mf][j][rh*2] - mn, sc[mf][j][rh*2+1] - mn, e0, e1);
                            sc[mf][j][rh*2]   = e0;
                            sc[mf][j][rh*2+1] = e1;
                            rs += e0 + e1;
                        }
                        rs += __shfl_xor_sync(0xffffffffu, rs, 1);
                        rs += __shfl_xor_sync(0xffffffffu, rs, 2);
                        lrw[mf][rh] = lrw[mf][rh] * alpha + rs;
                        #pragma unroll
                        for (int j = 0; j < 8; j++) {
                            oc[mf][j][rh*2]   *= alpha;
                            oc[mf][j][rh*2+1] *= alpha;
                        }
                    }

                #pragma unroll
                for (int u = 0; u < 4; u++) {
                    uint32_t A_hi[2][4];
                    #pragma unroll
                    for (int mf = 0; mf < 2; mf++)
                        #pragma unroll
                        for (int fr = 0; fr < 4; fr++) {
                            int cj = 2*u + (fr >> 1);
                            int po = (fr & 1) * 2;
                            A_hi[mf][fr] = pkhf(sc[mf][cj][po], sc[mf][cj][po+1]);
                        }
                    #pragma unroll
                    for (int dv = 0; dv < 4; dv++) {
                        uint32_t vv[4];
                        LDSM4T(vv, vbank + (ks + u * 16 + (lane & 15)) * 144
                                   + (dv * 16 + (lane >> 4) * 8) * 2);
                        #pragma unroll
                        for (int mf = 0; mf < 2; mf++) {
                            MMA_F16(oc[mf][dv*2],   A_hi[mf], vv[0], vv[1]);
                            MMA_F16(oc[mf][dv*2+1], A_hi[mf], vv[2], vv[3]);
                        }
                    }
                }
            }
        }
    }

    #pragma unroll
    for (int mf = 0; mf < 2; mf++) {
        float inv0 = 1.0f / lrw[mf][0], inv1 = 1.0f / lrw[mf][1];
        #pragma unroll
        for (int j = 0; j < 8; j++) {
            size_t col = (size_t)h * 64 + 8 * j + c2;
            *(uint32_t*)&g_yf[tok[mf][0] * 1024 + col] = pkhf(oc[mf][j][0] * inv0, oc[mf][j][1] * inv0);
            *(uint32_t*)&g_yf[tok[mf][1] * 1024 + col] = pkhf(oc[mf][j][2] * inv1, oc[mf][j][3] * inv1);
        }
    }
}

// ---------------- launch ----------------
extern "C" void kernel_launch(void* const* d_in, const int* in_sizes, int n_in,
                              void* d_out, int out_size) {
    const float* x    = (const float*)d_in[0];
    const float* Wq   = (const float*)d_in[1];
    const float* Wk   = (const float*)d_in[2];
    const float* Wv   = (const float*)d_in[3];
    const float* Wp   = (const float*)d_in[4];
    const float* gain = (const float*)d_in[5];
    const float* Aq   = (const float*)d_in[6];
    const float* Bq   = (const float*)d_in[7];
    const float* Av   = (const float*)d_in[8];
    const float* Bv   = (const float*)d_in[9];
    const int*   step = (const int*)d_in[10];
    float* out = (float*)d_out;

    prep_all_kernel<<<NBW_ + NBX_ + NBR_, 256>>>(x, Wq, Wk, Wv, Wp, Aq, Bq, Av, Bv, step);

    cudaFuncSetAttribute(gemm_mma_kernel<0>, cudaFuncAttributeMaxDynamicSharedMemorySize, G_SMEM);
    cudaFuncSetAttribute(gemm_mma_kernel<2>, cudaFuncAttributeMaxDynamicSharedMemorySize, G_SMEM);
    cudaFuncSetAttribute(flash_mma_kernel,   cudaFuncAttributeMaxDynamicSharedMemorySize, FA_SMEM);

    gemm_mma_kernel<0><<<dim3(1536/128, M_/128), 128, G_SMEM>>>(gain, nullptr);

    flash_mma_kernel<<<dim3(S_/128, H_, B_), 128, FA_SMEM>>>();

    gemm_mma_kernel<2><<<dim3(1024/128, M_/128), 128, G_SMEM>>>(gain, out);
}

// round 12
// speedup vs baseline: 8.8945x; 1.0148x over previous
#include <cuda_runtime.h>
#include <cuda_fp16.h>
#include <math.h>
#include <stdint.h>

#define B_      2
#define S_      2048
#define DIM_    1024
#define H_      16
#define KVH_    4
#define HD_     64
#define KVDIM_  256
#define R_      4
#define NSTEPS_ 2
#define M_      (B_*S_)
#define WROWS_  2560   // [0,1024): Wq+lora | [1024,1280): Wk | [1280,1536): Wv+lora | [1536,2560): Wp

#define QSCALE_ (0.125f * 1.4426950408889634f)

typedef unsigned short ushort_t;
typedef unsigned long long ull;

__device__ __forceinline__ uint32_t smem_u32(const void* p) {
    uint32_t a;
    asm("{ .reg .u64 t; cvta.to.shared.u64 t, %1; cvt.u32.u64 %0, t; }" : "=r"(a) : "l"(p));
    return a;
}

#define LDSM4(r, addr) \
    asm volatile("ldmatrix.sync.aligned.m8n8.x4.shared.b16 {%0,%1,%2,%3}, [%4];" \
        : "=r"((r)[0]),"=r"((r)[1]),"=r"((r)[2]),"=r"((r)[3]) : "r"(addr))
#define LDSM4T(r, addr) \
    asm volatile("ldmatrix.sync.aligned.m8n8.x4.trans.shared.b16 {%0,%1,%2,%3}, [%4];" \
        : "=r"((r)[0]),"=r"((r)[1]),"=r"((r)[2]),"=r"((r)[3]) : "r"(addr))

#define MMA_F16(c, a, b0v, b1v) \
    asm volatile("mma.sync.aligned.m16n8k16.row.col.f32.f16.f16.f32 " \
        "{%0,%1,%2,%3}, {%4,%5,%6,%7}, {%8,%9}, {%0,%1,%2,%3};" \
        : "+f"((c)[0]),"+f"((c)[1]),"+f"((c)[2]),"+f"((c)[3]) \
        : "r"((a)[0]),"r"((a)[1]),"r"((a)[2]),"r"((a)[3]), "r"(b0v),"r"(b1v))

#define CP_ASYNC16(dst, src) \
    asm volatile("cp.async.cg.shared.global [%0], [%1], 16;" :: "r"(dst), "l"(src) : "memory")
#define CP_COMMIT() asm volatile("cp.async.commit_group;" ::: "memory")
#define CP_WAIT(n)  asm volatile("cp.async.wait_group %0;" :: "n"(n) : "memory")

__device__ __forceinline__ uint32_t pkhf(float lo, float hi) {
    uint32_t r; asm("cvt.rn.f16x2.f32 %0, %1, %2;" : "=r"(r) : "f"(hi), "f"(lo)); return r;
}

// ---- packed f32x2 helpers ----
__device__ __forceinline__ ull pk2(float x, float y) {
    ull r; asm("mov.b64 %0, {%1, %2};" : "=l"(r) : "f"(x), "f"(y)); return r;
}
__device__ __forceinline__ ull pk2u(uint32_t x, uint32_t y) {
    ull r; asm("mov.b64 %0, {%1, %2};" : "=l"(r) : "r"(x), "r"(y)); return r;
}
__device__ __forceinline__ void up2(float& x, float& y, ull v) {
    asm("mov.b64 {%0, %1}, %2;" : "=f"(x), "=f"(y) : "l"(v));
}
__device__ __forceinline__ void up2u(uint32_t& x, uint32_t& y, ull v) {
    asm("mov.b64 {%0, %1}, %2;" : "=r"(x), "=r"(y) : "l"(v));
}
__device__ __forceinline__ ull add2_(ull a, ull b) {
    ull d; asm("add.rn.f32x2 %0, %1, %2;" : "=l"(d) : "l"(a), "l"(b)); return d;
}
__device__ __forceinline__ ull mul2_(ull a, ull b) {
    ull d; asm("mul.rn.f32x2 %0, %1, %2;" : "=l"(d) : "l"(a), "l"(b)); return d;
}
__device__ __forceinline__ ull fma2_(ull a, ull b, ull c) {
    ull d; asm("fma.rn.f32x2 %0, %1, %2, %3;" : "=l"(d) : "l"(a), "l"(b), "l"(c)); return d;
}

// ---------------- scratch ----------------
__device__ ushort_t g_xf[M_*DIM_];
__device__ ushort_t g_yf[M_*DIM_];
__device__ ushort_t g_whf[WROWS_*DIM_];
__device__ ushort_t g_qf[M_*DIM_];
__device__ ushort_t g_kf[M_*KVDIM_];
__device__ ushort_t g_vf[M_*KVDIM_];
__device__ float    g_rope[S_*16*2];   // [s][i] -> (cos, sin)

// ---------------- fused prep: W-fold+pack | x->fp16 | rope table ----------------
#define NBW_ ((WROWS_*256)/256)
#define NBX_ ((M_*DIM_/4)/256)
#define NBR_ ((S_*16+255)/256)
__global__ void prep_all_kernel(const float* __restrict__ x,
                                const float* __restrict__ Wq, const float* __restrict__ Wk,
                                const float* __restrict__ Wv, const float* __restrict__ Wp,
                                const float* __restrict__ Aq, const float* __restrict__ Bq,
                                const float* __restrict__ Av, const float* __restrict__ Bv,
                                const int*   __restrict__ stepp) {
    int blk = blockIdx.x;
    if (blk < NBW_) {
        int t = blk * 256 + threadIdx.x;
        int row = t >> 8, k4 = t & 255;
        int step = *stepp;
        bool ok = (step >= 0 && step < NSTEPS_);
        float4 w;
        if (row < 1024) {
            w = ((const float4*)(Wq + (size_t)row * DIM_))[k4];
            if (ok) {
                const float* Ab = Aq + (size_t)step * R_ * DIM_;
                const float* Bb = Bq + ((size_t)step * DIM_ + row) * R_;
                #pragma unroll
                for (int r = 0; r < R_; r++) {
                    float b = Bb[r];
                    float4 a = ((const float4*)(Ab + (size_t)r * DIM_))[k4];
                    w.x += b*a.x; w.y += b*a.y; w.z += b*a.z; w.w += b*a.w;
                }
            }
        } else if (row < 1280) {
            w = ((const float4*)(Wk + (size_t)(row - 1024) * DIM_))[k4];
        } else if (row < 1536) {
            int vr = row - 1280;
            w = ((const float4*)(Wv + (size_t)vr * DIM_))[k4];
            if (ok) {
                const float* Ab = Av + (size_t)step * R_ * DIM_;
                const float* Bb = Bv + ((size_t)step * KVDIM_ + vr) * R_;
                #pragma unroll
                for (int r = 0; r < R_; r++) {
                    float b = Bb[r];
                    float4 a = ((const float4*)(Ab + (size_t)r * DIM_))[k4];
                    w.x += b*a.x; w.y += b*a.y; w.z += b*a.z; w.w += b*a.w;
                }
            }
        } else {
            w = ((const float4*)(Wp + (size_t)(row - 1536) * DIM_))[k4];
        }
        uint2 hp;
        hp.x = pkhf(w.x, w.y);
        hp.y = pkhf(w.z, w.w);
        ((uint2*)g_whf)[t] = hp;
    } else if (blk < NBW_ + NBX_) {
        int t = (blk - NBW_) * 256 + threadIdx.x;
        float4 v = ((const float4*)x)[t];
        uint2 o;
        o.x = pkhf(v.x, v.y);
        o.y = pkhf(v.z, v.w);
        ((uint2*)g_xf)[t] = o;
    } else {
        int t = (blk - NBW_ - NBX_) * 256 + threadIdx.x;
        if (t < S_ * 16) {
            int s = t >> 4, i = t & 15;
            float invf = exp2f(-0.83048202372184059f * (float)i);
            float ang = (float)s * invf;
            g_rope[t * 2]     = cosf(ang);
            g_rope[t * 2 + 1] = sinf(ang);
        }
    }
}

// ---------------- fp16 GEMM, register-pipelined, fused RMS+RoPE epilogue ----------------
#define GT_      10240            // 128 rows x 80B
#define GSTAGE_  (2*GT_)
#define G_SMEM   (4*GSTAGE_)      // 81920

// MODE 0: merged QKV (N=1536) | MODE 2: proj (A=g_yf, fp32 out)
template<int MODE>
__global__ void __launch_bounds__(128, 2)
gemm_mma_kernel(const float* __restrict__ gainp, float* __restrict__ outp) {
    extern __shared__ char smem[];
    uint32_t sb = smem_u32(smem);
    constexpr int WOFF = (MODE == 0) ? 0 : 1536;
    const ushort_t* Xf = (MODE == 2) ? g_yf : g_xf;

    int m0 = blockIdx.y * 128, n0 = blockIdx.x * 128;
    int tid = threadIdx.x;
    int wid = tid >> 5, lane = tid & 31;
    int wm = (wid >> 1) * 64, wn = (wid & 1) * 64;
    int lrow = (lane & 7) + ((lane >> 3) & 1) * 8;
    int lcol = (lane >> 4) * 8;

    auto load_stage = [&](int it, int s) {
        int k0 = it * 32;
        int q = tid & 3;
        int r0 = tid >> 2;
        #pragma unroll
        for (int t = 0; t < 8; t++) {
            int tile = t >> 2;
            int row = (t & 3) * 32 + r0;
            const ushort_t* src;
            if (tile == 0) src = Xf    + (size_t)(m0 + row) * DIM_ + k0 + q * 8;
            else           src = g_whf + (size_t)(WOFF + n0 + row) * DIM_ + k0 + q * 8;
            CP_ASYNC16(sb + s * GSTAGE_ + tile * GT_ + row * 80 + q * 16, src);
        }
        CP_COMMIT();
    };

    float c[4][8][4];
    #pragma unroll
    for (int i = 0; i < 4; i++)
        #pragma unroll
        for (int j = 0; j < 8; j++)
            #pragma unroll
            for (int p = 0; p < 4; p++) c[i][j][p] = 0.f;

    load_stage(0, 0);
    load_stage(1, 1);
    load_stage(2, 2);

    for (int it = 0; it < 32; it++) {
        if (it < 30)       CP_WAIT(2);
        else if (it == 30) CP_WAIT(1);
        else               CP_WAIT(0);
        __syncthreads();
        if (it + 3 < 32) load_stage(it + 3, (it + 3) & 3);

        uint32_t base = sb + (it & 3) * GSTAGE_;

        // register-pipelined inner loop: all A frags up front, B frag chain 1 ahead
        uint32_t a[2][4][4];
        #pragma unroll
        for (int ks = 0; ks < 2; ks++)
            #pragma unroll
            for (int mf = 0; mf < 4; mf++)
                LDSM4(a[ks][mf], base + (wm + mf * 16 + lrow) * 80 + (ks * 16 + lcol) * 2);

        uint32_t bb[2][4];
        LDSM4(bb[0], base + GT_ + (wn + lrow) * 80 + lcol * 2);
        #pragma unroll
        for (int u = 0; u < 8; u++) {
            int ks = u >> 2, nt = u & 3;
            int cur = u & 1;
            if (u < 7) {
                int un = u + 1;
                int ksn = un >> 2, ntn = un & 3;
                LDSM4(bb[cur ^ 1], base + GT_ + (wn + ntn * 16 + lrow) * 80 + (ksn * 16 + lcol) * 2);
            }
            #pragma unroll
            for (int mf = 0; mf < 4; mf++) {
                MMA_F16(c[mf][nt*2],   a[ks][mf], bb[cur][0], bb[cur][2]);
                MMA_F16(c[mf][nt*2+1], a[ks][mf], bb[cur][1], bb[cur][3]);
            }
        }
    }

    if (MODE == 2) {
        #pragma unroll
        for (int mf = 0; mf < 4; mf++) {
            #pragma unroll
            for (int nf = 0; nf < 8; nf++) {
                int gr = m0 + wm + mf * 16 + (lane >> 2);
                int gc = n0 + wn + nf * 8 + (lane & 3) * 2;
                *(float2*)&outp[(size_t)gr * 1024 + gc]       = make_float2(c[mf][nf][0], c[mf][nf][1]);
                *(float2*)&outp[(size_t)(gr + 8) * 1024 + gc] = make_float2(c[mf][nf][2], c[mf][nf][3]);
            }
        }
        return;
    }

    int nglob = n0 + wn;
    if (nglob >= 1280) {
        #pragma unroll
        for (int mf = 0; mf < 4; mf++) {
            #pragma unroll
            for (int nf = 0; nf < 8; nf++) {
                int gr = m0 + wm + mf * 16 + (lane >> 2);
                int vc = nglob - 1280 + nf * 8 + (lane & 3) * 2;
                *(uint32_t*)&g_vf[(size_t)gr * 256 + vc]       = pkhf(c[mf][nf][0], c[mf][nf][1]);
                *(uint32_t*)&g_vf[(size_t)(gr + 8) * 256 + vc] = pkhf(c[mf][nf][2], c[mf][nf][3]);
            }
        }
        return;
    }

    bool isQ = (nglob < 1024);
    float gsc = isQ ? (gainp[nglob >> 6] * QSCALE_) : 1.0f;
    int q2 = (lane & 3) * 2;

    #pragma unroll
    for (int mf = 0; mf < 4; mf++) {
        #pragma unroll
        for (int rr = 0; rr < 2; rr++) {
            float v[8][2];
            #pragma unroll
            for (int nf = 0; nf < 8; nf++) {
                v[nf][0] = c[mf][nf][rr * 2];
                v[nf][1] = c[mf][nf][rr * 2 + 1];
            }
            float ss = 0.f;
            #pragma unroll
            for (int nf = 0; nf < 8; nf++)
                ss += v[nf][0] * v[nf][0] + v[nf][1] * v[nf][1];
            ss += __shfl_xor_sync(0xffffffffu, ss, 1);
            ss += __shfl_xor_sync(0xffffffffu, ss, 2);
            float scl = rsqrtf(ss * (1.0f / 64.0f) + 1.1920929e-7f) * gsc;
            #pragma unroll
            for (int nf = 0; nf < 8; nf++) { v[nf][0] *= scl; v[nf][1] *= scl; }

            int m = m0 + wm + mf * 16 + (lane >> 2) + rr * 8;
            int s = m & (S_ - 1);
            float4 r0 = *(const float4*)&g_rope[(s * 16 + q2) * 2];
            float4 r1 = *(const float4*)&g_rope[(s * 16 + 8 + q2) * 2];
            float x1, x2;
            x1 = v[0][0]; x2 = v[2][0];
            v[0][0] = x1 * r0.x + x2 * r0.y;  v[2][0] = -x1 * r0.y + x2 * r0.x;
            x1 = v[0][1]; x2 = v[2][1];
            v[0][1] = x1 * r0.z + x2 * r0.w;  v[2][1] = -x1 * r0.w + x2 * r0.z;
            x1 = v[1][0]; x2 = v[3][0];
            v[1][0] = x1 * r1.x + x2 * r1.y;  v[3][0] = -x1 * r1.y + x2 * r1.x;
            x1 = v[1][1]; x2 = v[3][1];
            v[1][1] = x1 * r1.z + x2 * r1.w;  v[3][1] = -x1 * r1.w + x2 * r1.z;

            if (isQ) {
                size_t bix = (size_t)m * 1024 + nglob + q2;
                #pragma unroll
                for (int nf = 0; nf < 8; nf++)
                    *(uint32_t*)&g_qf[bix + nf * 8] = pkhf(v[nf][0], v[nf][1]);
            } else {
                size_t bix = (size_t)m * 256 + (nglob - 1024) + q2;
                #pragma unroll
                for (int nf = 0; nf < 8; nf++)
                    *(uint32_t*)&g_kf[bix + nf * 8] = pkhf(v[nf][0], v[nf][1]);
            }
        }
    }
}

// ---------------- flash attention: fixed-offset softmax (no online max) ----------------
// scores bounded: |s| <= ||q_scaled||*||k|| = log2e * 8 ~= 11.6 (base-2 domain)
#define FA_TILE  18432
#define FA_STG   (2*FA_TILE)
#define FA_SMEM  (2*FA_STG)    // 73728
#define MASKV_   (-50.0f)

__global__ void __launch_bounds__(128, 2)
flash_mma_kernel() {
    extern __shared__ char smem[];
    uint32_t sb = smem_u32(smem);

    int b = blockIdx.z, h = blockIdx.y;
    int q0 = (gridDim.x - 1 - blockIdx.x) * 128;
    int kvh = h >> 2;
    int tid = threadIdx.x;
    int wid = tid >> 5, lane = tid & 31;
    int r = lane >> 2, c2 = (lane & 3) * 2;
    int lrow = (lane & 7) + ((lane >> 3) & 1) * 8;
    int lcol = (lane >> 4) * 8;

    int wq = wid * 32;
    int qmaxw = q0 + wq + 31;

    size_t tok[2][2];
    #pragma unroll
    for (int mf = 0; mf < 2; mf++) {
        tok[mf][0] = (size_t)(b * S_) + q0 + wq + mf * 16 + r;
        tok[mf][1] = tok[mf][0] + 8;
    }

    uint32_t qf[2][4][4];
    #pragma unroll
    for (int mf = 0; mf < 2; mf++)
        #pragma unroll
        for (int t = 0; t < 4; t++) {
            size_t c0 = (size_t)h * 64 + t * 16 + c2;
            qf[mf][t][0] = *(const uint32_t*)&g_qf[tok[mf][0] * 1024 + c0];
            qf[mf][t][1] = *(const uint32_t*)&g_qf[tok[mf][1] * 1024 + c0];
            qf[mf][t][2] = *(const uint32_t*)&g_qf[tok[mf][0] * 1024 + c0 + 8];
            qf[mf][t][3] = *(const uint32_t*)&g_qf[tok[mf][1] * 1024 + c0 + 8];
        }

    float oc[2][8][4];
    #pragma unroll
    for (int mf = 0; mf < 2; mf++)
        #pragma unroll
        for (int j = 0; j < 8; j++)
            #pragma unroll
            for (int p = 0; p < 4; p++) oc[mf][j][p] = 0.f;
    float lrw[2][2] = {{0.f, 0.f}, {0.f, 0.f}};

    const ull MAGIC2  = pk2(12582912.f, 12582912.f);
    const ull NMAGIC2 = pk2(-12582912.f, -12582912.f);
    const ull NONE2   = pk2(-1.f, -1.f);
    const ull ONE2    = pk2(1.f, 1.f);
    const ull EC1 = pk2(0.69314718f,  0.69314718f);
    const ull EC2 = pk2(0.24022651f,  0.24022651f);
    const ull EC3 = pk2(0.055504109f, 0.055504109f);
    const ull EC4 = pk2(0.0096181291f, 0.0096181291f);

    auto exp2pair = [&](float y0, float y1, float& e0, float& e1) {
        ull y = pk2(y0, y1);
        ull t = add2_(y, MAGIC2);
        ull rr_ = add2_(t, NMAGIC2);
        ull f = fma2_(rr_, NONE2, y);
        ull p = fma2_(EC4, f, EC3);
        p = fma2_(p, f, EC2);
        p = fma2_(p, f, EC1);
        p = fma2_(p, f, ONE2);
        uint32_t tl, th; up2u(tl, th, t);
        ull es = pk2u((tl << 23) + 0x3F800000u, (th << 23) + 0x3F800000u);
        ull res = mul2_(p, es);
        up2(e0, e1, res);
    };

    int q8 = tid & 7, rr = tid >> 3;

    auto load_tile = [&](int j0, int s) {
        #pragma unroll
        for (int p = 0; p < 8; p++) {
            int row = p * 16 + rr;
            size_t gsrc = (size_t)(b * S_ + j0 + row) * 256 + kvh * 64 + q8 * 8;
            CP_ASYNC16(sb + s * FA_STG + row * 144 + q8 * 16, g_kf + gsrc);
            CP_ASYNC16(sb + s * FA_STG + FA_TILE + row * 144 + q8 * 16, g_vf + gsrc);
        }
        CP_COMMIT();
    };

    load_tile(0, 0);

    for (int j0 = 0; j0 <= q0; j0 += 128) {
        int buf = (j0 >> 7) & 1;
        CP_WAIT(0);
        __syncthreads();
        if (j0 + 128 <= q0) load_tile(j0 + 128, buf ^ 1);

        uint32_t kbank = sb + buf * FA_STG;
        uint32_t vbank = kbank + FA_TILE;

        #pragma unroll
        for (int half = 0; half < 2; half++) {
            int kg0 = j0 + half * 64;
            bool active = (kg0 <= qmaxw);
            int ks = half * 64;

            if (active) {
                float sc[2][8][4];
                #pragma unroll
                for (int mf = 0; mf < 2; mf++)
                    #pragma unroll
                    for (int j = 0; j < 8; j++)
                        #pragma unroll
                        for (int p = 0; p < 4; p++) sc[mf][j][p] = 0.f;

                // scores = Q.K^T with bk register chain (prefetch 1 ahead)
                {
                    uint32_t bkb[2][4];
                    LDSM4(bkb[0], kbank + (ks + lrow) * 144 + lcol * 2);
                    #pragma unroll
                    for (int u = 0; u < 16; u++) {
                        int nt = u >> 2, t = u & 3;
                        int cur = u & 1;
                        if (u < 15) {
                            int un = u + 1;
                            int ntn = un >> 2, tn = un & 3;
                            LDSM4(bkb[cur ^ 1], kbank + (ks + ntn * 16 + lrow) * 144 + (tn * 16 + lcol) * 2);
                        }
                        #pragma unroll
                        for (int mf = 0; mf < 2; mf++) {
                            MMA_F16(sc[mf][nt*2],   qf[mf][t], bkb[cur][0], bkb[cur][2]);
                            MMA_F16(sc[mf][nt*2+1], qf[mf][t], bkb[cur][1], bkb[cur][3]);
                        }
                    }
                }

                if (kg0 + 63 > q0 + wq) {
                    #pragma unroll
                    for (int mf = 0; mf < 2; mf++) {
                        int qg0 = q0 + wq + mf * 16 + r;
                        int qg1 = qg0 + 8;
                        #pragma unroll
                        for (int j = 0; j < 8; j++) {
                            int key = kg0 + 8 * j + c2;
                            if (key     > qg0) sc[mf][j][0] = MASKV_;
                            if (key + 1 > qg0) sc[mf][j][1] = MASKV_;
                            if (key     > qg1) sc[mf][j][2] = MASKV_;
                            if (key + 1 > qg1) sc[mf][j][3] = MASKV_;
                        }
                    }
                }

                // softmax numerator: p = exp2(s) (scores bounded; offset cancels in normalization)
                #pragma unroll
                for (int mf = 0; mf < 2; mf++) {
                    float rs0 = 0.f, rs1 = 0.f;
                    #pragma unroll
                    for (int j = 0; j < 8; j++) {
                        float e0, e1, e2, e3;
                        exp2pair(sc[mf][j][0], sc[mf][j][1], e0, e1);
                        exp2pair(sc[mf][j][2], sc[mf][j][3], e2, e3);
                        sc[mf][j][0] = e0; sc[mf][j][1] = e1;
                        sc[mf][j][2] = e2; sc[mf][j][3] = e3;
                        rs0 += e0 + e1;
                        rs1 += e2 + e3;
                    }
                    lrw[mf][0] += rs0;
                    lrw[mf][1] += rs1;
                }

                // O += P @ V
                #pragma unroll
                for (int u = 0; u < 4; u++) {
                    uint32_t A_hi[2][4];
                    #pragma unroll
                    for (int mf = 0; mf < 2; mf++)
                        #pragma unroll
                        for (int fr = 0; fr < 4; fr++) {
                            int cj = 2*u + (fr >> 1);
                            int po = (fr & 1) * 2;
                            A_hi[mf][fr] = pkhf(sc[mf][cj][po], sc[mf][cj][po+1]);
                        }
                    #pragma unroll
                    for (int dv = 0; dv < 4; dv++) {
                        uint32_t vv[4];
                        LDSM4T(vv, vbank + (ks + u * 16 + (lane & 15)) * 144
                                   + (dv * 16 + (lane >> 4) * 8) * 2);
                        #pragma unroll
                        for (int mf = 0; mf < 2; mf++) {
                            MMA_F16(oc[mf][dv*2],   A_hi[mf], vv[0], vv[1]);
                            MMA_F16(oc[mf][dv*2+1], A_hi[mf], vv[2], vv[3]);
                        }
                    }
                }
            }
        }
    }

    // epilogue: deferred row-sum reduction, then y = O / l -> fp16
    #pragma unroll
    for (int mf = 0; mf < 2; mf++) {
        #pragma unroll
        for (int rh = 0; rh < 2; rh++) {
            float l = lrw[mf][rh];
            l += __shfl_xor_sync(0xffffffffu, l, 1);
            l += __shfl_xor_sync(0xffffffffu, l, 2);
            lrw[mf][rh] = 1.0f / l;
        }
        #pragma unroll
        for (int j = 0; j < 8; j++) {
            size_t col = (size_t)h * 64 + 8 * j + c2;
            *(uint32_t*)&g_yf[tok[mf][0] * 1024 + col] =
                pkhf(oc[mf][j][0] * lrw[mf][0], oc[mf][j][1] * lrw[mf][0]);
            *(uint32_t*)&g_yf[tok[mf][1] * 1024 + col] =
                pkhf(oc[mf][j][2] * lrw[mf][1], oc[mf][j][3] * lrw[mf][1]);
        }
    }
}

// ---------------- launch ----------------
extern "C" void kernel_launch(void* const* d_in, const int* in_sizes, int n_in,
                              void* d_out, int out_size) {
    const float* x    = (const float*)d_in[0];
    const float* Wq   = (const float*)d_in[1];
    const float* Wk   = (const float*)d_in[2];
    const float* Wv   = (const float*)d_in[3];
    const float* Wp   = (const float*)d_in[4];
    const float* gain = (const float*)d_in[5];
    const float* Aq   = (const float*)d_in[6];
    const float* Bq   = (const float*)d_in[7];
    const float* Av   = (const float*)d_in[8];
    const float* Bv   = (const float*)d_in[9];
    const int*   step = (const int*)d_in[10];
    float* out = (float*)d_out;

    prep_all_kernel<<<NBW_ + NBX_ + NBR_, 256>>>(x, Wq, Wk, Wv, Wp, Aq, Bq, Av, Bv, step);

    cudaFuncSetAttribute(gemm_mma_kernel<0>, cudaFuncAttributeMaxDynamicSharedMemorySize, G_SMEM);
    cudaFuncSetAttribute(gemm_mma_kernel<2>, cudaFuncAttributeMaxDynamicSharedMemorySize, G_SMEM);
    cudaFuncSetAttribute(flash_mma_kernel,   cudaFuncAttributeMaxDynamicSharedMemorySize, FA_SMEM);

    gemm_mma_kernel<0><<<dim3(1536/128, M_/128), 128, G_SMEM>>>(gain, nullptr);

    flash_mma_kernel<<<dim3(S_/128, H_, B_), 128, FA_SMEM>>>();

    gemm_mma_kernel<2><<<dim3(1024/128, M_/128), 128, G_SMEM>>>(gain, out);
}

// round 13
// speedup vs baseline: 9.6777x; 1.0880x over previous
#include <cuda_runtime.h>
#include <cuda_fp16.h>
#include <math.h>
#include <stdint.h>

#define B_      2
#define S_      2048
#define DIM_    1024
#define H_      16
#define KVH_    4
#define HD_     64
#define KVDIM_  256
#define R_      4
#define NSTEPS_ 2
#define M_      (B_*S_)
#define WROWS_  2560   // [0,1024): Wq+lora | [1024,1280): Wk | [1280,1536): Wv+lora | [1536,2560): Wp

#define QSCALE_ (0.125f * 1.4426950408889634f)

typedef unsigned short ushort_t;
typedef unsigned long long ull;

__device__ __forceinline__ uint32_t smem_u32(const void* p) {
    uint32_t a;
    asm("{ .reg .u64 t; cvta.to.shared.u64 t, %1; cvt.u32.u64 %0, t; }" : "=r"(a) : "l"(p));
    return a;
}

#define LDSM4(r, addr) \
    asm volatile("ldmatrix.sync.aligned.m8n8.x4.shared.b16 {%0,%1,%2,%3}, [%4];" \
        : "=r"((r)[0]),"=r"((r)[1]),"=r"((r)[2]),"=r"((r)[3]) : "r"(addr))
#define LDSM4T(r, addr) \
    asm volatile("ldmatrix.sync.aligned.m8n8.x4.trans.shared.b16 {%0,%1,%2,%3}, [%4];" \
        : "=r"((r)[0]),"=r"((r)[1]),"=r"((r)[2]),"=r"((r)[3]) : "r"(addr))

#define MMA_F16(c, a, b0v, b1v) \
    asm volatile("mma.sync.aligned.m16n8k16.row.col.f32.f16.f16.f32 " \
        "{%0,%1,%2,%3}, {%4,%5,%6,%7}, {%8,%9}, {%0,%1,%2,%3};" \
        : "+f"((c)[0]),"+f"((c)[1]),"+f"((c)[2]),"+f"((c)[3]) \
        : "r"((a)[0]),"r"((a)[1]),"r"((a)[2]),"r"((a)[3]), "r"(b0v),"r"(b1v))

#define CP_ASYNC16(dst, src) \
    asm volatile("cp.async.cg.shared.global [%0], [%1], 16;" :: "r"(dst), "l"(src) : "memory")
#define CP_COMMIT() asm volatile("cp.async.commit_group;" ::: "memory")
#define CP_WAIT(n)  asm volatile("cp.async.wait_group %0;" :: "n"(n) : "memory")

__device__ __forceinline__ uint32_t pkhf(float lo, float hi) {
    uint32_t r; asm("cvt.rn.f16x2.f32 %0, %1, %2;" : "=r"(r) : "f"(hi), "f"(lo)); return r;
}

// ---- packed f32x2 helpers ----
__device__ __forceinline__ ull pk2(float x, float y) {
    ull r; asm("mov.b64 %0, {%1, %2};" : "=l"(r) : "f"(x), "f"(y)); return r;
}
__device__ __forceinline__ ull pk2u(uint32_t x, uint32_t y) {
    ull r; asm("mov.b64 %0, {%1, %2};" : "=l"(r) : "r"(x), "r"(y)); return r;
}
__device__ __forceinline__ void up2(float& x, float& y, ull v) {
    asm("mov.b64 {%0, %1}, %2;" : "=f"(x), "=f"(y) : "l"(v));
}
__device__ __forceinline__ void up2u(uint32_t& x, uint32_t& y, ull v) {
    asm("mov.b64 {%0, %1}, %2;" : "=r"(x), "=r"(y) : "l"(v));
}
__device__ __forceinline__ ull add2_(ull a, ull b) {
    ull d; asm("add.rn.f32x2 %0, %1, %2;" : "=l"(d) : "l"(a), "l"(b)); return d;
}
__device__ __forceinline__ ull mul2_(ull a, ull b) {
    ull d; asm("mul.rn.f32x2 %0, %1, %2;" : "=l"(d) : "l"(a), "l"(b)); return d;
}
__device__ __forceinline__ ull fma2_(ull a, ull b, ull c) {
    ull d; asm("fma.rn.f32x2 %0, %1, %2, %3;" : "=l"(d) : "l"(a), "l"(b), "l"(c)); return d;
}

// ---------------- scratch ----------------
__device__ ushort_t g_xf[M_*DIM_];
__device__ ushort_t g_yf[M_*DIM_];
__device__ ushort_t g_whf[WROWS_*DIM_];
__device__ ushort_t g_qf[M_*DIM_];
__device__ ushort_t g_kf[M_*KVDIM_];
__device__ ushort_t g_vf[M_*KVDIM_];
__device__ float    g_rope[S_*16*2];   // [s][i] -> (cos, sin)

// ---------------- fused prep: W-fold+pack | x->fp16 | rope table ----------------
#define NBW_ ((WROWS_*256)/256)
#define NBX_ ((M_*DIM_/4)/256)
#define NBR_ ((S_*16+255)/256)
__global__ void prep_all_kernel(const float* __restrict__ x,
                                const float* __restrict__ Wq, const float* __restrict__ Wk,
                                const float* __restrict__ Wv, const float* __restrict__ Wp,
                                const float* __restrict__ Aq, const float* __restrict__ Bq,
                                const float* __restrict__ Av, const float* __restrict__ Bv,
                                const int*   __restrict__ stepp) {
    int blk = blockIdx.x;
    if (blk < NBW_) {
        int t = blk * 256 + threadIdx.x;
        int row = t >> 8, k4 = t & 255;
        int step = *stepp;
        bool ok = (step >= 0 && step < NSTEPS_);
        float4 w;
        if (row < 1024) {
            w = ((const float4*)(Wq + (size_t)row * DIM_))[k4];
            if (ok) {
                const float* Ab = Aq + (size_t)step * R_ * DIM_;
                const float* Bb = Bq + ((size_t)step * DIM_ + row) * R_;
                #pragma unroll
                for (int r = 0; r < R_; r++) {
                    float b = Bb[r];
                    float4 a = ((const float4*)(Ab + (size_t)r * DIM_))[k4];
                    w.x += b*a.x; w.y += b*a.y; w.z += b*a.z; w.w += b*a.w;
                }
            }
        } else if (row < 1280) {
            w = ((const float4*)(Wk + (size_t)(row - 1024) * DIM_))[k4];
        } else if (row < 1536) {
            int vr = row - 1280;
            w = ((const float4*)(Wv + (size_t)vr * DIM_))[k4];
            if (ok) {
                const float* Ab = Av + (size_t)step * R_ * DIM_;
                const float* Bb = Bv + ((size_t)step * KVDIM_ + vr) * R_;
                #pragma unroll
                for (int r = 0; r < R_; r++) {
                    float b = Bb[r];
                    float4 a = ((const float4*)(Ab + (size_t)r * DIM_))[k4];
                    w.x += b*a.x; w.y += b*a.y; w.z += b*a.z; w.w += b*a.w;
                }
            }
        } else {
            w = ((const float4*)(Wp + (size_t)(row - 1536) * DIM_))[k4];
        }
        uint2 hp;
        hp.x = pkhf(w.x, w.y);
        hp.y = pkhf(w.z, w.w);
        ((uint2*)g_whf)[t] = hp;
    } else if (blk < NBW_ + NBX_) {
        int t = (blk - NBW_) * 256 + threadIdx.x;
        float4 v = ((const float4*)x)[t];
        uint2 o;
        o.x = pkhf(v.x, v.y);
        o.y = pkhf(v.z, v.w);
        ((uint2*)g_xf)[t] = o;
    } else {
        int t = (blk - NBW_ - NBX_) * 256 + threadIdx.x;
        if (t < S_ * 16) {
            int s = t >> 4, i = t & 15;
            float invf = exp2f(-0.83048202372184059f * (float)i);
            float ang = (float)s * invf;
            g_rope[t * 2]     = cosf(ang);
            g_rope[t * 2 + 1] = sinf(ang);
        }
    }
}

// ---------------- fp16 GEMM, 3 stages, 3 CTAs/SM, fused RMS+RoPE epilogue ----------------
#define GT_      10240            // 128 rows x 80B
#define GSTAGE_  (2*GT_)
#define G_SMEM   (3*GSTAGE_)      // 61440 -> 3 CTAs/SM

// MODE 0: merged QKV (N=1536) | MODE 2: proj (A=g_yf, fp32 out)
template<int MODE>
__global__ void __launch_bounds__(128, 3)
gemm_mma_kernel(const float* __restrict__ gainp, float* __restrict__ outp) {
    extern __shared__ char smem[];
    uint32_t sb = smem_u32(smem);
    constexpr int WOFF = (MODE == 0) ? 0 : 1536;
    const ushort_t* Xf = (MODE == 2) ? g_yf : g_xf;

    int m0 = blockIdx.y * 128, n0 = blockIdx.x * 128;
    int tid = threadIdx.x;
    int wid = tid >> 5, lane = tid & 31;
    int wm = (wid >> 1) * 64, wn = (wid & 1) * 64;
    int lrow = (lane & 7) + ((lane >> 3) & 1) * 8;
    int lcol = (lane >> 4) * 8;

    auto load_stage = [&](int it, int s) {
        int k0 = it * 32;
        int q = tid & 3;
        int r0 = tid >> 2;
        #pragma unroll
        for (int t = 0; t < 8; t++) {
            int tile = t >> 2;
            int row = (t & 3) * 32 + r0;
            const ushort_t* src;
            if (tile == 0) src = Xf    + (size_t)(m0 + row) * DIM_ + k0 + q * 8;
            else           src = g_whf + (size_t)(WOFF + n0 + row) * DIM_ + k0 + q * 8;
            CP_ASYNC16(sb + s * GSTAGE_ + tile * GT_ + row * 80 + q * 16, src);
        }
        CP_COMMIT();
    };

    float c[4][8][4];
    #pragma unroll
    for (int i = 0; i < 4; i++)
        #pragma unroll
        for (int j = 0; j < 8; j++)
            #pragma unroll
            for (int p = 0; p < 4; p++) c[i][j][p] = 0.f;

    load_stage(0, 0);
    load_stage(1, 1);

    int slot = 2;
    for (int it = 0; it < 32; it++) {
        if (it < 31) CP_WAIT(1);
        else         CP_WAIT(0);
        __syncthreads();
        if (it + 2 < 32) load_stage(it + 2, slot);
        if (++slot == 3) slot = 0;

        uint32_t base = sb + (it % 3) * GSTAGE_;

        #pragma unroll
        for (int ks = 0; ks < 2; ks++) {
            int kb = ks * 16;
            uint32_t a[4][4];
            #pragma unroll
            for (int mf = 0; mf < 4; mf++)
                LDSM4(a[mf], base + (wm + mf * 16 + lrow) * 80 + (kb + lcol) * 2);
            uint32_t bb[2][4];
            LDSM4(bb[0], base + GT_ + (wn + lrow) * 80 + (kb + lcol) * 2);
            #pragma unroll
            for (int nt = 0; nt < 4; nt++) {
                int cur = nt & 1;
                if (nt < 3)
                    LDSM4(bb[cur ^ 1], base + GT_ + (wn + (nt+1) * 16 + lrow) * 80 + (kb + lcol) * 2);
                #pragma unroll
                for (int mf = 0; mf < 4; mf++) {
                    MMA_F16(c[mf][nt*2],   a[mf], bb[cur][0], bb[cur][2]);
                    MMA_F16(c[mf][nt*2+1], a[mf], bb[cur][1], bb[cur][3]);
                }
            }
        }
    }

    if (MODE == 2) {
        #pragma unroll
        for (int mf = 0; mf < 4; mf++) {
            #pragma unroll
            for (int nf = 0; nf < 8; nf++) {
                int gr = m0 + wm + mf * 16 + (lane >> 2);
                int gc = n0 + wn + nf * 8 + (lane & 3) * 2;
                *(float2*)&outp[(size_t)gr * 1024 + gc]       = make_float2(c[mf][nf][0], c[mf][nf][1]);
                *(float2*)&outp[(size_t)(gr + 8) * 1024 + gc] = make_float2(c[mf][nf][2], c[mf][nf][3]);
            }
        }
        return;
    }

    int nglob = n0 + wn;
    if (nglob >= 1280) {
        #pragma unroll
        for (int mf = 0; mf < 4; mf++) {
            #pragma unroll
            for (int nf = 0; nf < 8; nf++) {
                int gr = m0 + wm + mf * 16 + (lane >> 2);
                int vc = nglob - 1280 + nf * 8 + (lane & 3) * 2;
                *(uint32_t*)&g_vf[(size_t)gr * 256 + vc]       = pkhf(c[mf][nf][0], c[mf][nf][1]);
                *(uint32_t*)&g_vf[(size_t)(gr + 8) * 256 + vc] = pkhf(c[mf][nf][2], c[mf][nf][3]);
            }
        }
        return;
    }

    bool isQ = (nglob < 1024);
    float gsc = isQ ? (gainp[nglob >> 6] * QSCALE_) : 1.0f;
    int q2 = (lane & 3) * 2;

    #pragma unroll
    for (int mf = 0; mf < 4; mf++) {
        #pragma unroll
        for (int rr = 0; rr < 2; rr++) {
            float v[8][2];
            #pragma unroll
            for (int nf = 0; nf < 8; nf++) {
                v[nf][0] = c[mf][nf][rr * 2];
                v[nf][1] = c[mf][nf][rr * 2 + 1];
            }
            float ss = 0.f;
            #pragma unroll
            for (int nf = 0; nf < 8; nf++)
                ss += v[nf][0] * v[nf][0] + v[nf][1] * v[nf][1];
            ss += __shfl_xor_sync(0xffffffffu, ss, 1);
            ss += __shfl_xor_sync(0xffffffffu, ss, 2);
            float scl = rsqrtf(ss * (1.0f / 64.0f) + 1.1920929e-7f) * gsc;
            #pragma unroll
            for (int nf = 0; nf < 8; nf++) { v[nf][0] *= scl; v[nf][1] *= scl; }

            int m = m0 + wm + mf * 16 + (lane >> 2) + rr * 8;
            int s = m & (S_ - 1);
            float4 r0 = *(const float4*)&g_rope[(s * 16 + q2) * 2];
            float4 r1 = *(const float4*)&g_rope[(s * 16 + 8 + q2) * 2];
            float x1, x2;
            x1 = v[0][0]; x2 = v[2][0];
            v[0][0] = x1 * r0.x + x2 * r0.y;  v[2][0] = -x1 * r0.y + x2 * r0.x;
            x1 = v[0][1]; x2 = v[2][1];
            v[0][1] = x1 * r0.z + x2 * r0.w;  v[2][1] = -x1 * r0.w + x2 * r0.z;
            x1 = v[1][0]; x2 = v[3][0];
            v[1][0] = x1 * r1.x + x2 * r1.y;  v[3][0] = -x1 * r1.y + x2 * r1.x;
            x1 = v[1][1]; x2 = v[3][1];
            v[1][1] = x1 * r1.z + x2 * r1.w;  v[3][1] = -x1 * r1.w + x2 * r1.z;

            if (isQ) {
                size_t bix = (size_t)m * 1024 + nglob + q2;
                #pragma unroll
                for (int nf = 0; nf < 8; nf++)
                    *(uint32_t*)&g_qf[bix + nf * 8] = pkhf(v[nf][0], v[nf][1]);
            } else {
                size_t bix = (size_t)m * 256 + (nglob - 1024) + q2;
                #pragma unroll
                for (int nf = 0; nf < 8; nf++)
                    *(uint32_t*)&g_kf[bix + nf * 8] = pkhf(v[nf][0], v[nf][1]);
            }
        }
    }
}

// ---------------- flash attention: fixed-offset softmax (no online max) ----------------
#define FA_TILE  18432
#define FA_STG   (2*FA_TILE)
#define FA_SMEM  (2*FA_STG)    // 73728
#define MASKV_   (-50.0f)

__global__ void __launch_bounds__(128, 2)
flash_mma_kernel() {
    extern __shared__ char smem[];
    uint32_t sb = smem_u32(smem);

    int b = blockIdx.z, h = blockIdx.y;
    int q0 = (gridDim.x - 1 - blockIdx.x) * 128;
    int kvh = h >> 2;
    int tid = threadIdx.x;
    int wid = tid >> 5, lane = tid & 31;
    int r = lane >> 2, c2 = (lane & 3) * 2;
    int lrow = (lane & 7) + ((lane >> 3) & 1) * 8;
    int lcol = (lane >> 4) * 8;

    int wq = wid * 32;
    int qmaxw = q0 + wq + 31;

    size_t tok[2][2];
    #pragma unroll
    for (int mf = 0; mf < 2; mf++) {
        tok[mf][0] = (size_t)(b * S_) + q0 + wq + mf * 16 + r;
        tok[mf][1] = tok[mf][0] + 8;
    }

    uint32_t qf[2][4][4];
    #pragma unroll
    for (int mf = 0; mf < 2; mf++)
        #pragma unroll
        for (int t = 0; t < 4; t++) {
            size_t c0 = (size_t)h * 64 + t * 16 + c2;
            qf[mf][t][0] = *(const uint32_t*)&g_qf[tok[mf][0] * 1024 + c0];
            qf[mf][t][1] = *(const uint32_t*)&g_qf[tok[mf][1] * 1024 + c0];
            qf[mf][t][2] = *(const uint32_t*)&g_qf[tok[mf][0] * 1024 + c0 + 8];
            qf[mf][t][3] = *(const uint32_t*)&g_qf[tok[mf][1] * 1024 + c0 + 8];
        }

    float oc[2][8][4];
    #pragma unroll
    for (int mf = 0; mf < 2; mf++)
        #pragma unroll
        for (int j = 0; j < 8; j++)
            #pragma unroll
            for (int p = 0; p < 4; p++) oc[mf][j][p] = 0.f;
    float lrw[2][2] = {{0.f, 0.f}, {0.f, 0.f}};

    const ull MAGIC2  = pk2(12582912.f, 12582912.f);
    const ull NMAGIC2 = pk2(-12582912.f, -12582912.f);
    const ull NONE2   = pk2(-1.f, -1.f);
    const ull ONE2    = pk2(1.f, 1.f);
    const ull EC1 = pk2(0.69314718f,  0.69314718f);
    const ull EC2 = pk2(0.24022651f,  0.24022651f);
    const ull EC3 = pk2(0.055504109f, 0.055504109f);
    const ull EC4 = pk2(0.0096181291f, 0.0096181291f);

    auto exp2pair = [&](float y0, float y1, float& e0, float& e1) {
        ull y = pk2(y0, y1);
        ull t = add2_(y, MAGIC2);
        ull rr_ = add2_(t, NMAGIC2);
        ull f = fma2_(rr_, NONE2, y);
        ull p = fma2_(EC4, f, EC3);
        p = fma2_(p, f, EC2);
        p = fma2_(p, f, EC1);
        p = fma2_(p, f, ONE2);
        uint32_t tl, th; up2u(tl, th, t);
        ull es = pk2u((tl << 23) + 0x3F800000u, (th << 23) + 0x3F800000u);
        ull res = mul2_(p, es);
        up2(e0, e1, res);
    };

    int q8 = tid & 7, rr = tid >> 3;

    auto load_tile = [&](int j0, int s) {
        #pragma unroll
        for (int p = 0; p < 8; p++) {
            int row = p * 16 + rr;
            size_t gsrc = (size_t)(b * S_ + j0 + row) * 256 + kvh * 64 + q8 * 8;
            CP_ASYNC16(sb + s * FA_STG + row * 144 + q8 * 16, g_kf + gsrc);
            CP_ASYNC16(sb + s * FA_STG + FA_TILE + row * 144 + q8 * 16, g_vf + gsrc);
        }
        CP_COMMIT();
    };

    load_tile(0, 0);

    for (int j0 = 0; j0 <= q0; j0 += 128) {
        int buf = (j0 >> 7) & 1;
        CP_WAIT(0);
        __syncthreads();
        if (j0 + 128 <= q0) load_tile(j0 + 128, buf ^ 1);

        uint32_t kbank = sb + buf * FA_STG;
        uint32_t vbank = kbank + FA_TILE;

        #pragma unroll
        for (int half = 0; half < 2; half++) {
            int kg0 = j0 + half * 64;
            bool active = (kg0 <= qmaxw);
            int ks = half * 64;

            if (active) {
                float sc[2][8][4];
                #pragma unroll
                for (int mf = 0; mf < 2; mf++)
                    #pragma unroll
                    for (int j = 0; j < 8; j++)
                        #pragma unroll
                        for (int p = 0; p < 4; p++) sc[mf][j][p] = 0.f;

                {
                    uint32_t bkb[2][4];
                    LDSM4(bkb[0], kbank + (ks + lrow) * 144 + lcol * 2);
                    #pragma unroll
                    for (int u = 0; u < 16; u++) {
                        int nt = u >> 2, t = u & 3;
                        int cur = u & 1;
                        if (u < 15) {
                            int un = u + 1;
                            int ntn = un >> 2, tn = un & 3;
                            LDSM4(bkb[cur ^ 1], kbank + (ks + ntn * 16 + lrow) * 144 + (tn * 16 + lcol) * 2);
                        }
                        #pragma unroll
                        for (int mf = 0; mf < 2; mf++) {
                            MMA_F16(sc[mf][nt*2],   qf[mf][t], bkb[cur][0], bkb[cur][2]);
                            MMA_F16(sc[mf][nt*2+1], qf[mf][t], bkb[cur][1], bkb[cur][3]);
                        }
                    }
                }

                if (kg0 + 63 > q0 + wq) {
                    #pragma unroll
                    for (int mf = 0; mf < 2; mf++) {
                        int qg0 = q0 + wq + mf * 16 + r;
                        int qg1 = qg0 + 8;
                        #pragma unroll
                        for (int j = 0; j < 8; j++) {
                            int key = kg0 + 8 * j + c2;
                            if (key     > qg0) sc[mf][j][0] = MASKV_;
                            if (key + 1 > qg0) sc[mf][j][1] = MASKV_;
                            if (key     > qg1) sc[mf][j][2] = MASKV_;
                            if (key + 1 > qg1) sc[mf][j][3] = MASKV_;
                        }
                    }
                }

                #pragma unroll
                for (int mf = 0; mf < 2; mf++) {
                    float rs0 = 0.f, rs1 = 0.f;
                    #pragma unroll
                    for (int j = 0; j < 8; j++) {
                        float e0, e1, e2, e3;
                        exp2pair(sc[mf][j][0], sc[mf][j][1], e0, e1);
                        exp2pair(sc[mf][j][2], sc[mf][j][3], e2, e3);
                        sc[mf][j][0] = e0; sc[mf][j][1] = e1;
                        sc[mf][j][2] = e2; sc[mf][j][3] = e3;
                        rs0 += e0 + e1;
                        rs1 += e2 + e3;
                    }
                    lrw[mf][0] += rs0;
                    lrw[mf][1] += rs1;
                }

                #pragma unroll
                for (int u = 0; u < 4; u++) {
                    uint32_t A_hi[2][4];
                    #pragma unroll
                    for (int mf = 0; mf < 2; mf++)
                        #pragma unroll
                        for (int fr = 0; fr < 4; fr++) {
                            int cj = 2*u + (fr >> 1);
                            int po = (fr & 1) * 2;
                            A_hi[mf][fr] = pkhf(sc[mf][cj][po], sc[mf][cj][po+1]);
                        }
                    #pragma unroll
                    for (int dv = 0; dv < 4; dv++) {
                        uint32_t vv[4];
                        LDSM4T(vv, vbank + (ks + u * 16 + (lane & 15)) * 144
                                   + (dv * 16 + (lane >> 4) * 8) * 2);
                        #pragma unroll
                        for (int mf = 0; mf < 2; mf++) {
                            MMA_F16(oc[mf][dv*2],   A_hi[mf], vv[0], vv[1]);
                            MMA_F16(oc[mf][dv*2+1], A_hi[mf], vv[2], vv[3]);
                        }
                    }
                }
            }
        }
    }

    #pragma unroll
    for (int mf = 0; mf < 2; mf++) {
        #pragma unroll
        for (int rh = 0; rh < 2; rh++) {
            float l = lrw[mf][rh];
            l += __shfl_xor_sync(0xffffffffu, l, 1);
            l += __shfl_xor_sync(0xffffffffu, l, 2);
            lrw[mf][rh] = 1.0f / l;
        }
        #pragma unroll
        for (int j = 0; j < 8; j++) {
            size_t col = (size_t)h * 64 + 8 * j + c2;
            *(uint32_t*)&g_yf[tok[mf][0] * 1024 + col] =
                pkhf(oc[mf][j][0] * lrw[mf][0], oc[mf][j][1] * lrw[mf][0]);
            *(uint32_t*)&g_yf[tok[mf][1] * 1024 + col] =
                pkhf(oc[mf][j][2] * lrw[mf][1], oc[mf][j][3] * lrw[mf][1]);
        }
    }
}

// ---------------- launch ----------------
extern "C" void kernel_launch(void* const* d_in, const int* in_sizes, int n_in,
                              void* d_out, int out_size) {
    const float* x    = (const float*)d_in[0];
    const float* Wq   = (const float*)d_in[1];
    const float* Wk   = (const float*)d_in[2];
    const float* Wv   = (const float*)d_in[3];
    const float* Wp   = (const float*)d_in[4];
    const float* gain = (const float*)d_in[5];
    const float* Aq   = (const float*)d_in[6];
    const float* Bq   = (const float*)d_in[7];
    const float* Av   = (const float*)d_in[8];
    const float* Bv   = (const float*)d_in[9];
    const int*   step = (const int*)d_in[10];
    float* out = (float*)d_out;

    prep_all_kernel<<<NBW_ + NBX_ + NBR_, 256>>>(x, Wq, Wk, Wv, Wp, Aq, Bq, Av, Bv, step);

    cudaFuncSetAttribute(gemm_mma_kernel<0>, cudaFuncAttributeMaxDynamicSharedMemorySize, G_SMEM);
    cudaFuncSetAttribute(gemm_mma_kernel<2>, cudaFuncAttributeMaxDynamicSharedMemorySize, G_SMEM);
    cudaFuncSetAttribute(flash_mma_kernel,   cudaFuncAttributeMaxDynamicSharedMemorySize, FA_SMEM);

    gemm_mma_kernel<0><<<dim3(1536/128, M_/128), 128, G_SMEM>>>(gain, nullptr);

    flash_mma_kernel<<<dim3(S_/128, H_, B_), 128, FA_SMEM>>>();

    gemm_mma_kernel<2><<<dim3(1024/128, M_/128), 128, G_SMEM>>>(gain, out);
}